// round 1
// baseline (speedup 1.0000x reference)
#include <cuda_runtime.h>
#include <math.h>

#define HID 1024
#define INP 256
#define BB  64
#define TSRC 256
#define TTRG 64
#define G3  3072

// ---------------- scratch (static device globals; no runtime allocation) ----
__device__ float g_gi [(long)TSRC * BB * G3];   // precomputed input gates (reused per layer)
__device__ float g_ys0[(long)TSRC * BB * HID];  // encoder layer-0 outputs [t][b][h]
__device__ float g_h0 [2 * BB * HID];           // decoder layer-0 hidden (ping-pong)
__device__ float g_h1 [2 * BB * HID];           // decoder layer-1 hidden (ping-pong)
__device__ float g_x  [BB * INP];               // decoder autoregressive input (prev pred)

__device__ __forceinline__ float sigmoidf_(float x) { return 1.0f / (1.0f + expf(-x)); }

// ---------------------------------------------------------------------------
// Batched input-gate GEMM: out[r][n] = sum_k X_row(r)[k] * W[n][k] + bias[n]
// rows r in [0, 16384): r = t*64 + b ; row offset = b*sb + t*st (t = blockIdx.y)
// Tile 64 rows x 64 cols, KT=32. grid = (48, 256), 256 threads, 4x4 micro-tile.
// ---------------------------------------------------------------------------
__global__ void __launch_bounds__(256) gi_gemm(
    const float* __restrict__ X, long sb, long st,
    const float* __restrict__ W, const float* __restrict__ bias,
    float* __restrict__ out, int K)
{
    __shared__ float Xs[32][66];
    __shared__ float Ws[32][66];
    const int tid = threadIdx.x;
    const int tr  = tid >> 4;     // 0..15 -> 4 rows each
    const int tc  = tid & 15;     // 0..15 -> 4 cols each
    const long cb = (long)blockIdx.x * 64;
    const long rb = (long)blockIdx.y;
    const float* Xb = X + rb * st;

    float acc[4][4];
#pragma unroll
    for (int i = 0; i < 4; i++)
#pragma unroll
        for (int jj = 0; jj < 4; jj++) acc[i][jj] = 0.0f;

    for (int k0 = 0; k0 < K; k0 += 32) {
#pragma unroll
        for (int i = 0; i < 8; i++) {
            int lin = tid + (i << 8);
            int rr = lin >> 5, kk = lin & 31;
            Xs[kk][rr] = Xb[(long)rr * sb + k0 + kk];
            Ws[kk][rr] = W[(cb + rr) * (long)K + k0 + kk];
        }
        __syncthreads();
#pragma unroll
        for (int kk = 0; kk < 32; kk++) {
            float2 a01 = *(const float2*)&Xs[kk][tr * 4];
            float2 a23 = *(const float2*)&Xs[kk][tr * 4 + 2];
            float2 b01 = *(const float2*)&Ws[kk][tc * 4];
            float2 b23 = *(const float2*)&Ws[kk][tc * 4 + 2];
            float a[4] = {a01.x, a01.y, a23.x, a23.y};
            float b[4] = {b01.x, b01.y, b23.x, b23.y};
#pragma unroll
            for (int i = 0; i < 4; i++)
#pragma unroll
                for (int jj = 0; jj < 4; jj++) acc[i][jj] += a[i] * b[jj];
        }
        __syncthreads();
    }
#pragma unroll
    for (int i = 0; i < 4; i++) {
        long r = rb * 64 + tr * 4 + i;
#pragma unroll
        for (int jj = 0; jj < 4; jj++) {
            long c = cb + tc * 4 + jj;
            out[r * G3 + c] = acc[i][jj] + bias[c];
        }
    }
}

// ---------------------------------------------------------------------------
// Fused GRU step. Computes, for 8 hidden columns per block, all 3 gates over
// all 64 batch rows:   gh = h_prev @ Wh.T (+ optional gi = x @ Wi.T inline),
// then r/z/n nonlinearity and h' = (1-z)*n + z*h.
// grid = 128 blocks, 256 threads. Each thread: 1 col x 2 batch rows x gates.
// gi_pre != null  -> input gates precomputed (already include bi)
// gi_pre == null  -> compute gi inline from (x, Wi, bi); x_zero skips x phase.
// ---------------------------------------------------------------------------
__global__ void __launch_bounds__(256) gru_step(
    const float* __restrict__ x, int x_zero, int Kx,
    const float* __restrict__ Wi, const float* __restrict__ bi,
    const float* __restrict__ gi_pre,
    const float* __restrict__ h_prev, long h_stride, int h_zero,
    const float* __restrict__ Wh, const float* __restrict__ bh,
    float* __restrict__ out1, long s1,
    float* __restrict__ out2, long s2)
{
    __shared__ float hs[32][66];
    __shared__ float ws[24][33];
    const int tid = threadIdx.x;
    const int j   = tid & 7;          // column within block tile
    const int grp = tid >> 3;         // 0..31
    const int m   = grp << 1;         // batch row pair
    const int j0  = blockIdx.x << 3;  // 8 cols per block -> 128 blocks

    float ar0 = 0.f, ar1 = 0.f, az0 = 0.f, az1 = 0.f;
    float ain0 = 0.f, ain1 = 0.f, ahn0 = 0.f, ahn1 = 0.f;

    // ---- phase A: input gates from x @ Wi.T (decoder path) ----
    if (gi_pre == nullptr && !x_zero) {
        for (int k0 = 0; k0 < Kx; k0 += 32) {
#pragma unroll
            for (int i = 0; i < 8; i++) {
                int lin = tid + (i << 8);
                int b = lin >> 5, kk = lin & 31;
                hs[kk][b] = x[(long)b * Kx + k0 + kk];
            }
#pragma unroll
            for (int i = 0; i < 3; i++) {
                int lin = tid + (i << 8);
                int row = lin >> 5, kk = lin & 31;
                ws[row][kk] = Wi[(long)((row >> 3) * HID + j0 + (row & 7)) * Kx + k0 + kk];
            }
            __syncthreads();
#pragma unroll
            for (int kk = 0; kk < 32; kk++) {
                float2 hv = *(const float2*)&hs[kk][m];
                float wr = ws[j][kk];
                float wz = ws[8 + j][kk];
                float wn = ws[16 + j][kk];
                ar0  += hv.x * wr;  ar1  += hv.y * wr;
                az0  += hv.x * wz;  az1  += hv.y * wz;
                ain0 += hv.x * wn;  ain1 += hv.y * wn;
            }
            __syncthreads();
        }
    }

    // ---- phase B: hidden gates from h_prev @ Wh.T ----
    if (!h_zero) {
        for (int k0 = 0; k0 < HID; k0 += 32) {
#pragma unroll
            for (int i = 0; i < 8; i++) {
                int lin = tid + (i << 8);
                int b = lin >> 5, kk = lin & 31;
                hs[kk][b] = h_prev[(long)b * h_stride + k0 + kk];
            }
#pragma unroll
            for (int i = 0; i < 3; i++) {
                int lin = tid + (i << 8);
                int row = lin >> 5, kk = lin & 31;
                ws[row][kk] = Wh[(long)((row >> 3) * HID + j0 + (row & 7)) * HID + k0 + kk];
            }
            __syncthreads();
#pragma unroll
            for (int kk = 0; kk < 32; kk++) {
                float2 hv = *(const float2*)&hs[kk][m];
                float wr = ws[j][kk];
                float wz = ws[8 + j][kk];
                float wn = ws[16 + j][kk];
                ar0  += hv.x * wr;  ar1  += hv.y * wr;
                az0  += hv.x * wz;  az1  += hv.y * wz;
                ahn0 += hv.x * wn;  ahn1 += hv.y * wn;
            }
            __syncthreads();
        }
    }

    // ---- epilogue: gates + state update ----
    const int col = j0 + j;
    const float bhr = bh[col], bhz = bh[HID + col], bhn = bh[2 * HID + col];
    float GR0, GZ0, GN0, GR1, GZ1, GN1;
    if (gi_pre) {
        const float* gp0 = gi_pre + (long)m * G3;
        const float* gp1 = gi_pre + (long)(m + 1) * G3;
        GR0 = gp0[col]; GZ0 = gp0[HID + col]; GN0 = gp0[2 * HID + col];
        GR1 = gp1[col]; GZ1 = gp1[HID + col]; GN1 = gp1[2 * HID + col];
    } else {
        GR0 = GR1 = bi[col];
        GZ0 = GZ1 = bi[HID + col];
        GN0 = GN1 = bi[2 * HID + col];
    }
    float hold0 = h_zero ? 0.f : h_prev[(long)m * h_stride + col];
    float hold1 = h_zero ? 0.f : h_prev[(long)(m + 1) * h_stride + col];

    float r0 = sigmoidf_(GR0 + ar0 + bhr);
    float z0 = sigmoidf_(GZ0 + az0 + bhz);
    float n0 = tanhf(GN0 + ain0 + r0 * (ahn0 + bhn));
    float hn0 = (1.f - z0) * n0 + z0 * hold0;

    float r1 = sigmoidf_(GR1 + ar1 + bhr);
    float z1 = sigmoidf_(GZ1 + az1 + bhz);
    float n1 = tanhf(GN1 + ain1 + r1 * (ahn1 + bhn));
    float hn1 = (1.f - z1) * n1 + z1 * hold1;

    out1[(long)m * s1 + col] = hn0;
    out1[(long)(m + 1) * s1 + col] = hn1;
    if (out2) {
        out2[(long)m * s2 + col] = hn0;
        out2[(long)(m + 1) * s2 + col] = hn1;
    }
}

// ---------------------------------------------------------------------------
// FC projection: pred[b][o] = h[b] . fcW[o] + fcb[o]; writes to d_out "out"
// region AND to the decoder input buffer. grid = 32 blocks (8 cols each).
// ---------------------------------------------------------------------------
__global__ void __launch_bounds__(256) fc_kernel(
    const float* __restrict__ h,
    const float* __restrict__ W, const float* __restrict__ bias,
    float* __restrict__ o1, long s1,
    float* __restrict__ o2, long s2)
{
    __shared__ float hs[32][66];
    __shared__ float ws[8][33];
    const int tid = threadIdx.x;
    const int c   = tid & 7;
    const int grp = tid >> 3;
    const int m   = grp << 1;
    const int c0  = blockIdx.x << 3;
    float a0 = 0.f, a1 = 0.f;

    for (int k0 = 0; k0 < HID; k0 += 32) {
#pragma unroll
        for (int i = 0; i < 8; i++) {
            int lin = tid + (i << 8);
            int b = lin >> 5, kk = lin & 31;
            hs[kk][b] = h[(long)b * HID + k0 + kk];
        }
        {
            int row = tid >> 5, kk = tid & 31;
            ws[row][kk] = W[(long)(c0 + row) * HID + k0 + kk];
        }
        __syncthreads();
#pragma unroll
        for (int kk = 0; kk < 32; kk++) {
            float2 hv = *(const float2*)&hs[kk][m];
            float w = ws[c][kk];
            a0 += hv.x * w;
            a1 += hv.y * w;
        }
        __syncthreads();
    }
    int col = c0 + c;
    float bv = bias[col];
    o1[(long)m * s1 + col] = a0 + bv;
    o1[(long)(m + 1) * s1 + col] = a1 + bv;
    o2[(long)m * s2 + col] = a0 + bv;
    o2[(long)(m + 1) * s2 + col] = a1 + bv;
}

// ---------------------------------------------------------------------------
extern "C" void kernel_launch(void* const* d_in, const int* in_sizes, int n_in,
                              void* d_out, int out_size)
{
    const float* src  = (const float*)d_in[0];
    // d_in[1] = trg : values unused (teacher_forcing_ratio = 0)
    const float* eWi0 = (const float*)d_in[2];
    const float* eWh0 = (const float*)d_in[3];
    const float* ebi0 = (const float*)d_in[4];
    const float* ebh0 = (const float*)d_in[5];
    const float* eWi1 = (const float*)d_in[6];
    const float* eWh1 = (const float*)d_in[7];
    const float* ebi1 = (const float*)d_in[8];
    const float* ebh1 = (const float*)d_in[9];
    const float* dWi0 = (const float*)d_in[10];
    const float* dWh0 = (const float*)d_in[11];
    const float* dbi0 = (const float*)d_in[12];
    const float* dbh0 = (const float*)d_in[13];
    const float* dWi1 = (const float*)d_in[14];
    const float* dWh1 = (const float*)d_in[15];
    const float* dbi1 = (const float*)d_in[16];
    const float* dbh1 = (const float*)d_in[17];
    const float* fcW  = (const float*)d_in[18];
    const float* fcb  = (const float*)d_in[19];

    float* out     = (float*)d_out;                       // [64, 64, 256]
    float* enc_out = out + (long)BB * TTRG * INP;         // [64, 256, 1024]
    float* dec_out = enc_out + (long)BB * TSRC * HID;     // [64, 64, 1024]

    float *gi, *ys0, *h0, *h1, *xbuf;
    cudaGetSymbolAddress((void**)&gi,   g_gi);
    cudaGetSymbolAddress((void**)&ys0,  g_ys0);
    cudaGetSymbolAddress((void**)&h0,   g_h0);
    cudaGetSymbolAddress((void**)&h1,   g_h1);
    cudaGetSymbolAddress((void**)&xbuf, g_x);

    dim3 gridGi(48, 256);

    // ---------- encoder layer 0 ----------
    // src[b][t][k]: row (t*64+b) offset = b*65536 + t*256
    gi_gemm<<<gridGi, 256>>>(src, 65536L, 256L, eWi0, ebi0, gi, 256);
    for (int t = 0; t < TSRC; t++) {
        gru_step<<<128, 256>>>(
            nullptr, 1, 0, nullptr, nullptr,
            gi + (long)t * BB * G3,
            t ? ys0 + (long)(t - 1) * BB * HID : nullptr, (long)HID, (t == 0),
            eWh0, ebh0,
            ys0 + (long)t * BB * HID, (long)HID,
            nullptr, 0);
    }

    // ---------- encoder layer 1 ----------
    // ys0[t][b][k]: row (t*64+b) offset = b*1024 + t*65536
    gi_gemm<<<gridGi, 256>>>(ys0, 1024L, 65536L, eWi1, ebi1, gi, 1024);
    for (int t = 0; t < TSRC; t++) {
        gru_step<<<128, 256>>>(
            nullptr, 1, 0, nullptr, nullptr,
            gi + (long)t * BB * G3,
            t ? enc_out + (long)(t - 1) * HID : nullptr, (long)TSRC * HID, (t == 0),
            eWh1, ebh1,
            enc_out + (long)t * HID, (long)TSRC * HID,
            nullptr, 0);
    }

    // ---------- decoder (autoregressive, 64 steps) ----------
    for (int t = 0; t < TTRG; t++) {
        int w = t & 1;
        const float* h0p = t ? h0 + (long)(1 - w) * BB * HID
                             : ys0 + (long)(TSRC - 1) * BB * HID;  // enc layer-0 h_T
        gru_step<<<128, 256>>>(
            xbuf, (t == 0), INP, dWi0, dbi0, nullptr,
            h0p, (long)HID, 0,
            dWh0, dbh0,
            h0 + (long)w * BB * HID, (long)HID,
            nullptr, 0);

        const float* h1p = t ? h1 + (long)(1 - w) * BB * HID
                             : enc_out + (long)(TSRC - 1) * HID;   // enc layer-1 h_T
        long h1s = t ? (long)HID : (long)TSRC * HID;
        gru_step<<<128, 256>>>(
            h0 + (long)w * BB * HID, 0, HID, dWi1, dbi1, nullptr,
            h1p, h1s, 0,
            dWh1, dbh1,
            h1 + (long)w * BB * HID, (long)HID,
            dec_out + (long)t * HID, (long)TTRG * HID);

        fc_kernel<<<32, 256>>>(
            h1 + (long)w * BB * HID, fcW, fcb,
            out + (long)t * INP, (long)TTRG * INP,
            xbuf, (long)INP);
    }
}

// round 2
// speedup vs baseline: 1.0019x; 1.0019x over previous
#include <cuda_runtime.h>
#include <math.h>

#define HID 1024
#define INP 256
#define BB  64
#define TSRC 256
#define TTRG 64
#define G3  3072

// ---------------- scratch (static device globals; no runtime allocation) ----
__device__ float g_gi [(long)TSRC * BB * G3];   // precomputed input gates (reused per layer)
__device__ float g_ys0[(long)TSRC * BB * HID];  // encoder layer-0 outputs [t][b][h]
__device__ float g_h0 [2 * BB * HID];           // decoder layer-0 hidden (ping-pong)
__device__ float g_h1 [2 * BB * HID];           // decoder layer-1 hidden (ping-pong)
__device__ float g_x  [BB * INP];               // decoder autoregressive input (prev pred)

__device__ __forceinline__ float sigmoidf_(float x) { return 1.0f / (1.0f + expf(-x)); }

// ---------------------------------------------------------------------------
// Batched input-gate GEMM: out[r][n] = sum_k X_row(r)[k] * W[n][k] + bias[n]
// rows r in [0, 16384): r = t*64 + b ; row offset = b*sb + t*st (t = blockIdx.y)
// Tile 64 rows x 64 cols, KT=32. grid = (48, 256), 256 threads, 4x4 micro-tile.
// ---------------------------------------------------------------------------
__global__ void __launch_bounds__(256) gi_gemm(
    const float* __restrict__ X, long sb, long st,
    const float* __restrict__ W, const float* __restrict__ bias,
    float* __restrict__ out, int K)
{
    __shared__ float Xs[32][66];
    __shared__ float Ws[32][66];
    const int tid = threadIdx.x;
    const int tr  = tid >> 4;     // 0..15 -> 4 rows each
    const int tc  = tid & 15;     // 0..15 -> 4 cols each
    const long cb = (long)blockIdx.x * 64;
    const long rb = (long)blockIdx.y;
    const float* Xb = X + rb * st;

    float acc[4][4];
#pragma unroll
    for (int i = 0; i < 4; i++)
#pragma unroll
        for (int jj = 0; jj < 4; jj++) acc[i][jj] = 0.0f;

    for (int k0 = 0; k0 < K; k0 += 32) {
#pragma unroll
        for (int i = 0; i < 8; i++) {
            int lin = tid + (i << 8);
            int rr = lin >> 5, kk = lin & 31;
            Xs[kk][rr] = Xb[(long)rr * sb + k0 + kk];
            Ws[kk][rr] = W[(cb + rr) * (long)K + k0 + kk];
        }
        __syncthreads();
#pragma unroll
        for (int kk = 0; kk < 32; kk++) {
            float2 a01 = *(const float2*)&Xs[kk][tr * 4];
            float2 a23 = *(const float2*)&Xs[kk][tr * 4 + 2];
            float2 b01 = *(const float2*)&Ws[kk][tc * 4];
            float2 b23 = *(const float2*)&Ws[kk][tc * 4 + 2];
            float a[4] = {a01.x, a01.y, a23.x, a23.y};
            float b[4] = {b01.x, b01.y, b23.x, b23.y};
#pragma unroll
            for (int i = 0; i < 4; i++)
#pragma unroll
                for (int jj = 0; jj < 4; jj++) acc[i][jj] += a[i] * b[jj];
        }
        __syncthreads();
    }
#pragma unroll
    for (int i = 0; i < 4; i++) {
        long r = rb * 64 + tr * 4 + i;
#pragma unroll
        for (int jj = 0; jj < 4; jj++) {
            long c = cb + tc * 4 + jj;
            out[r * G3 + c] = acc[i][jj] + bias[c];
        }
    }
}

// ---------------------------------------------------------------------------
// Fused GRU step. Computes, for 8 hidden columns per block, all 3 gates over
// all 64 batch rows:   gh = h_prev @ Wh.T (+ optional gi = x @ Wi.T inline),
// then r/z/n nonlinearity and h' = (1-z)*n + z*h.
// grid = 128 blocks, 256 threads. Each thread: 1 col x 2 batch rows x gates.
// gi_pre != null  -> input gates precomputed (already include bi)
// gi_pre == null  -> compute gi inline from (x, Wi, bi); x_zero skips x phase.
// ---------------------------------------------------------------------------
__global__ void __launch_bounds__(256) gru_step(
    const float* __restrict__ x, int x_zero, int Kx,
    const float* __restrict__ Wi, const float* __restrict__ bi,
    const float* __restrict__ gi_pre,
    const float* __restrict__ h_prev, long h_stride, int h_zero,
    const float* __restrict__ Wh, const float* __restrict__ bh,
    float* __restrict__ out1, long s1,
    float* __restrict__ out2, long s2)
{
    __shared__ float hs[32][66];
    __shared__ float ws[24][33];
    const int tid = threadIdx.x;
    const int j   = tid & 7;          // column within block tile
    const int grp = tid >> 3;         // 0..31
    const int m   = grp << 1;         // batch row pair
    const int j0  = blockIdx.x << 3;  // 8 cols per block -> 128 blocks

    float ar0 = 0.f, ar1 = 0.f, az0 = 0.f, az1 = 0.f;
    float ain0 = 0.f, ain1 = 0.f, ahn0 = 0.f, ahn1 = 0.f;

    // ---- phase A: input gates from x @ Wi.T (decoder path) ----
    if (gi_pre == nullptr && !x_zero) {
        for (int k0 = 0; k0 < Kx; k0 += 32) {
#pragma unroll
            for (int i = 0; i < 8; i++) {
                int lin = tid + (i << 8);
                int b = lin >> 5, kk = lin & 31;
                hs[kk][b] = x[(long)b * Kx + k0 + kk];
            }
#pragma unroll
            for (int i = 0; i < 3; i++) {
                int lin = tid + (i << 8);
                int row = lin >> 5, kk = lin & 31;
                ws[row][kk] = Wi[(long)((row >> 3) * HID + j0 + (row & 7)) * Kx + k0 + kk];
            }
            __syncthreads();
#pragma unroll
            for (int kk = 0; kk < 32; kk++) {
                float2 hv = *(const float2*)&hs[kk][m];
                float wr = ws[j][kk];
                float wz = ws[8 + j][kk];
                float wn = ws[16 + j][kk];
                ar0  += hv.x * wr;  ar1  += hv.y * wr;
                az0  += hv.x * wz;  az1  += hv.y * wz;
                ain0 += hv.x * wn;  ain1 += hv.y * wn;
            }
            __syncthreads();
        }
    }

    // ---- phase B: hidden gates from h_prev @ Wh.T ----
    if (!h_zero) {
        for (int k0 = 0; k0 < HID; k0 += 32) {
#pragma unroll
            for (int i = 0; i < 8; i++) {
                int lin = tid + (i << 8);
                int b = lin >> 5, kk = lin & 31;
                hs[kk][b] = h_prev[(long)b * h_stride + k0 + kk];
            }
#pragma unroll
            for (int i = 0; i < 3; i++) {
                int lin = tid + (i << 8);
                int row = lin >> 5, kk = lin & 31;
                ws[row][kk] = Wh[(long)((row >> 3) * HID + j0 + (row & 7)) * HID + k0 + kk];
            }
            __syncthreads();
#pragma unroll
            for (int kk = 0; kk < 32; kk++) {
                float2 hv = *(const float2*)&hs[kk][m];
                float wr = ws[j][kk];
                float wz = ws[8 + j][kk];
                float wn = ws[16 + j][kk];
                ar0  += hv.x * wr;  ar1  += hv.y * wr;
                az0  += hv.x * wz;  az1  += hv.y * wz;
                ahn0 += hv.x * wn;  ahn1 += hv.y * wn;
            }
            __syncthreads();
        }
    }

    // ---- epilogue: gates + state update ----
    const int col = j0 + j;
    const float bhr = bh[col], bhz = bh[HID + col], bhn = bh[2 * HID + col];
    float GR0, GZ0, GN0, GR1, GZ1, GN1;
    if (gi_pre) {
        const float* gp0 = gi_pre + (long)m * G3;
        const float* gp1 = gi_pre + (long)(m + 1) * G3;
        GR0 = gp0[col]; GZ0 = gp0[HID + col]; GN0 = gp0[2 * HID + col];
        GR1 = gp1[col]; GZ1 = gp1[HID + col]; GN1 = gp1[2 * HID + col];
    } else {
        GR0 = GR1 = bi[col];
        GZ0 = GZ1 = bi[HID + col];
        GN0 = GN1 = bi[2 * HID + col];
    }
    float hold0 = h_zero ? 0.f : h_prev[(long)m * h_stride + col];
    float hold1 = h_zero ? 0.f : h_prev[(long)(m + 1) * h_stride + col];

    float r0 = sigmoidf_(GR0 + ar0 + bhr);
    float z0 = sigmoidf_(GZ0 + az0 + bhz);
    float n0 = tanhf(GN0 + ain0 + r0 * (ahn0 + bhn));
    float hn0 = (1.f - z0) * n0 + z0 * hold0;

    float r1 = sigmoidf_(GR1 + ar1 + bhr);
    float z1 = sigmoidf_(GZ1 + az1 + bhz);
    float n1 = tanhf(GN1 + ain1 + r1 * (ahn1 + bhn));
    float hn1 = (1.f - z1) * n1 + z1 * hold1;

    out1[(long)m * s1 + col] = hn0;
    out1[(long)(m + 1) * s1 + col] = hn1;
    if (out2) {
        out2[(long)m * s2 + col] = hn0;
        out2[(long)(m + 1) * s2 + col] = hn1;
    }
}

// ---------------------------------------------------------------------------
// FC projection: pred[b][o] = h[b] . fcW[o] + fcb[o]; writes to d_out "out"
// region AND to the decoder input buffer. grid = 32 blocks (8 cols each).
// ---------------------------------------------------------------------------
__global__ void __launch_bounds__(256) fc_kernel(
    const float* __restrict__ h,
    const float* __restrict__ W, const float* __restrict__ bias,
    float* __restrict__ o1, long s1,
    float* __restrict__ o2, long s2)
{
    __shared__ float hs[32][66];
    __shared__ float ws[8][33];
    const int tid = threadIdx.x;
    const int c   = tid & 7;
    const int grp = tid >> 3;
    const int m   = grp << 1;
    const int c0  = blockIdx.x << 3;
    float a0 = 0.f, a1 = 0.f;

    for (int k0 = 0; k0 < HID; k0 += 32) {
#pragma unroll
        for (int i = 0; i < 8; i++) {
            int lin = tid + (i << 8);
            int b = lin >> 5, kk = lin & 31;
            hs[kk][b] = h[(long)b * HID + k0 + kk];
        }
        {
            int row = tid >> 5, kk = tid & 31;
            ws[row][kk] = W[(long)(c0 + row) * HID + k0 + kk];
        }
        __syncthreads();
#pragma unroll
        for (int kk = 0; kk < 32; kk++) {
            float2 hv = *(const float2*)&hs[kk][m];
            float w = ws[c][kk];
            a0 += hv.x * w;
            a1 += hv.y * w;
        }
        __syncthreads();
    }
    int col = c0 + c;
    float bv = bias[col];
    o1[(long)m * s1 + col] = a0 + bv;
    o1[(long)(m + 1) * s1 + col] = a1 + bv;
    o2[(long)m * s2 + col] = a0 + bv;
    o2[(long)(m + 1) * s2 + col] = a1 + bv;
}

// ---------------------------------------------------------------------------
extern "C" void kernel_launch(void* const* d_in, const int* in_sizes, int n_in,
                              void* d_out, int out_size)
{
    const float* src  = (const float*)d_in[0];
    // d_in[1] = trg : values unused (teacher_forcing_ratio = 0)
    const float* eWi0 = (const float*)d_in[2];
    const float* eWh0 = (const float*)d_in[3];
    const float* ebi0 = (const float*)d_in[4];
    const float* ebh0 = (const float*)d_in[5];
    const float* eWi1 = (const float*)d_in[6];
    const float* eWh1 = (const float*)d_in[7];
    const float* ebi1 = (const float*)d_in[8];
    const float* ebh1 = (const float*)d_in[9];
    const float* dWi0 = (const float*)d_in[10];
    const float* dWh0 = (const float*)d_in[11];
    const float* dbi0 = (const float*)d_in[12];
    const float* dbh0 = (const float*)d_in[13];
    const float* dWi1 = (const float*)d_in[14];
    const float* dWh1 = (const float*)d_in[15];
    const float* dbi1 = (const float*)d_in[16];
    const float* dbh1 = (const float*)d_in[17];
    const float* fcW  = (const float*)d_in[18];
    const float* fcb  = (const float*)d_in[19];

    float* out     = (float*)d_out;                       // [64, 64, 256]
    float* enc_out = out + (long)BB * TTRG * INP;         // [64, 256, 1024]
    float* dec_out = enc_out + (long)BB * TSRC * HID;     // [64, 64, 1024]

    float *gi, *ys0, *h0, *h1, *xbuf;
    cudaGetSymbolAddress((void**)&gi,   g_gi);
    cudaGetSymbolAddress((void**)&ys0,  g_ys0);
    cudaGetSymbolAddress((void**)&h0,   g_h0);
    cudaGetSymbolAddress((void**)&h1,   g_h1);
    cudaGetSymbolAddress((void**)&xbuf, g_x);

    dim3 gridGi(48, 256);

    // ---------- encoder layer 0 ----------
    // src[b][t][k]: row (t*64+b) offset = b*65536 + t*256
    gi_gemm<<<gridGi, 256>>>(src, 65536L, 256L, eWi0, ebi0, gi, 256);
    for (int t = 0; t < TSRC; t++) {
        gru_step<<<128, 256>>>(
            nullptr, 1, 0, nullptr, nullptr,
            gi + (long)t * BB * G3,
            t ? ys0 + (long)(t - 1) * BB * HID : nullptr, (long)HID, (t == 0),
            eWh0, ebh0,
            ys0 + (long)t * BB * HID, (long)HID,
            nullptr, 0);
    }

    // ---------- encoder layer 1 ----------
    // ys0[t][b][k]: row (t*64+b) offset = b*1024 + t*65536
    gi_gemm<<<gridGi, 256>>>(ys0, 1024L, 65536L, eWi1, ebi1, gi, 1024);
    for (int t = 0; t < TSRC; t++) {
        gru_step<<<128, 256>>>(
            nullptr, 1, 0, nullptr, nullptr,
            gi + (long)t * BB * G3,
            t ? enc_out + (long)(t - 1) * HID : nullptr, (long)TSRC * HID, (t == 0),
            eWh1, ebh1,
            enc_out + (long)t * HID, (long)TSRC * HID,
            nullptr, 0);
    }

    // ---------- decoder (autoregressive, 64 steps) ----------
    for (int t = 0; t < TTRG; t++) {
        int w = t & 1;
        const float* h0p = t ? h0 + (long)(1 - w) * BB * HID
                             : ys0 + (long)(TSRC - 1) * BB * HID;  // enc layer-0 h_T
        gru_step<<<128, 256>>>(
            xbuf, (t == 0), INP, dWi0, dbi0, nullptr,
            h0p, (long)HID, 0,
            dWh0, dbh0,
            h0 + (long)w * BB * HID, (long)HID,
            nullptr, 0);

        const float* h1p = t ? h1 + (long)(1 - w) * BB * HID
                             : enc_out + (long)(TSRC - 1) * HID;   // enc layer-1 h_T
        long h1s = t ? (long)HID : (long)TSRC * HID;
        gru_step<<<128, 256>>>(
            h0 + (long)w * BB * HID, 0, HID, dWi1, dbi1, nullptr,
            h1p, h1s, 0,
            dWh1, dbh1,
            h1 + (long)w * BB * HID, (long)HID,
            dec_out + (long)t * HID, (long)TTRG * HID);

        fc_kernel<<<32, 256>>>(
            h1 + (long)w * BB * HID, fcW, fcb,
            out + (long)t * INP, (long)TTRG * INP,
            xbuf, (long)INP);
    }
}

// round 3
// speedup vs baseline: 1.0114x; 1.0095x over previous
#include <cuda_runtime.h>
#include <math.h>

#define HID  1024
#define INP  256
#define BB   64
#define TSRC 256
#define TTRG 64
#define G3   3072
#define GRID 128
#define NTH  512

// ---------------- scratch (static device globals; no runtime allocation) ----
__device__ float g_gi [(long)TSRC * BB * G3];   // precomputed input gates
__device__ float g_ys0[(long)TSRC * BB * HID];  // enc layer-0 outputs [t][b][h]
__device__ float g_h0 [2 * BB * HID];           // decoder layer-0 hidden (ping-pong)
__device__ float g_h1 [2 * BB * HID];           // decoder layer-1 hidden (ping-pong)
__device__ float g_x  [BB * INP];               // decoder AR input
__device__ unsigned g_bars[1024];               // grid-barrier slots (memset by host)

__device__ __forceinline__ float sigf(float x) { return 1.0f / (1.0f + expf(-x)); }

// ---------------------------------------------------------------------------
// Software grid barrier (one slot per use; slots pre-zeroed via memsetAsync).
// All GRID blocks co-resident (1 block/SM by SMEM footprint).
// ---------------------------------------------------------------------------
__device__ __forceinline__ void grid_bar(unsigned* bar)
{
    __threadfence();
    __syncthreads();
    if (threadIdx.x == 0) {
        unsigned arrived = atomicAdd(bar, 1u) + 1u;
        if (arrived < (unsigned)GRID) {
            volatile unsigned* p = bar;
            while (*p < (unsigned)GRID) { }
        }
        __threadfence();
    }
    __syncthreads();
}

// ---------------------------------------------------------------------------
// Batched input-gate GEMM: out[r][n] = X_row(r).W[n] + bias[n]
// r = t*64+b, row offset = b*sb + t*st (t = blockIdx.y)
// ---------------------------------------------------------------------------
__global__ void __launch_bounds__(256) gi_gemm(
    const float* __restrict__ X, long sb, long st,
    const float* __restrict__ W, const float* __restrict__ bias,
    float* __restrict__ out, int K)
{
    __shared__ float Xs[32][66];
    __shared__ float Ws[32][66];
    const int tid = threadIdx.x;
    const int tr  = tid >> 4;
    const int tc  = tid & 15;
    const long cb = (long)blockIdx.x * 64;
    const long rb = (long)blockIdx.y;
    const float* Xb = X + rb * st;

    float acc[4][4];
#pragma unroll
    for (int i = 0; i < 4; i++)
#pragma unroll
        for (int jj = 0; jj < 4; jj++) acc[i][jj] = 0.0f;

    for (int k0 = 0; k0 < K; k0 += 32) {
#pragma unroll
        for (int i = 0; i < 8; i++) {
            int lin = tid + (i << 8);
            int rr = lin >> 5, kk = lin & 31;
            Xs[kk][rr] = Xb[(long)rr * sb + k0 + kk];
            Ws[kk][rr] = W[(cb + rr) * (long)K + k0 + kk];
        }
        __syncthreads();
#pragma unroll
        for (int kk = 0; kk < 32; kk++) {
            float2 a01 = *(const float2*)&Xs[kk][tr * 4];
            float2 a23 = *(const float2*)&Xs[kk][tr * 4 + 2];
            float2 b01 = *(const float2*)&Ws[kk][tc * 4];
            float2 b23 = *(const float2*)&Ws[kk][tc * 4 + 2];
            float a[4] = {a01.x, a01.y, a23.x, a23.y};
            float b[4] = {b01.x, b01.y, b23.x, b23.y};
#pragma unroll
            for (int i = 0; i < 4; i++)
#pragma unroll
                for (int jj = 0; jj < 4; jj++) acc[i][jj] += a[i] * b[jj];
        }
        __syncthreads();
    }
#pragma unroll
    for (int i = 0; i < 4; i++) {
        long r = rb * 64 + tr * 4 + i;
#pragma unroll
        for (int jj = 0; jj < 4; jj++) {
            long c = cb + tc * 4 + jj;
            out[r * G3 + c] = acc[i][jj] + bias[c];
        }
    }
}

// ---------------------------------------------------------------------------
// Persistent encoder layer. Per block: 24 gate-cols (3 gates x 8 hidden cols)
// resident in SMEM for all 256 steps. NTH=512 threads.
// compute map: tid = ks*64 + bg*4 + cg   (k-split 8, 16 b-groups, 4 c-groups)
// epilogue map: tid = eb*8 + ej          (b-major -> coalesced I/O)
// out addr = t*out_t + b*out_b + col ; gi precomputed (includes bi).
// SMEM: ws[1024*26] | hs[128*72] | red[8*24*68] | gis[64*25]
// ---------------------------------------------------------------------------
extern __shared__ float sm[];

__global__ void __launch_bounds__(NTH) enc_layer_kernel(
    const float* __restrict__ gi,
    const float* __restrict__ Wh,
    const float* __restrict__ bh,
    float* __restrict__ out, long out_t, long out_b,
    unsigned* __restrict__ bars)
{
    float* ws  = sm;                  // 26624 f
    float* hs  = ws + 1024 * 26;      // 9216 f
    float* red = hs + 128 * 72;       // 13056 f
    float* gis = red + 8 * 24 * 68;   // 1600 f

    const int tid = threadIdx.x;
    const int j0  = blockIdx.x << 3;
    const int ks  = tid >> 6;
    const int bg  = (tid >> 2) & 15;
    const int cg  = tid & 3;
    const int eb  = tid >> 3;
    const int ej  = tid & 7;
    const int ecol = j0 + ej;

    // load persistent weight slice, transposed: ws[k*26 + c]
    for (int i = 0; i < 48; i++) {
        int idx = tid + (i << 9);
        int c = idx >> 10;            // 0..23
        int k = idx & 1023;
        int row = ((c >> 3) << 10) + j0 + (c & 7);
        ws[k * 26 + c] = Wh[(long)row * HID + k];
    }
    const float bhr = bh[ecol];
    const float bhz = bh[HID + ecol];
    const float bhn = bh[2 * HID + ecol];
    __syncthreads();

    for (int t = 0; t < TSRC; t++) {
        float acc[6][4];
#pragma unroll
        for (int ci = 0; ci < 6; ci++)
#pragma unroll
            for (int bi = 0; bi < 4; bi++) acc[ci][bi] = 0.0f;

        // stage gi tile for this step: 64 b x 24 local cols
        {
            const float* gi_t = gi + (long)t * BB * G3;
#pragma unroll
            for (int i = 0; i < 3; i++) {
                int idx = (i << 9) + tid;
                int b = idx / 24;
                int rem = idx - b * 24;
                gis[b * 25 + rem] = gi_t[(long)b * G3 + ((rem >> 3) << 10) + j0 + (rem & 7)];
            }
        }

        const float* hprev = out + (long)(t - 1) * out_t;
        if (t > 0) {
            for (int k0 = 0; k0 < HID; k0 += 128) {
                __syncthreads();
                // stage 128-k chunk of h_prev: hs[k*72 + b]
#pragma unroll
                for (int i = 0; i < 4; i++) {
                    int idx = (i << 9) + tid;
                    int b  = idx & 63;
                    int k4 = idx >> 6;
                    float4 v = *(const float4*)(hprev + (long)b * out_b + k0 + (k4 << 2));
                    int base = (k4 << 2) * 72 + b;
                    hs[base]       = v.x;
                    hs[base + 72]  = v.y;
                    hs[base + 144] = v.z;
                    hs[base + 216] = v.w;
                }
                __syncthreads();
                const float* wc = ws + k0 * 26 + cg * 6;
#pragma unroll 4
                for (int i = 0; i < 16; i++) {
                    int kk = (i << 3) + ks;
                    const float* wr = wc + kk * 26;
                    float2 w01 = *(const float2*)(wr);
                    float2 w23 = *(const float2*)(wr + 2);
                    float2 w45 = *(const float2*)(wr + 4);
                    float4 hv  = *(const float4*)(hs + kk * 72 + (bg << 2));
                    float wv[6] = {w01.x, w01.y, w23.x, w23.y, w45.x, w45.y};
                    float hb[4] = {hv.x, hv.y, hv.z, hv.w};
#pragma unroll
                    for (int ci = 0; ci < 6; ci++)
#pragma unroll
                        for (int bi = 0; bi < 4; bi++) acc[ci][bi] += wv[ci] * hb[bi];
                }
            }
        }
        __syncthreads();
        // write k-split partials: red[ks][c][b]
        {
            float* rp = red + ks * 1632 + (cg * 6) * 68 + (bg << 2);
#pragma unroll
            for (int ci = 0; ci < 6; ci++)
                *(float4*)(rp + ci * 68) =
                    make_float4(acc[ci][0], acc[ci][1], acc[ci][2], acc[ci][3]);
        }
        __syncthreads();

        // epilogue: one (b, col) per thread
        float s0 = 0.f, s1 = 0.f, s2 = 0.f;
#pragma unroll
        for (int k = 0; k < 8; k++) {
            const float* rp = red + k * 1632 + eb;
            s0 += rp[(ej)      * 68];
            s1 += rp[(8 + ej)  * 68];
            s2 += rp[(16 + ej) * 68];
        }
        const float* gp = gis + eb * 25;
        float GR = gp[ej], GZ = gp[8 + ej], GN = gp[16 + ej];
        float hold = (t > 0) ? hprev[(long)eb * out_b + ecol] : 0.0f;
        float r = sigf(GR + s0 + bhr);
        float z = sigf(GZ + s1 + bhz);
        float n = tanhf(GN + r * (s2 + bhn));
        float hn = (1.0f - z) * n + z * hold;
        out[(long)t * out_t + (long)eb * out_b + ecol] = hn;

        if (t < TSRC - 1) grid_bar(&bars[t]);
    }
}

// ---------------------------------------------------------------------------
// Decoder per-step GRU (unchanged from baseline; ~2.5 ms total, optimize later)
// ---------------------------------------------------------------------------
__global__ void __launch_bounds__(256) gru_step(
    const float* __restrict__ x, int x_zero, int Kx,
    const float* __restrict__ Wi, const float* __restrict__ bi,
    const float* __restrict__ h_prev, long h_stride,
    const float* __restrict__ Wh, const float* __restrict__ bh,
    float* __restrict__ out1, long s1,
    float* __restrict__ out2, long s2)
{
    __shared__ float hs[32][66];
    __shared__ float wsn[24][33];
    const int tid = threadIdx.x;
    const int j   = tid & 7;
    const int m   = (tid >> 3) << 1;
    const int j0  = blockIdx.x << 3;

    float ar0 = 0.f, ar1 = 0.f, az0 = 0.f, az1 = 0.f;
    float ain0 = 0.f, ain1 = 0.f, ahn0 = 0.f, ahn1 = 0.f;

    if (!x_zero) {
        for (int k0 = 0; k0 < Kx; k0 += 32) {
#pragma unroll
            for (int i = 0; i < 8; i++) {
                int lin = tid + (i << 8);
                hs[lin & 31][lin >> 5] = x[(long)(lin >> 5) * Kx + k0 + (lin & 31)];
            }
#pragma unroll
            for (int i = 0; i < 3; i++) {
                int lin = tid + (i << 8);
                int row = lin >> 5, kk = lin & 31;
                wsn[row][kk] = Wi[(long)((row >> 3) * HID + j0 + (row & 7)) * Kx + k0 + kk];
            }
            __syncthreads();
#pragma unroll
            for (int kk = 0; kk < 32; kk++) {
                float2 hv = *(const float2*)&hs[kk][m];
                float wr = wsn[j][kk], wz = wsn[8 + j][kk], wn = wsn[16 + j][kk];
                ar0 += hv.x * wr;  ar1 += hv.y * wr;
                az0 += hv.x * wz;  az1 += hv.y * wz;
                ain0 += hv.x * wn; ain1 += hv.y * wn;
            }
            __syncthreads();
        }
    }
    for (int k0 = 0; k0 < HID; k0 += 32) {
#pragma unroll
        for (int i = 0; i < 8; i++) {
            int lin = tid + (i << 8);
            hs[lin & 31][lin >> 5] = h_prev[(long)(lin >> 5) * h_stride + k0 + (lin & 31)];
        }
#pragma unroll
        for (int i = 0; i < 3; i++) {
            int lin = tid + (i << 8);
            int row = lin >> 5, kk = lin & 31;
            wsn[row][kk] = Wh[(long)((row >> 3) * HID + j0 + (row & 7)) * HID + k0 + kk];
        }
        __syncthreads();
#pragma unroll
        for (int kk = 0; kk < 32; kk++) {
            float2 hv = *(const float2*)&hs[kk][m];
            float wr = wsn[j][kk], wz = wsn[8 + j][kk], wn = wsn[16 + j][kk];
            ar0 += hv.x * wr;  ar1 += hv.y * wr;
            az0 += hv.x * wz;  az1 += hv.y * wz;
            ahn0 += hv.x * wn; ahn1 += hv.y * wn;
        }
        __syncthreads();
    }

    const int col = j0 + j;
    const float bhr = bh[col], bhz = bh[HID + col], bhn = bh[2 * HID + col];
    const float bir = bi[col], biz = bi[HID + col], bin = bi[2 * HID + col];
    float hold0 = h_prev[(long)m * h_stride + col];
    float hold1 = h_prev[(long)(m + 1) * h_stride + col];

    float r0 = sigf(bir + ar0 + bhr);
    float z0 = sigf(biz + az0 + bhz);
    float n0 = tanhf(bin + ain0 + r0 * (ahn0 + bhn));
    float hn0 = (1.f - z0) * n0 + z0 * hold0;
    float r1 = sigf(bir + ar1 + bhr);
    float z1 = sigf(biz + az1 + bhz);
    float n1 = tanhf(bin + ain1 + r1 * (ahn1 + bhn));
    float hn1 = (1.f - z1) * n1 + z1 * hold1;

    out1[(long)m * s1 + col] = hn0;
    out1[(long)(m + 1) * s1 + col] = hn1;
    if (out2) {
        out2[(long)m * s2 + col] = hn0;
        out2[(long)(m + 1) * s2 + col] = hn1;
    }
}

__global__ void __launch_bounds__(256) fc_kernel(
    const float* __restrict__ h,
    const float* __restrict__ W, const float* __restrict__ bias,
    float* __restrict__ o1, long s1,
    float* __restrict__ o2, long s2)
{
    __shared__ float hs[32][66];
    __shared__ float wsn[8][33];
    const int tid = threadIdx.x;
    const int c   = tid & 7;
    const int m   = (tid >> 3) << 1;
    const int c0  = blockIdx.x << 3;
    float a0 = 0.f, a1 = 0.f;

    for (int k0 = 0; k0 < HID; k0 += 32) {
#pragma unroll
        for (int i = 0; i < 8; i++) {
            int lin = tid + (i << 8);
            hs[lin & 31][lin >> 5] = h[(long)(lin >> 5) * HID + k0 + (lin & 31)];
        }
        wsn[tid >> 5][tid & 31] = W[(long)(c0 + (tid >> 5)) * HID + k0 + (tid & 31)];
        __syncthreads();
#pragma unroll
        for (int kk = 0; kk < 32; kk++) {
            float2 hv = *(const float2*)&hs[kk][m];
            float w = wsn[c][kk];
            a0 += hv.x * w;
            a1 += hv.y * w;
        }
        __syncthreads();
    }
    int col = c0 + c;
    float bv = bias[col];
    o1[(long)m * s1 + col] = a0 + bv;
    o1[(long)(m + 1) * s1 + col] = a1 + bv;
    o2[(long)m * s2 + col] = a0 + bv;
    o2[(long)(m + 1) * s2 + col] = a1 + bv;
}

// ---------------------------------------------------------------------------
extern "C" void kernel_launch(void* const* d_in, const int* in_sizes, int n_in,
                              void* d_out, int out_size)
{
    const float* src  = (const float*)d_in[0];
    const float* eWi0 = (const float*)d_in[2];
    const float* eWh0 = (const float*)d_in[3];
    const float* ebi0 = (const float*)d_in[4];
    const float* ebh0 = (const float*)d_in[5];
    const float* eWi1 = (const float*)d_in[6];
    const float* eWh1 = (const float*)d_in[7];
    const float* ebi1 = (const float*)d_in[8];
    const float* ebh1 = (const float*)d_in[9];
    const float* dWi0 = (const float*)d_in[10];
    const float* dWh0 = (const float*)d_in[11];
    const float* dbi0 = (const float*)d_in[12];
    const float* dbh0 = (const float*)d_in[13];
    const float* dWi1 = (const float*)d_in[14];
    const float* dWh1 = (const float*)d_in[15];
    const float* dbi1 = (const float*)d_in[16];
    const float* dbh1 = (const float*)d_in[17];
    const float* fcW  = (const float*)d_in[18];
    const float* fcb  = (const float*)d_in[19];

    float* out     = (float*)d_out;                   // [64, 64, 256]
    float* enc_out = out + (long)BB * TTRG * INP;     // [64, 256, 1024]
    float* dec_out = enc_out + (long)BB * TSRC * HID; // [64, 64, 1024]

    float *gi, *ys0, *h0, *h1, *xbuf;
    unsigned* bars;
    cudaGetSymbolAddress((void**)&gi,   g_gi);
    cudaGetSymbolAddress((void**)&ys0,  g_ys0);
    cudaGetSymbolAddress((void**)&h0,   g_h0);
    cudaGetSymbolAddress((void**)&h1,   g_h1);
    cudaGetSymbolAddress((void**)&xbuf, g_x);
    cudaGetSymbolAddress((void**)&bars, g_bars);

    const int SMEM_BYTES = (1024 * 26 + 128 * 72 + 8 * 24 * 68 + 64 * 25) * 4;
    cudaFuncSetAttribute(enc_layer_kernel,
                         cudaFuncAttributeMaxDynamicSharedMemorySize, SMEM_BYTES);

    dim3 gridGi(48, 256);

    // ---------- encoder layer 0 ----------
    gi_gemm<<<gridGi, 256>>>(src, 65536L, 256L, eWi0, ebi0, gi, 256);
    cudaMemsetAsync(bars, 0, sizeof(g_bars));
    enc_layer_kernel<<<GRID, NTH, SMEM_BYTES>>>(
        gi, eWh0, ebh0, ys0, (long)BB * HID, (long)HID, bars);

    // ---------- encoder layer 1 ----------
    gi_gemm<<<gridGi, 256>>>(ys0, 1024L, 65536L, eWi1, ebi1, gi, 1024);
    cudaMemsetAsync(bars, 0, sizeof(g_bars));
    enc_layer_kernel<<<GRID, NTH, SMEM_BYTES>>>(
        gi, eWh1, ebh1, enc_out, (long)HID, (long)TSRC * HID, bars);

    // ---------- decoder (autoregressive, 64 steps) ----------
    for (int t = 0; t < TTRG; t++) {
        int w = t & 1;
        const float* h0p = t ? h0 + (long)(1 - w) * BB * HID
                             : ys0 + (long)(TSRC - 1) * BB * HID;
        gru_step<<<128, 256>>>(
            xbuf, (t == 0), INP, dWi0, dbi0,
            h0p, (long)HID,
            dWh0, dbh0,
            h0 + (long)w * BB * HID, (long)HID,
            nullptr, 0);

        const float* h1p = t ? h1 + (long)(1 - w) * BB * HID
                             : enc_out + (long)(TSRC - 1) * HID;
        long h1s = t ? (long)HID : (long)TSRC * HID;
        gru_step<<<128, 256>>>(
            h0 + (long)w * BB * HID, 0, HID, dWi1, dbi1,
            h1p, h1s,
            dWh1, dbh1,
            h1 + (long)w * BB * HID, (long)HID,
            dec_out + (long)t * HID, (long)TTRG * HID);

        fc_kernel<<<32, 256>>>(
            h1 + (long)w * BB * HID, fcW, fcb,
            out + (long)t * INP, (long)TTRG * INP,
            xbuf, (long)INP);
    }
}

// round 4
// speedup vs baseline: 1.1412x; 1.1284x over previous
#include <cuda_runtime.h>
#include <math.h>

#define HID  1024
#define INP  256
#define BB   64
#define TSRC 256
#define TTRG 64
#define G3   3072
#define GRID 128
#define NTH  512

typedef unsigned long long ull;

// ---------------- scratch (static device globals; no runtime allocation) ----
__device__ float g_gi [(long)TSRC * BB * G3];   // precomputed input gates
__device__ float g_ys0[(long)TSRC * BB * HID];  // enc layer-0 outputs [t][b][h]
__device__ float g_h0 [2 * BB * HID];           // decoder layer-0 hidden (ping-pong)
__device__ float g_h1 [2 * BB * HID];           // decoder layer-1 hidden (ping-pong)
__device__ float g_x  [BB * INP];               // decoder AR input
__device__ unsigned g_cnt;                      // barrier arrive count (self-resetting)
__device__ unsigned g_phase;                    // barrier release phase (monotonic)

__device__ __forceinline__ float sigf(float x) { return 1.0f / (1.0f + expf(-x)); }

// packed f32x2 helpers (SASS FFMA2 — only reachable via PTX)
#define FMA2(a, b, c) asm volatile("fma.rn.f32x2 %0, %1, %2, %0;" : "+l"(a) : "l"(b), "l"(c))
#define PACK2(d, x)   asm volatile("mov.b64 %0, {%1, %1};" : "=l"(d) : "f"(x))
#define UNPK2(lo, hi, v) asm volatile("mov.b64 {%0, %1}, %2;" : "=f"(lo), "=f"(hi) : "l"(v))

// ---------------------------------------------------------------------------
// Replay-safe grid barrier: monotonic phase + self-resetting counter.
// All GRID blocks co-resident (1 block/SM). Call uniformly from all threads.
// ---------------------------------------------------------------------------
__device__ __forceinline__ void grid_bar(unsigned& target)
{
    __threadfence();
    __syncthreads();
    if (threadIdx.x == 0) {
        unsigned a = atomicAdd(&g_cnt, 1u);
        if (a == (unsigned)GRID - 1u) {
            g_cnt = 0u;
            __threadfence();
            atomicAdd(&g_phase, 1u);
        } else {
            for (;;) {
                unsigned ph;
                asm volatile("ld.acquire.gpu.u32 %0, [%1];" : "=r"(ph) : "l"(&g_phase));
                if ((int)(ph - target) >= 0) break;
                __nanosleep(64);
            }
        }
        __threadfence();
    }
    __syncthreads();
    target++;
}

// ---------------------------------------------------------------------------
// Shared tiles/layout for the recurrent kernels:
//   ws/wsd : [k][28]  weight tile transposed (24 used cols, pad 28 for LDS.64)
//   hs     : [k][72]  staged 128-k x 64-b activation chunk
//   red    : [8][24][68]  k-split partials
// compute map : tid = ks*64 + bg*4 + cg  (k-split 8, 16 b-groups of 4, 4 c-groups of 6)
// epilogue map: tid = eb*8 + ej
// ---------------------------------------------------------------------------
extern __shared__ float sm[];

__device__ __forceinline__ void stage_x(
    float* hs, const float* __restrict__ X, long xs, int k0, int tid)
{
#pragma unroll
    for (int i = 0; i < 4; i++) {
        int idx = (i << 9) + tid;
        int b = idx & 63, k4 = idx >> 6;
        float4 v = *(const float4*)(X + (long)b * xs + k0 + (k4 << 2));
        int base = (k4 << 2) * 72 + b;
        hs[base]       = v.x;
        hs[base + 72]  = v.y;
        hs[base + 144] = v.z;
        hs[base + 216] = v.w;
    }
}

__device__ __forceinline__ void gemm_chunk(
    const float* __restrict__ wsp, const float* __restrict__ hs,
    ull (&acc)[3][4], int ks, int bg, int cg)
{
#pragma unroll 4
    for (int i = 0; i < 16; i++) {
        int kk = (i << 3) + ks;
        const ull* wr = (const ull*)(wsp + kk * 28 + cg * 6);
        ull w0 = wr[0], w1 = wr[1], w2 = wr[2];
        float4 hv = *(const float4*)(hs + kk * 72 + (bg << 2));
        ull hb0, hb1, hb2, hb3;
        PACK2(hb0, hv.x); PACK2(hb1, hv.y); PACK2(hb2, hv.z); PACK2(hb3, hv.w);
        FMA2(acc[0][0], w0, hb0); FMA2(acc[0][1], w0, hb1);
        FMA2(acc[0][2], w0, hb2); FMA2(acc[0][3], w0, hb3);
        FMA2(acc[1][0], w1, hb0); FMA2(acc[1][1], w1, hb1);
        FMA2(acc[1][2], w1, hb2); FMA2(acc[1][3], w1, hb3);
        FMA2(acc[2][0], w2, hb0); FMA2(acc[2][1], w2, hb1);
        FMA2(acc[2][2], w2, hb2); FMA2(acc[2][3], w2, hb3);
    }
}

__device__ __forceinline__ void zero_acc(ull (&acc)[3][4])
{
#pragma unroll
    for (int c = 0; c < 3; c++)
#pragma unroll
        for (int b = 0; b < 4; b++) acc[c][b] = 0ull;
}

__device__ __forceinline__ void dump_red(
    float* red, ull (&acc)[3][4], int ks, int bg, int cg)
{
    float* rp = red + ks * 1632 + (cg * 6) * 68 + (bg << 2);
#pragma unroll
    for (int cp = 0; cp < 3; cp++) {
        float l0, h0, l1, h1, l2, h2, l3, h3;
        UNPK2(l0, h0, acc[cp][0]); UNPK2(l1, h1, acc[cp][1]);
        UNPK2(l2, h2, acc[cp][2]); UNPK2(l3, h3, acc[cp][3]);
        *(float4*)(rp + (2 * cp) * 68)     = make_float4(l0, l1, l2, l3);
        *(float4*)(rp + (2 * cp + 1) * 68) = make_float4(h0, h1, h2, h3);
    }
}

// streamed-weight GEMM phase (decoder): stage W+X chunks, accumulate
__device__ __forceinline__ void stream_phase(
    const float* __restrict__ X, long xs,
    const float* __restrict__ W, int K,
    float* wsd, float* hs, ull (&acc)[3][4],
    int tid, int ks, int bg, int cg, int j0)
{
    for (int k0 = 0; k0 < K; k0 += 128) {
        __syncthreads();
        stage_x(hs, X, xs, k0, tid);
#pragma unroll
        for (int i = 0; i < 6; i++) {
            int idx = (i << 9) + tid;           // < 3072
            int c = idx >> 7;                   // 0..23
            int k = idx & 127;
            int row = ((c >> 3) << 10) + j0 + (c & 7);
            wsd[k * 28 + c] = W[(long)row * (long)K + k0 + k];
        }
        __syncthreads();
        gemm_chunk(wsd, hs, acc, ks, bg, cg);
    }
}

// ---------------------------------------------------------------------------
// Batched input-gate GEMM (unchanged)
// ---------------------------------------------------------------------------
__global__ void __launch_bounds__(256) gi_gemm(
    const float* __restrict__ X, long sb, long st,
    const float* __restrict__ W, const float* __restrict__ bias,
    float* __restrict__ out, int K)
{
    __shared__ float Xs[32][66];
    __shared__ float Ws[32][66];
    const int tid = threadIdx.x;
    const int tr  = tid >> 4;
    const int tc  = tid & 15;
    const long cb = (long)blockIdx.x * 64;
    const long rb = (long)blockIdx.y;
    const float* Xb = X + rb * st;

    float acc[4][4];
#pragma unroll
    for (int i = 0; i < 4; i++)
#pragma unroll
        for (int jj = 0; jj < 4; jj++) acc[i][jj] = 0.0f;

    for (int k0 = 0; k0 < K; k0 += 32) {
#pragma unroll
        for (int i = 0; i < 8; i++) {
            int lin = tid + (i << 8);
            int rr = lin >> 5, kk = lin & 31;
            Xs[kk][rr] = Xb[(long)rr * sb + k0 + kk];
            Ws[kk][rr] = W[(cb + rr) * (long)K + k0 + kk];
        }
        __syncthreads();
#pragma unroll
        for (int kk = 0; kk < 32; kk++) {
            float2 a01 = *(const float2*)&Xs[kk][tr * 4];
            float2 a23 = *(const float2*)&Xs[kk][tr * 4 + 2];
            float2 b01 = *(const float2*)&Ws[kk][tc * 4];
            float2 b23 = *(const float2*)&Ws[kk][tc * 4 + 2];
            float a[4] = {a01.x, a01.y, a23.x, a23.y};
            float b[4] = {b01.x, b01.y, b23.x, b23.y};
#pragma unroll
            for (int i = 0; i < 4; i++)
#pragma unroll
                for (int jj = 0; jj < 4; jj++) acc[i][jj] += a[i] * b[jj];
        }
        __syncthreads();
    }
#pragma unroll
    for (int i = 0; i < 4; i++) {
        long r = rb * 64 + tr * 4 + i;
#pragma unroll
        for (int jj = 0; jj < 4; jj++) {
            long c = cb + tc * 4 + jj;
            out[r * G3 + c] = acc[i][jj] + bias[c];
        }
    }
}

// ---------------------------------------------------------------------------
// Persistent encoder layer (256 GRU steps; Wh slice resident in SMEM)
// SMEM: ws[1024*28] | hs[128*72] | red[8*24*68] | gis[64*25]
// ---------------------------------------------------------------------------
__global__ void __launch_bounds__(NTH, 1) enc_layer_kernel(
    const float* __restrict__ gi,
    const float* __restrict__ Wh,
    const float* __restrict__ bh,
    float* __restrict__ out, long out_t, long out_b)
{
    float* ws  = sm;                  // 28672 f
    float* hs  = ws + 1024 * 28;      // 9216 f
    float* red = hs + 128 * 72;       // 13056 f
    float* gis = red + 8 * 24 * 68;   // 1600 f

    const int tid = threadIdx.x;
    const int j0  = blockIdx.x << 3;
    const int ks  = tid >> 6;
    const int bg  = (tid >> 2) & 15;
    const int cg  = tid & 3;
    const int eb  = tid >> 3;
    const int ej  = tid & 7;
    const int ecol = j0 + ej;

    unsigned target;
    { volatile unsigned* pp = &g_phase; target = *pp + 1u; }

    // persistent weight slice, transposed: ws[k*28 + c]
    for (int i = 0; i < 48; i++) {
        int idx = tid + (i << 9);
        int c = idx >> 10;            // 0..23
        int k = idx & 1023;
        int row = ((c >> 3) << 10) + j0 + (c & 7);
        ws[k * 28 + c] = Wh[(long)row * HID + k];
    }
    const float bhr = bh[ecol];
    const float bhz = bh[HID + ecol];
    const float bhn = bh[2 * HID + ecol];
    __syncthreads();

    for (int t = 0; t < TSRC; t++) {
        ull acc[3][4];
        zero_acc(acc);

        // stage gi tile: 64 b x 24 local cols
        {
            const float* gi_t = gi + (long)t * BB * G3;
#pragma unroll
            for (int i = 0; i < 3; i++) {
                int idx = (i << 9) + tid;
                int b = idx / 24;
                int rem = idx - b * 24;
                gis[b * 25 + rem] = gi_t[(long)b * G3 + ((rem >> 3) << 10) + j0 + (rem & 7)];
            }
        }

        const float* hprev = out + (long)(t - 1) * out_t;
        if (t > 0) {
            for (int k0 = 0; k0 < HID; k0 += 128) {
                __syncthreads();
                stage_x(hs, hprev, out_b, k0, tid);
                __syncthreads();
                gemm_chunk(ws + k0 * 28, hs, acc, ks, bg, cg);
            }
        }
        __syncthreads();
        dump_red(red, acc, ks, bg, cg);
        __syncthreads();

        // epilogue: one (b, col) per thread
        float s0 = 0.f, s1 = 0.f, s2 = 0.f;
#pragma unroll
        for (int k = 0; k < 8; k++) {
            const float* rp = red + k * 1632 + eb;
            s0 += rp[(ej)      * 68];
            s1 += rp[(8 + ej)  * 68];
            s2 += rp[(16 + ej) * 68];
        }
        const float* gp = gis + eb * 25;
        float GR = gp[ej], GZ = gp[8 + ej], GN = gp[16 + ej];
        float hold = (t > 0) ? hprev[(long)eb * out_b + ecol] : 0.0f;
        float r = sigf(GR + s0 + bhr);
        float z = sigf(GZ + s1 + bhz);
        float n = tanhf(GN + r * (s2 + bhn));
        float hn = (1.0f - z) * n + z * hold;
        out[(long)t * out_t + (long)eb * out_b + ecol] = hn;

        if (t < TSRC - 1) grid_bar(target);
    }
}

// ---------------------------------------------------------------------------
// Persistent decoder: 64 steps of (layer0, layer1, fc), streamed weights.
// SMEM: wsd[128*28] | hs[128*72] | redA[8*24*68] | redB[8*24*68]
// ---------------------------------------------------------------------------
__global__ void __launch_bounds__(NTH, 1) dec_kernel(
    const float* __restrict__ dWi0, const float* __restrict__ dWh0,
    const float* __restrict__ dbi0, const float* __restrict__ dbh0,
    const float* __restrict__ dWi1, const float* __restrict__ dWh1,
    const float* __restrict__ dbi1, const float* __restrict__ dbh1,
    const float* __restrict__ fcW,  const float* __restrict__ fcb,
    const float* __restrict__ enc0_hT,   // ys0 last step, stride HID
    const float* __restrict__ enc1_hT,   // enc_out last step, stride TSRC*HID
    float* __restrict__ h0buf, float* __restrict__ h1buf, float* __restrict__ xbuf,
    float* __restrict__ out,             // [B][TTRG][INP]
    float* __restrict__ dec_out)         // [B][TTRG][HID]
{
    float* wsd  = sm;                    // 3584 f
    float* hs   = wsd + 128 * 28;        // 9216 f
    float* redA = hs + 128 * 72;         // 13056 f
    float* redB = redA + 8 * 24 * 68;    // 13056 f

    const int tid = threadIdx.x;
    const int j0  = blockIdx.x << 3;
    const int ks  = tid >> 6;
    const int bg  = (tid >> 2) & 15;
    const int cg  = tid & 3;
    const int eb  = tid >> 3;
    const int ej  = tid & 7;
    const int ecol = j0 + ej;
    // fc mapping: tid = b*8 + c*4 + ksf
    const int fb  = tid >> 3;
    const int fcc = (tid >> 2) & 1;
    const int fks = tid & 3;
    const int fcol = (blockIdx.x << 1) + fcc;

    unsigned target;
    { volatile unsigned* pp = &g_phase; target = *pp + 1u; }

    const float b0ir = dbi0[ecol], b0iz = dbi0[HID + ecol], b0in = dbi0[2 * HID + ecol];
    const float b0hr = dbh0[ecol], b0hz = dbh0[HID + ecol], b0hn = dbh0[2 * HID + ecol];
    const float b1ir = dbi1[ecol], b1iz = dbi1[HID + ecol], b1in = dbi1[2 * HID + ecol];
    const float b1hr = dbh1[ecol], b1hz = dbh1[HID + ecol], b1hn = dbh1[2 * HID + ecol];
    const float fcbv = fcb[fcol];

    ull acc[3][4];

    for (int t = 0; t < TTRG; t++) {
        const int w = t & 1;

        // ================= layer 0 =================
        zero_acc(acc);
        if (t > 0)
            stream_phase(xbuf, INP, dWi0, INP, wsd, hs, acc, tid, ks, bg, cg, j0);
        dump_red(redA, acc, ks, bg, cg);

        const float* h0p = t ? h0buf + (long)(1 - w) * BB * HID : enc0_hT;
        zero_acc(acc);
        stream_phase(h0p, HID, dWh0, HID, wsd, hs, acc, tid, ks, bg, cg, j0);
        dump_red(redB, acc, ks, bg, cg);
        __syncthreads();
        {
            float a0 = 0.f, a1 = 0.f, a2 = 0.f, c0 = 0.f, c1 = 0.f, c2 = 0.f;
#pragma unroll
            for (int k = 0; k < 8; k++) {
                const float* ra = redA + k * 1632 + eb;
                const float* rb = redB + k * 1632 + eb;
                a0 += ra[ej * 68];        c0 += rb[ej * 68];
                a1 += ra[(8 + ej) * 68];  c1 += rb[(8 + ej) * 68];
                a2 += ra[(16 + ej) * 68]; c2 += rb[(16 + ej) * 68];
            }
            float hold = h0p[(long)eb * HID + ecol];
            float r = sigf(a0 + b0ir + c0 + b0hr);
            float z = sigf(a1 + b0iz + c1 + b0hz);
            float n = tanhf(a2 + b0in + r * (c2 + b0hn));
            h0buf[(long)w * BB * HID + (long)eb * HID + ecol] = (1.f - z) * n + z * hold;
        }
        grid_bar(target);

        // ================= layer 1 =================
        const float* x1 = h0buf + (long)w * BB * HID;
        zero_acc(acc);
        stream_phase(x1, HID, dWi1, HID, wsd, hs, acc, tid, ks, bg, cg, j0);
        dump_red(redA, acc, ks, bg, cg);

        const float* h1p = t ? h1buf + (long)(1 - w) * BB * HID : enc1_hT;
        const long   h1s = t ? (long)HID : (long)TSRC * HID;
        zero_acc(acc);
        stream_phase(h1p, h1s, dWh1, HID, wsd, hs, acc, tid, ks, bg, cg, j0);
        dump_red(redB, acc, ks, bg, cg);
        __syncthreads();
        {
            float a0 = 0.f, a1 = 0.f, a2 = 0.f, c0 = 0.f, c1 = 0.f, c2 = 0.f;
#pragma unroll
            for (int k = 0; k < 8; k++) {
                const float* ra = redA + k * 1632 + eb;
                const float* rb = redB + k * 1632 + eb;
                a0 += ra[ej * 68];        c0 += rb[ej * 68];
                a1 += ra[(8 + ej) * 68];  c1 += rb[(8 + ej) * 68];
                a2 += ra[(16 + ej) * 68]; c2 += rb[(16 + ej) * 68];
            }
            float hold = h1p[(long)eb * h1s + ecol];
            float r = sigf(a0 + b1ir + c0 + b1hr);
            float z = sigf(a1 + b1iz + c1 + b1hz);
            float n = tanhf(a2 + b1in + r * (c2 + b1hn));
            float hn = (1.f - z) * n + z * hold;
            h1buf[(long)w * BB * HID + (long)eb * HID + ecol] = hn;
            dec_out[(long)eb * TTRG * HID + (long)t * HID + ecol] = hn;
        }
        grid_bar(target);

        // ================= fc =================
        // stage this block's 2 fcW rows: wsd[k*2 + c]
        {
            const float* h1c = h1buf + (long)w * BB * HID;
#pragma unroll
            for (int i = 0; i < 4; i++) {
                int idx = (i << 9) + tid;       // < 2048
                int k = idx >> 1, c = idx & 1;
                wsd[idx] = fcW[(long)((blockIdx.x << 1) + c) * HID + k];
            }
            float partial = 0.f;
            for (int k0 = 0; k0 < HID; k0 += 128) {
                __syncthreads();
                stage_x(hs, h1c, HID, k0, tid);
                __syncthreads();
#pragma unroll 8
                for (int i = 0; i < 32; i++) {
                    int kk = fks * 32 + i;
                    partial += hs[kk * 72 + fb] * wsd[(k0 + kk) * 2 + fcc];
                }
            }
            __syncthreads();
            redA[tid] = partial;
            __syncthreads();
            if (fks == 0) {
                float s = redA[tid] + redA[tid + 1] + redA[tid + 2] + redA[tid + 3] + fcbv;
                out [(long)fb * TTRG * INP + (long)t * INP + fcol] = s;
                xbuf[(long)fb * INP + fcol] = s;
            }
        }
        grid_bar(target);
    }
}

// ---------------------------------------------------------------------------
extern "C" void kernel_launch(void* const* d_in, const int* in_sizes, int n_in,
                              void* d_out, int out_size)
{
    const float* src  = (const float*)d_in[0];
    const float* eWi0 = (const float*)d_in[2];
    const float* eWh0 = (const float*)d_in[3];
    const float* ebi0 = (const float*)d_in[4];
    const float* ebh0 = (const float*)d_in[5];
    const float* eWi1 = (const float*)d_in[6];
    const float* eWh1 = (const float*)d_in[7];
    const float* ebi1 = (const float*)d_in[8];
    const float* ebh1 = (const float*)d_in[9];
    const float* dWi0 = (const float*)d_in[10];
    const float* dWh0 = (const float*)d_in[11];
    const float* dbi0 = (const float*)d_in[12];
    const float* dbh0 = (const float*)d_in[13];
    const float* dWi1 = (const float*)d_in[14];
    const float* dWh1 = (const float*)d_in[15];
    const float* dbi1 = (const float*)d_in[16];
    const float* dbh1 = (const float*)d_in[17];
    const float* fcW  = (const float*)d_in[18];
    const float* fcb  = (const float*)d_in[19];

    float* out     = (float*)d_out;                   // [64, 64, 256]
    float* enc_out = out + (long)BB * TTRG * INP;     // [64, 256, 1024]
    float* dec_out = enc_out + (long)BB * TSRC * HID; // [64, 64, 1024]

    float *gi, *ys0, *h0, *h1, *xbuf;
    cudaGetSymbolAddress((void**)&gi,   g_gi);
    cudaGetSymbolAddress((void**)&ys0,  g_ys0);
    cudaGetSymbolAddress((void**)&h0,   g_h0);
    cudaGetSymbolAddress((void**)&h1,   g_h1);
    cudaGetSymbolAddress((void**)&xbuf, g_x);

    const int ENC_SMEM = (1024 * 28 + 128 * 72 + 8 * 24 * 68 + 64 * 25) * 4;
    const int DEC_SMEM = (128 * 28 + 128 * 72 + 2 * 8 * 24 * 68) * 4;
    cudaFuncSetAttribute(enc_layer_kernel,
                         cudaFuncAttributeMaxDynamicSharedMemorySize, ENC_SMEM);
    cudaFuncSetAttribute(dec_kernel,
                         cudaFuncAttributeMaxDynamicSharedMemorySize, DEC_SMEM);

    dim3 gridGi(48, 256);

    // ---------- encoder layer 0 ----------
    gi_gemm<<<gridGi, 256>>>(src, 65536L, 256L, eWi0, ebi0, gi, 256);
    enc_layer_kernel<<<GRID, NTH, ENC_SMEM>>>(
        gi, eWh0, ebh0, ys0, (long)BB * HID, (long)HID);

    // ---------- encoder layer 1 ----------
    gi_gemm<<<gridGi, 256>>>(ys0, 1024L, 65536L, eWi1, ebi1, gi, 1024);
    enc_layer_kernel<<<GRID, NTH, ENC_SMEM>>>(
        gi, eWh1, ebh1, enc_out, (long)HID, (long)TSRC * HID);

    // ---------- decoder ----------
    dec_kernel<<<GRID, NTH, DEC_SMEM>>>(
        dWi0, dWh0, dbi0, dbh0,
        dWi1, dWh1, dbi1, dbh1,
        fcW, fcb,
        ys0 + (long)(TSRC - 1) * BB * HID,
        enc_out + (long)(TSRC - 1) * HID,
        h0, h1, xbuf,
        out, dec_out);
}

// round 6
// speedup vs baseline: 1.2989x; 1.1381x over previous
#include <cuda_runtime.h>
#include <cuda_bf16.h>
#include <math.h>
#include <stdint.h>

#define HID  1024
#define INP  256
#define BB   64
#define TSRC 256
#define TTRG 64
#define G3   3072
#define GRID 128
#define NTH  512

typedef unsigned long long ull;

// ---------------- scratch (static device globals; no runtime allocation) ----
__device__ float g_gi [(long)TSRC * BB * G3];   // precomputed input gates
__device__ float g_ys0[(long)TSRC * BB * HID];  // enc layer-0 outputs [t][b][h]
__device__ float g_h0 [2 * BB * HID];           // decoder layer-0 hidden (ping-pong)
__device__ float g_h1 [2 * BB * HID];           // decoder layer-1 hidden (ping-pong)
__device__ float g_x  [BB * INP];               // decoder AR input
__device__ unsigned g_cnt;                      // barrier arrive count (self-resetting)
__device__ unsigned g_phase;                    // barrier release phase (monotonic)

__device__ __forceinline__ float sigf(float x) { return 1.0f / (1.0f + expf(-x)); }

// packed f32x2 helpers (decoder scalar path)
#define FMA2(a, b, c) asm volatile("fma.rn.f32x2 %0, %1, %2, %0;" : "+l"(a) : "l"(b), "l"(c))
#define PACK2(d, x)   asm volatile("mov.b64 %0, {%1, %1};" : "=l"(d) : "f"(x))
#define UNPK2(lo, hi, v) asm volatile("mov.b64 {%0, %1}, %2;" : "=f"(lo), "=f"(hi) : "l"(v))

// ---- tensor-core primitives ----
__device__ __forceinline__ uint32_t smem_u32(const void* p) {
    uint32_t a;
    asm("{ .reg .u64 t; cvta.to.shared.u64 t, %1; cvt.u32.u64 %0, t; }" : "=r"(a) : "l"(p));
    return a;
}
__device__ __forceinline__ void ldsm4(uint32_t& r0, uint32_t& r1, uint32_t& r2, uint32_t& r3,
                                      uint32_t addr) {
    asm volatile("ldmatrix.sync.aligned.m8n8.x4.shared.b16 {%0,%1,%2,%3}, [%4];"
                 : "=r"(r0), "=r"(r1), "=r"(r2), "=r"(r3) : "r"(addr));
}
__device__ __forceinline__ void ldsm2(uint32_t& r0, uint32_t& r1, uint32_t addr) {
    asm volatile("ldmatrix.sync.aligned.m8n8.x2.shared.b16 {%0,%1}, [%2];"
                 : "=r"(r0), "=r"(r1) : "r"(addr));
}
__device__ __forceinline__ void mma_bf16(float* d, const uint32_t* a, const uint32_t* b) {
    asm volatile(
        "mma.sync.aligned.m16n8k16.row.col.f32.bf16.bf16.f32 "
        "{%0,%1,%2,%3}, {%4,%5,%6,%7}, {%8,%9}, {%0,%1,%2,%3};"
        : "+f"(d[0]), "+f"(d[1]), "+f"(d[2]), "+f"(d[3])
        : "r"(a[0]), "r"(a[1]), "r"(a[2]), "r"(a[3]), "r"(b[0]), "r"(b[1]));
}
__device__ __forceinline__ uint32_t pack_bf2(float x, float y) {
    __nv_bfloat162 v = __floats2bfloat162_rn(x, y);
    return *(uint32_t*)&v;
}
__device__ __forceinline__ void split_bf(float x, __nv_bfloat16& hi, __nv_bfloat16& lo) {
    hi = __float2bfloat16_rn(x);
    lo = __float2bfloat16_rn(x - __bfloat162float(hi));
}

// ---------------------------------------------------------------------------
// Replay-safe grid barrier: monotonic phase + self-resetting counter.
// ---------------------------------------------------------------------------
__device__ __forceinline__ void grid_bar(unsigned& target)
{
    __threadfence();
    __syncthreads();
    if (threadIdx.x == 0) {
        unsigned a = atomicAdd(&g_cnt, 1u);
        if (a == (unsigned)GRID - 1u) {
            g_cnt = 0u;
            __threadfence();
            atomicAdd(&g_phase, 1u);
        } else {
            for (;;) {
                unsigned ph;
                asm volatile("ld.acquire.gpu.u32 %0, [%1];" : "=r"(ph) : "l"(&g_phase));
                if ((int)(ph - target) >= 0) break;
                __nanosleep(64);
            }
        }
        __threadfence();
    }
    __syncthreads();
    target++;
}

extern __shared__ float sm[];

// ---------------------------------------------------------------------------
// Decoder scalar helpers (unchanged)
// ---------------------------------------------------------------------------
__device__ __forceinline__ void stage_x(
    float* hs, const float* __restrict__ X, long xs, int k0, int tid)
{
#pragma unroll
    for (int i = 0; i < 4; i++) {
        int idx = (i << 9) + tid;
        int b = idx & 63, k4 = idx >> 6;
        float4 v = *(const float4*)(X + (long)b * xs + k0 + (k4 << 2));
        int base = (k4 << 2) * 72 + b;
        hs[base]       = v.x;
        hs[base + 72]  = v.y;
        hs[base + 144] = v.z;
        hs[base + 216] = v.w;
    }
}

__device__ __forceinline__ void gemm_chunk(
    const float* __restrict__ wsp, const float* __restrict__ hs,
    ull (&acc)[3][4], int ks, int bg, int cg)
{
#pragma unroll 4
    for (int i = 0; i < 16; i++) {
        int kk = (i << 3) + ks;
        const ull* wr = (const ull*)(wsp + kk * 28 + cg * 6);
        ull w0 = wr[0], w1 = wr[1], w2 = wr[2];
        float4 hv = *(const float4*)(hs + kk * 72 + (bg << 2));
        ull hb0, hb1, hb2, hb3;
        PACK2(hb0, hv.x); PACK2(hb1, hv.y); PACK2(hb2, hv.z); PACK2(hb3, hv.w);
        FMA2(acc[0][0], w0, hb0); FMA2(acc[0][1], w0, hb1);
        FMA2(acc[0][2], w0, hb2); FMA2(acc[0][3], w0, hb3);
        FMA2(acc[1][0], w1, hb0); FMA2(acc[1][1], w1, hb1);
        FMA2(acc[1][2], w1, hb2); FMA2(acc[1][3], w1, hb3);
        FMA2(acc[2][0], w2, hb0); FMA2(acc[2][1], w2, hb1);
        FMA2(acc[2][2], w2, hb2); FMA2(acc[2][3], w2, hb3);
    }
}

__device__ __forceinline__ void zero_acc(ull (&acc)[3][4])
{
#pragma unroll
    for (int c = 0; c < 3; c++)
#pragma unroll
        for (int b = 0; b < 4; b++) acc[c][b] = 0ull;
}

__device__ __forceinline__ void dump_red(
    float* red, ull (&acc)[3][4], int ks, int bg, int cg)
{
    float* rp = red + ks * 1632 + (cg * 6) * 68 + (bg << 2);
#pragma unroll
    for (int cp = 0; cp < 3; cp++) {
        float l0, h0, l1, h1, l2, h2, l3, h3;
        UNPK2(l0, h0, acc[cp][0]); UNPK2(l1, h1, acc[cp][1]);
        UNPK2(l2, h2, acc[cp][2]); UNPK2(l3, h3, acc[cp][3]);
        *(float4*)(rp + (2 * cp) * 68)     = make_float4(l0, l1, l2, l3);
        *(float4*)(rp + (2 * cp + 1) * 68) = make_float4(h0, h1, h2, h3);
    }
}

__device__ __forceinline__ void stream_phase(
    const float* __restrict__ X, long xs,
    const float* __restrict__ W, int K,
    float* wsd, float* hs, ull (&acc)[3][4],
    int tid, int ks, int bg, int cg, int j0)
{
    for (int k0 = 0; k0 < K; k0 += 128) {
        __syncthreads();
        stage_x(hs, X, xs, k0, tid);
#pragma unroll
        for (int i = 0; i < 6; i++) {
            int idx = (i << 9) + tid;
            int c = idx >> 7;
            int k = idx & 127;
            int row = ((c >> 3) << 10) + j0 + (c & 7);
            wsd[k * 28 + c] = W[(long)row * (long)K + k0 + k];
        }
        __syncthreads();
        gemm_chunk(wsd, hs, acc, ks, bg, cg);
    }
}

// ---------------------------------------------------------------------------
// Batched input-gate GEMM (unchanged)
// ---------------------------------------------------------------------------
__global__ void __launch_bounds__(256) gi_gemm(
    const float* __restrict__ X, long sb, long st,
    const float* __restrict__ W, const float* __restrict__ bias,
    float* __restrict__ out, int K)
{
    __shared__ float Xs[32][66];
    __shared__ float Ws[32][66];
    const int tid = threadIdx.x;
    const int tr  = tid >> 4;
    const int tc  = tid & 15;
    const long cb = (long)blockIdx.x * 64;
    const long rb = (long)blockIdx.y;
    const float* Xb = X + rb * st;

    float acc[4][4];
#pragma unroll
    for (int i = 0; i < 4; i++)
#pragma unroll
        for (int jj = 0; jj < 4; jj++) acc[i][jj] = 0.0f;

    for (int k0 = 0; k0 < K; k0 += 32) {
#pragma unroll
        for (int i = 0; i < 8; i++) {
            int lin = tid + (i << 8);
            int rr = lin >> 5, kk = lin & 31;
            Xs[kk][rr] = Xb[(long)rr * sb + k0 + kk];
            Ws[kk][rr] = W[(cb + rr) * (long)K + k0 + kk];
        }
        __syncthreads();
#pragma unroll
        for (int kk = 0; kk < 32; kk++) {
            float2 a01 = *(const float2*)&Xs[kk][tr * 4];
            float2 a23 = *(const float2*)&Xs[kk][tr * 4 + 2];
            float2 b01 = *(const float2*)&Ws[kk][tc * 4];
            float2 b23 = *(const float2*)&Ws[kk][tc * 4 + 2];
            float a[4] = {a01.x, a01.y, a23.x, a23.y};
            float b[4] = {b01.x, b01.y, b23.x, b23.y};
#pragma unroll
            for (int i = 0; i < 4; i++)
#pragma unroll
                for (int jj = 0; jj < 4; jj++) acc[i][jj] += a[i] * b[jj];
        }
        __syncthreads();
    }
#pragma unroll
    for (int i = 0; i < 4; i++) {
        long r = rb * 64 + tr * 4 + i;
#pragma unroll
        for (int jj = 0; jj < 4; jj++) {
            long c = cb + tc * 4 + jj;
            out[r * G3 + c] = acc[i][jj] + bias[c];
        }
    }
}

// ---------------------------------------------------------------------------
// Persistent encoder layer — tensor-core (split-bf16 mma.sync) version.
// FIX vs R5: weight ldmatrix addresses now include the chunk offset k0.
// ---------------------------------------------------------------------------
#define WKP 1032   // padded k-stride (bf16) for weight rows
#define HKP 136    // padded k-stride (bf16) for h rows

__global__ void __launch_bounds__(NTH, 1) enc_layer_kernel(
    const float* __restrict__ gi,
    const float* __restrict__ Wh,
    const float* __restrict__ bh,
    float* __restrict__ out, long out_t, long out_b)
{
    __nv_bfloat16* whi = (__nv_bfloat16*)sm;
    __nv_bfloat16* wlo = whi + 24 * WKP;
    __nv_bfloat16* hhi = wlo + 24 * WKP;
    __nv_bfloat16* hlo = hhi + 64 * HKP;
    float* red = (float*)(hlo + 64 * HKP);
    float* gis = red + 4 * 24 * 68;

    const int tid  = threadIdx.x;
    const int j0   = blockIdx.x << 3;
    const int warp = tid >> 5;
    const int lane = tid & 31;
    const int mw   = warp & 3;
    const int kw   = warp >> 2;
    const int eb   = tid >> 3;
    const int ej   = tid & 7;
    const int ecol = j0 + ej;

    unsigned target;
    { volatile unsigned* pp = &g_phase; target = *pp + 1u; }

    // ---- persistent weight load + split ----
    for (int i = 0; i < 48; i++) {
        int idx = tid + (i << 9);
        int c = idx >> 10, k = idx & 1023;
        int row = ((c >> 3) << 10) + j0 + (c & 7);
        float w = Wh[(long)row * HID + k];
        __nv_bfloat16 hi, lo;
        split_bf(w, hi, lo);
        whi[c * WKP + k] = hi;
        wlo[c * WKP + k] = lo;
    }
    const float bhr = bh[ecol];
    const float bhz = bh[HID + ecol];
    const float bhn = bh[2 * HID + ecol];

    const int rowA = mw * 16 + ((lane >> 3) & 1) * 8 + (lane & 7);
    const int kA   = ((lane >> 4) & 1) * 8;
    const int lm   = lane & 15;
    const int bOff = (lm & 7) * WKP + ((lm >> 3) & 1) * 8;
    const uint32_t hhiA = smem_u32(hhi);
    const uint32_t hloA = smem_u32(hlo);
    const uint32_t whiA = smem_u32(whi);
    const uint32_t wloA = smem_u32(wlo);
    __syncthreads();

    for (int t = 0; t < TSRC; t++) {
        float c0[4], c1[4], c2[4];
#pragma unroll
        for (int i = 0; i < 4; i++) { c0[i] = 0.f; c1[i] = 0.f; c2[i] = 0.f; }

        // stage gi tile: 64 b x 24 local cols
        {
            const float* gi_t = gi + (long)t * BB * G3;
#pragma unroll
            for (int i = 0; i < 3; i++) {
                int idx = (i << 9) + tid;
                int b = idx / 24;
                int rem = idx - b * 24;
                gis[b * 25 + rem] = gi_t[(long)b * G3 + ((rem >> 3) << 10) + j0 + (rem & 7)];
            }
        }

        const float* hprev = out + (long)(t - 1) * out_t;
        if (t > 0) {
            for (int k0 = 0; k0 < HID; k0 += 128) {
                __syncthreads();
#pragma unroll
                for (int i = 0; i < 4; i++) {
                    int idx = (i << 9) + tid;
                    int b = idx & 63, k4 = idx >> 6;
                    float4 v = *(const float4*)(hprev + (long)b * out_b + k0 + (k4 << 2));
                    __nv_bfloat16 h0, l0, h1, l1, h2, l2, h3, l3;
                    split_bf(v.x, h0, l0); split_bf(v.y, h1, l1);
                    split_bf(v.z, h2, l2); split_bf(v.w, h3, l3);
                    uint2 uh, ul;
                    uh.x = pack_bf2(__bfloat162float(h0), __bfloat162float(h1));
                    uh.y = pack_bf2(__bfloat162float(h2), __bfloat162float(h3));
                    ul.x = pack_bf2(__bfloat162float(l0), __bfloat162float(l1));
                    ul.y = pack_bf2(__bfloat162float(l2), __bfloat162float(l3));
                    *(uint2*)&hhi[b * HKP + (k4 << 2)] = uh;
                    *(uint2*)&hlo[b * HKP + (k4 << 2)] = ul;
                }
                __syncthreads();
#pragma unroll
                for (int s = 0; s < 2; s++) {
                    int kk = kw * 32 + s * 16;      // within-chunk k
                    int kg = k0 + kk;               // GLOBAL k for weight addresses
                    uint32_t ah[4], al[4];
                    ldsm4(ah[0], ah[1], ah[2], ah[3],
                          hhiA + (uint32_t)((rowA * HKP + kk + kA) * 2));
                    ldsm4(al[0], al[1], al[2], al[3],
                          hloA + (uint32_t)((rowA * HKP + kk + kA) * 2));
                    uint32_t bh2[2], bl2[2];
                    // n-tile 0
                    ldsm2(bh2[0], bh2[1], whiA + (uint32_t)((bOff + kg) * 2));
                    ldsm2(bl2[0], bl2[1], wloA + (uint32_t)((bOff + kg) * 2));
                    mma_bf16(c0, ah, bh2); mma_bf16(c0, ah, bl2); mma_bf16(c0, al, bh2);
                    // n-tile 1
                    ldsm2(bh2[0], bh2[1], whiA + (uint32_t)((8 * WKP + bOff + kg) * 2));
                    ldsm2(bl2[0], bl2[1], wloA + (uint32_t)((8 * WKP + bOff + kg) * 2));
                    mma_bf16(c1, ah, bh2); mma_bf16(c1, ah, bl2); mma_bf16(c1, al, bh2);
                    // n-tile 2
                    ldsm2(bh2[0], bh2[1], whiA + (uint32_t)((16 * WKP + bOff + kg) * 2));
                    ldsm2(bl2[0], bl2[1], wloA + (uint32_t)((16 * WKP + bOff + kg) * 2));
                    mma_bf16(c2, ah, bh2); mma_bf16(c2, ah, bl2); mma_bf16(c2, al, bh2);
                }
            }
        }
        __syncthreads();
        // dump fragments: red[kw][n][b]
        {
            float* rp = red + kw * 1632;
            int g = lane >> 2, t4 = lane & 3;
            int r0 = mw * 16 + g;
            int n0 = 2 * t4;
            rp[n0 * 68 + r0]            = c0[0];
            rp[(n0 + 1) * 68 + r0]      = c0[1];
            rp[n0 * 68 + r0 + 8]        = c0[2];
            rp[(n0 + 1) * 68 + r0 + 8]  = c0[3];
            rp[(8 + n0) * 68 + r0]           = c1[0];
            rp[(8 + n0 + 1) * 68 + r0]       = c1[1];
            rp[(8 + n0) * 68 + r0 + 8]       = c1[2];
            rp[(8 + n0 + 1) * 68 + r0 + 8]   = c1[3];
            rp[(16 + n0) * 68 + r0]          = c2[0];
            rp[(16 + n0 + 1) * 68 + r0]      = c2[1];
            rp[(16 + n0) * 68 + r0 + 8]      = c2[2];
            rp[(16 + n0 + 1) * 68 + r0 + 8]  = c2[3];
        }
        __syncthreads();

        // epilogue: one (b, col) per thread; reduce 4 k-splits
        float s0 = 0.f, s1 = 0.f, s2 = 0.f;
#pragma unroll
        for (int k = 0; k < 4; k++) {
            const float* rp = red + k * 1632 + eb;
            s0 += rp[(ej)      * 68];
            s1 += rp[(8 + ej)  * 68];
            s2 += rp[(16 + ej) * 68];
        }
        const float* gp = gis + eb * 25;
        float GR = gp[ej], GZ = gp[8 + ej], GN = gp[16 + ej];
        float hold = (t > 0) ? hprev[(long)eb * out_b + ecol] : 0.0f;
        float r = sigf(GR + s0 + bhr);
        float z = sigf(GZ + s1 + bhz);
        float n = tanhf(GN + r * (s2 + bhn));
        float hn = (1.0f - z) * n + z * hold;
        out[(long)t * out_t + (long)eb * out_b + ecol] = hn;

        if (t < TSRC - 1) grid_bar(target);
    }
}

// ---------------------------------------------------------------------------
// Persistent decoder (unchanged from R4)
// ---------------------------------------------------------------------------
__global__ void __launch_bounds__(NTH, 1) dec_kernel(
    const float* __restrict__ dWi0, const float* __restrict__ dWh0,
    const float* __restrict__ dbi0, const float* __restrict__ dbh0,
    const float* __restrict__ dWi1, const float* __restrict__ dWh1,
    const float* __restrict__ dbi1, const float* __restrict__ dbh1,
    const float* __restrict__ fcW,  const float* __restrict__ fcb,
    const float* __restrict__ enc0_hT,
    const float* __restrict__ enc1_hT,
    float* __restrict__ h0buf, float* __restrict__ h1buf, float* __restrict__ xbuf,
    float* __restrict__ out,
    float* __restrict__ dec_out)
{
    float* wsd  = sm;
    float* hs   = wsd + 128 * 28;
    float* redA = hs + 128 * 72;
    float* redB = redA + 8 * 24 * 68;

    const int tid = threadIdx.x;
    const int j0  = blockIdx.x << 3;
    const int ks  = tid >> 6;
    const int bg  = (tid >> 2) & 15;
    const int cg  = tid & 3;
    const int eb  = tid >> 3;
    const int ej  = tid & 7;
    const int ecol = j0 + ej;
    const int fb  = tid >> 3;
    const int fcc = (tid >> 2) & 1;
    const int fks = tid & 3;
    const int fcol = (blockIdx.x << 1) + fcc;

    unsigned target;
    { volatile unsigned* pp = &g_phase; target = *pp + 1u; }

    const float b0ir = dbi0[ecol], b0iz = dbi0[HID + ecol], b0in = dbi0[2 * HID + ecol];
    const float b0hr = dbh0[ecol], b0hz = dbh0[HID + ecol], b0hn = dbh0[2 * HID + ecol];
    const float b1ir = dbi1[ecol], b1iz = dbi1[HID + ecol], b1in = dbi1[2 * HID + ecol];
    const float b1hr = dbh1[ecol], b1hz = dbh1[HID + ecol], b1hn = dbh1[2 * HID + ecol];
    const float fcbv = fcb[fcol];

    ull acc[3][4];

    for (int t = 0; t < TTRG; t++) {
        const int w = t & 1;

        // ================= layer 0 =================
        zero_acc(acc);
        if (t > 0)
            stream_phase(xbuf, INP, dWi0, INP, wsd, hs, acc, tid, ks, bg, cg, j0);
        dump_red(redA, acc, ks, bg, cg);

        const float* h0p = t ? h0buf + (long)(1 - w) * BB * HID : enc0_hT;
        zero_acc(acc);
        stream_phase(h0p, HID, dWh0, HID, wsd, hs, acc, tid, ks, bg, cg, j0);
        dump_red(redB, acc, ks, bg, cg);
        __syncthreads();
        {
            float a0 = 0.f, a1 = 0.f, a2 = 0.f, c0 = 0.f, c1 = 0.f, c2 = 0.f;
#pragma unroll
            for (int k = 0; k < 8; k++) {
                const float* ra = redA + k * 1632 + eb;
                const float* rb = redB + k * 1632 + eb;
                a0 += ra[ej * 68];        c0 += rb[ej * 68];
                a1 += ra[(8 + ej) * 68];  c1 += rb[(8 + ej) * 68];
                a2 += ra[(16 + ej) * 68]; c2 += rb[(16 + ej) * 68];
            }
            float hold = h0p[(long)eb * HID + ecol];
            float r = sigf(a0 + b0ir + c0 + b0hr);
            float z = sigf(a1 + b0iz + c1 + b0hz);
            float n = tanhf(a2 + b0in + r * (c2 + b0hn));
            h0buf[(long)w * BB * HID + (long)eb * HID + ecol] = (1.f - z) * n + z * hold;
        }
        grid_bar(target);

        // ================= layer 1 =================
        const float* x1 = h0buf + (long)w * BB * HID;
        zero_acc(acc);
        stream_phase(x1, HID, dWi1, HID, wsd, hs, acc, tid, ks, bg, cg, j0);
        dump_red(redA, acc, ks, bg, cg);

        const float* h1p = t ? h1buf + (long)(1 - w) * BB * HID : enc1_hT;
        const long   h1s = t ? (long)HID : (long)TSRC * HID;
        zero_acc(acc);
        stream_phase(h1p, h1s, dWh1, HID, wsd, hs, acc, tid, ks, bg, cg, j0);
        dump_red(redB, acc, ks, bg, cg);
        __syncthreads();
        {
            float a0 = 0.f, a1 = 0.f, a2 = 0.f, c0 = 0.f, c1 = 0.f, c2 = 0.f;
#pragma unroll
            for (int k = 0; k < 8; k++) {
                const float* ra = redA + k * 1632 + eb;
                const float* rb = redB + k * 1632 + eb;
                a0 += ra[ej * 68];        c0 += rb[ej * 68];
                a1 += ra[(8 + ej) * 68];  c1 += rb[(8 + ej) * 68];
                a2 += ra[(16 + ej) * 68]; c2 += rb[(16 + ej) * 68];
            }
            float hold = h1p[(long)eb * h1s + ecol];
            float r = sigf(a0 + b1ir + c0 + b1hr);
            float z = sigf(a1 + b1iz + c1 + b1hz);
            float n = tanhf(a2 + b1in + r * (c2 + b1hn));
            float hn = (1.f - z) * n + z * hold;
            h1buf[(long)w * BB * HID + (long)eb * HID + ecol] = hn;
            dec_out[(long)eb * TTRG * HID + (long)t * HID + ecol] = hn;
        }
        grid_bar(target);

        // ================= fc =================
        {
            const float* h1c = h1buf + (long)w * BB * HID;
#pragma unroll
            for (int i = 0; i < 4; i++) {
                int idx = (i << 9) + tid;
                int k = idx >> 1, c = idx & 1;
                wsd[idx] = fcW[(long)((blockIdx.x << 1) + c) * HID + k];
            }
            float partial = 0.f;
            for (int k0 = 0; k0 < HID; k0 += 128) {
                __syncthreads();
                stage_x(hs, h1c, HID, k0, tid);
                __syncthreads();
#pragma unroll 8
                for (int i = 0; i < 32; i++) {
                    int kk = fks * 32 + i;
                    partial += hs[kk * 72 + fb] * wsd[(k0 + kk) * 2 + fcc];
                }
            }
            __syncthreads();
            redA[tid] = partial;
            __syncthreads();
            if (fks == 0) {
                float s = redA[tid] + redA[tid + 1] + redA[tid + 2] + redA[tid + 3] + fcbv;
                out [(long)fb * TTRG * INP + (long)t * INP + fcol] = s;
                xbuf[(long)fb * INP + fcol] = s;
            }
        }
        grid_bar(target);
    }
}

// ---------------------------------------------------------------------------
extern "C" void kernel_launch(void* const* d_in, const int* in_sizes, int n_in,
                              void* d_out, int out_size)
{
    const float* src  = (const float*)d_in[0];
    const float* eWi0 = (const float*)d_in[2];
    const float* eWh0 = (const float*)d_in[3];
    const float* ebi0 = (const float*)d_in[4];
    const float* ebh0 = (const float*)d_in[5];
    const float* eWi1 = (const float*)d_in[6];
    const float* eWh1 = (const float*)d_in[7];
    const float* ebi1 = (const float*)d_in[8];
    const float* ebh1 = (const float*)d_in[9];
    const float* dWi0 = (const float*)d_in[10];
    const float* dWh0 = (const float*)d_in[11];
    const float* dbi0 = (const float*)d_in[12];
    const float* dbh0 = (const float*)d_in[13];
    const float* dWi1 = (const float*)d_in[14];
    const float* dWh1 = (const float*)d_in[15];
    const float* dbi1 = (const float*)d_in[16];
    const float* dbh1 = (const float*)d_in[17];
    const float* fcW  = (const float*)d_in[18];
    const float* fcb  = (const float*)d_in[19];

    float* out     = (float*)d_out;                   // [64, 64, 256]
    float* enc_out = out + (long)BB * TTRG * INP;     // [64, 256, 1024]
    float* dec_out = enc_out + (long)BB * TSRC * HID; // [64, 64, 1024]

    float *gi, *ys0, *h0, *h1, *xbuf;
    cudaGetSymbolAddress((void**)&gi,   g_gi);
    cudaGetSymbolAddress((void**)&ys0,  g_ys0);
    cudaGetSymbolAddress((void**)&h0,   g_h0);
    cudaGetSymbolAddress((void**)&h1,   g_h1);
    cudaGetSymbolAddress((void**)&xbuf, g_x);

    const int ENC_SMEM = 24 * WKP * 2 * 2 + 64 * HKP * 2 * 2
                       + 4 * 24 * 68 * 4 + 64 * 25 * 4;   // 166400 B
    const int DEC_SMEM = (128 * 28 + 128 * 72 + 2 * 8 * 24 * 68) * 4;
    cudaFuncSetAttribute(enc_layer_kernel,
                         cudaFuncAttributeMaxDynamicSharedMemorySize, ENC_SMEM);
    cudaFuncSetAttribute(dec_kernel,
                         cudaFuncAttributeMaxDynamicSharedMemorySize, DEC_SMEM);

    dim3 gridGi(48, 256);

    // ---------- encoder layer 0 ----------
    gi_gemm<<<gridGi, 256>>>(src, 65536L, 256L, eWi0, ebi0, gi, 256);
    enc_layer_kernel<<<GRID, NTH, ENC_SMEM>>>(
        gi, eWh0, ebh0, ys0, (long)BB * HID, (long)HID);

    // ---------- encoder layer 1 ----------
    gi_gemm<<<gridGi, 256>>>(ys0, 1024L, 65536L, eWi1, ebi1, gi, 1024);
    enc_layer_kernel<<<GRID, NTH, ENC_SMEM>>>(
        gi, eWh1, ebh1, enc_out, (long)HID, (long)TSRC * HID);

    // ---------- decoder ----------
    dec_kernel<<<GRID, NTH, DEC_SMEM>>>(
        dWi0, dWh0, dbi0, dbh0,
        dWi1, dWh1, dbi1, dbh1,
        fcW, fcb,
        ys0 + (long)(TSRC - 1) * BB * HID,
        enc_out + (long)(TSRC - 1) * HID,
        h0, h1, xbuf,
        out, dec_out);
}

// round 7
// speedup vs baseline: 1.4511x; 1.1172x over previous
#include <cuda_runtime.h>
#include <cuda_bf16.h>
#include <math.h>
#include <stdint.h>

#define HID  1024
#define INP  256
#define BB   64
#define TSRC 256
#define TTRG 64
#define G3   3072
#define GRID 128
#define NTH  512

typedef unsigned long long ull;

// ---------------- scratch (static device globals; no runtime allocation) ----
__device__ float g_gi [(long)TSRC * BB * G3];   // precomputed input gates
__device__ float g_ys0[(long)TSRC * BB * HID];  // enc layer-0 outputs [t][b][h]
__device__ float g_h0 [2 * BB * HID];           // decoder layer-0 hidden (ping-pong)
__device__ float g_h1 [2 * BB * HID];           // decoder layer-1 hidden (ping-pong)
__device__ float g_x  [BB * INP];               // decoder AR input
__device__ unsigned g_cnt;                      // barrier arrive count (self-resetting)
__device__ unsigned g_phase;                    // barrier release phase (monotonic)

__device__ __forceinline__ float sigf(float x) { return 1.0f / (1.0f + expf(-x)); }

// packed f32x2 helpers (decoder scalar path)
#define FMA2(a, b, c) asm volatile("fma.rn.f32x2 %0, %1, %2, %0;" : "+l"(a) : "l"(b), "l"(c))
#define PACK2(d, x)   asm volatile("mov.b64 %0, {%1, %1};" : "=l"(d) : "f"(x))
#define UNPK2(lo, hi, v) asm volatile("mov.b64 {%0, %1}, %2;" : "=f"(lo), "=f"(hi) : "l"(v))

// ---- tensor-core primitives ----
__device__ __forceinline__ uint32_t smem_u32(const void* p) {
    uint32_t a;
    asm("{ .reg .u64 t; cvta.to.shared.u64 t, %1; cvt.u32.u64 %0, t; }" : "=r"(a) : "l"(p));
    return a;
}
__device__ __forceinline__ void ldsm4(uint32_t& r0, uint32_t& r1, uint32_t& r2, uint32_t& r3,
                                      uint32_t addr) {
    asm volatile("ldmatrix.sync.aligned.m8n8.x4.shared.b16 {%0,%1,%2,%3}, [%4];"
                 : "=r"(r0), "=r"(r1), "=r"(r2), "=r"(r3) : "r"(addr));
}
__device__ __forceinline__ void ldsm2(uint32_t& r0, uint32_t& r1, uint32_t addr) {
    asm volatile("ldmatrix.sync.aligned.m8n8.x2.shared.b16 {%0,%1}, [%2];"
                 : "=r"(r0), "=r"(r1) : "r"(addr));
}
__device__ __forceinline__ void mma_bf16(float* d, const uint32_t* a, const uint32_t* b) {
    asm volatile(
        "mma.sync.aligned.m16n8k16.row.col.f32.bf16.bf16.f32 "
        "{%0,%1,%2,%3}, {%4,%5,%6,%7}, {%8,%9}, {%0,%1,%2,%3};"
        : "+f"(d[0]), "+f"(d[1]), "+f"(d[2]), "+f"(d[3])
        : "r"(a[0]), "r"(a[1]), "r"(a[2]), "r"(a[3]), "r"(b[0]), "r"(b[1]));
}
__device__ __forceinline__ uint32_t pack_bf2(float x, float y) {
    __nv_bfloat162 v = __floats2bfloat162_rn(x, y);
    return *(uint32_t*)&v;
}
__device__ __forceinline__ void split_bf(float x, __nv_bfloat16& hi, __nv_bfloat16& lo) {
    hi = __float2bfloat16_rn(x);
    lo = __float2bfloat16_rn(x - __bfloat162float(hi));
}
// split a float4 into packed hi-pair / lo-pair uint2s
__device__ __forceinline__ void split4(float4 v, uint2& uh, uint2& ul) {
    __nv_bfloat16 h0, l0, h1, l1, h2, l2, h3, l3;
    split_bf(v.x, h0, l0); split_bf(v.y, h1, l1);
    split_bf(v.z, h2, l2); split_bf(v.w, h3, l3);
    uh.x = pack_bf2(__bfloat162float(h0), __bfloat162float(h1));
    uh.y = pack_bf2(__bfloat162float(h2), __bfloat162float(h3));
    ul.x = pack_bf2(__bfloat162float(l0), __bfloat162float(l1));
    ul.y = pack_bf2(__bfloat162float(l2), __bfloat162float(l3));
}

// ---------------------------------------------------------------------------
// Replay-safe grid barrier: monotonic phase + self-resetting counter.
// ---------------------------------------------------------------------------
__device__ __forceinline__ void grid_bar(unsigned& target)
{
    __threadfence();
    __syncthreads();
    if (threadIdx.x == 0) {
        unsigned a = atomicAdd(&g_cnt, 1u);
        if (a == (unsigned)GRID - 1u) {
            g_cnt = 0u;
            __threadfence();
            atomicAdd(&g_phase, 1u);
        } else {
            for (;;) {
                unsigned ph;
                asm volatile("ld.acquire.gpu.u32 %0, [%1];" : "=r"(ph) : "l"(&g_phase));
                if ((int)(ph - target) >= 0) break;
                __nanosleep(64);
            }
        }
        __threadfence();
    }
    __syncthreads();
    target++;
}

extern __shared__ float sm[];

// ---------------------------------------------------------------------------
// Decoder scalar helpers (unchanged)
// ---------------------------------------------------------------------------
__device__ __forceinline__ void stage_x(
    float* hs, const float* __restrict__ X, long xs, int k0, int tid)
{
#pragma unroll
    for (int i = 0; i < 4; i++) {
        int idx = (i << 9) + tid;
        int b = idx & 63, k4 = idx >> 6;
        float4 v = *(const float4*)(X + (long)b * xs + k0 + (k4 << 2));
        int base = (k4 << 2) * 72 + b;
        hs[base]       = v.x;
        hs[base + 72]  = v.y;
        hs[base + 144] = v.z;
        hs[base + 216] = v.w;
    }
}

__device__ __forceinline__ void gemm_chunk(
    const float* __restrict__ wsp, const float* __restrict__ hs,
    ull (&acc)[3][4], int ks, int bg, int cg)
{
#pragma unroll 4
    for (int i = 0; i < 16; i++) {
        int kk = (i << 3) + ks;
        const ull* wr = (const ull*)(wsp + kk * 28 + cg * 6);
        ull w0 = wr[0], w1 = wr[1], w2 = wr[2];
        float4 hv = *(const float4*)(hs + kk * 72 + (bg << 2));
        ull hb0, hb1, hb2, hb3;
        PACK2(hb0, hv.x); PACK2(hb1, hv.y); PACK2(hb2, hv.z); PACK2(hb3, hv.w);
        FMA2(acc[0][0], w0, hb0); FMA2(acc[0][1], w0, hb1);
        FMA2(acc[0][2], w0, hb2); FMA2(acc[0][3], w0, hb3);
        FMA2(acc[1][0], w1, hb0); FMA2(acc[1][1], w1, hb1);
        FMA2(acc[1][2], w1, hb2); FMA2(acc[1][3], w1, hb3);
        FMA2(acc[2][0], w2, hb0); FMA2(acc[2][1], w2, hb1);
        FMA2(acc[2][2], w2, hb2); FMA2(acc[2][3], w2, hb3);
    }
}

__device__ __forceinline__ void zero_acc(ull (&acc)[3][4])
{
#pragma unroll
    for (int c = 0; c < 3; c++)
#pragma unroll
        for (int b = 0; b < 4; b++) acc[c][b] = 0ull;
}

__device__ __forceinline__ void dump_red(
    float* red, ull (&acc)[3][4], int ks, int bg, int cg)
{
    float* rp = red + ks * 1632 + (cg * 6) * 68 + (bg << 2);
#pragma unroll
    for (int cp = 0; cp < 3; cp++) {
        float l0, h0, l1, h1, l2, h2, l3, h3;
        UNPK2(l0, h0, acc[cp][0]); UNPK2(l1, h1, acc[cp][1]);
        UNPK2(l2, h2, acc[cp][2]); UNPK2(l3, h3, acc[cp][3]);
        *(float4*)(rp + (2 * cp) * 68)     = make_float4(l0, l1, l2, l3);
        *(float4*)(rp + (2 * cp + 1) * 68) = make_float4(h0, h1, h2, h3);
    }
}

__device__ __forceinline__ void stream_phase(
    const float* __restrict__ X, long xs,
    const float* __restrict__ W, int K,
    float* wsd, float* hs, ull (&acc)[3][4],
    int tid, int ks, int bg, int cg, int j0)
{
    for (int k0 = 0; k0 < K; k0 += 128) {
        __syncthreads();
        stage_x(hs, X, xs, k0, tid);
#pragma unroll
        for (int i = 0; i < 6; i++) {
            int idx = (i << 9) + tid;
            int c = idx >> 7;
            int k = idx & 127;
            int row = ((c >> 3) << 10) + j0 + (c & 7);
            wsd[k * 28 + c] = W[(long)row * (long)K + k0 + k];
        }
        __syncthreads();
        gemm_chunk(wsd, hs, acc, ks, bg, cg);
    }
}

// ---------------------------------------------------------------------------
// Tensor-core batched input-gate GEMM (split-bf16, compensated):
// out[r][n] = X_row(r).W[n] + bias[n],  r = t*64+b, row off = b*sb + t*st.
// Block tile: 128 rows x 64 cols; K-chunk 32; 256 threads (8 warps).
// Warp w -> m16 tile rows [w*16, w*16+16), 8 n8-tiles (64 cols).
// grid = (N/64, M/128) = (48, 128).
// ---------------------------------------------------------------------------
#define AKP 40   // bf16 row stride for staged tiles (32 + 8 pad)

__global__ void __launch_bounds__(256) tc_gemm(
    const float* __restrict__ X, long sb, long st,
    const float* __restrict__ W, const float* __restrict__ bias,
    float* __restrict__ out, int K)
{
    __shared__ __nv_bfloat16 Ahi[128 * AKP];
    __shared__ __nv_bfloat16 Alo[128 * AKP];
    __shared__ __nv_bfloat16 Bhi[64 * AKP];
    __shared__ __nv_bfloat16 Blo[64 * AKP];

    const int tid  = threadIdx.x;
    const int warp = tid >> 5;
    const int lane = tid & 31;
    const long cb  = (long)blockIdx.x * 64;
    const long rb  = (long)blockIdx.y * 128;

    // ldmatrix lane addressing
    const int rowA = warp * 16 + ((lane >> 3) & 1) * 8 + (lane & 7);
    const int kA   = ((lane >> 4) & 1) * 8;
    const int lm   = lane & 15;
    const int bRow = lm & 7;
    const int bK   = ((lm >> 3) & 1) * 8;
    const uint32_t AhiA = smem_u32(Ahi);
    const uint32_t AloA = smem_u32(Alo);
    const uint32_t BhiA = smem_u32(Bhi);
    const uint32_t BloA = smem_u32(Blo);

    float acc[8][4];
#pragma unroll
    for (int n = 0; n < 8; n++)
#pragma unroll
        for (int i = 0; i < 4; i++) acc[n][i] = 0.0f;

    for (int k0 = 0; k0 < K; k0 += 32) {
        __syncthreads();
        // stage A: 128 rows x 32 k  (4 float4 per thread)
#pragma unroll
        for (int i = 0; i < 4; i++) {
            int idx = (i << 8) + tid;
            int row = idx >> 3, q = idx & 7;
            long r = rb + row;
            long off = (r & 63) * sb + (r >> 6) * st + k0 + (q << 2);
            float4 v = *(const float4*)(X + off);
            uint2 uh, ul;
            split4(v, uh, ul);
            *(uint2*)&Ahi[row * AKP + (q << 2)] = uh;
            *(uint2*)&Alo[row * AKP + (q << 2)] = ul;
        }
        // stage B: 64 rows (gate cols) x 32 k  (2 float4 per thread)
#pragma unroll
        for (int i = 0; i < 2; i++) {
            int idx = (i << 8) + tid;
            int row = idx >> 3, q = idx & 7;
            float4 v = *(const float4*)(W + (cb + row) * (long)K + k0 + (q << 2));
            uint2 uh, ul;
            split4(v, uh, ul);
            *(uint2*)&Bhi[row * AKP + (q << 2)] = uh;
            *(uint2*)&Blo[row * AKP + (q << 2)] = ul;
        }
        __syncthreads();

#pragma unroll
        for (int s = 0; s < 2; s++) {
            int kk = s * 16;
            uint32_t ah[4], al[4];
            ldsm4(ah[0], ah[1], ah[2], ah[3],
                  AhiA + (uint32_t)((rowA * AKP + kk + kA) * 2));
            ldsm4(al[0], al[1], al[2], al[3],
                  AloA + (uint32_t)((rowA * AKP + kk + kA) * 2));
#pragma unroll
            for (int nt = 0; nt < 8; nt++) {
                uint32_t bh2[2], bl2[2];
                uint32_t boff = (uint32_t)(((nt * 8 + bRow) * AKP + kk + bK) * 2);
                ldsm2(bh2[0], bh2[1], BhiA + boff);
                ldsm2(bl2[0], bl2[1], BloA + boff);
                mma_bf16(acc[nt], ah, bh2);
                mma_bf16(acc[nt], ah, bl2);
                mma_bf16(acc[nt], al, bh2);
            }
        }
    }

    // epilogue: add bias, write float2 pairs
    const int g  = lane >> 2;
    const int t4 = lane & 3;
#pragma unroll
    for (int nt = 0; nt < 8; nt++) {
        long c = cb + nt * 8 + t4 * 2;
        float2 bv = *(const float2*)(bias + c);
        long r0 = rb + warp * 16 + g;
        *(float2*)(out + r0 * G3 + c) = make_float2(acc[nt][0] + bv.x, acc[nt][1] + bv.y);
        *(float2*)(out + (r0 + 8) * G3 + c) = make_float2(acc[nt][2] + bv.x, acc[nt][3] + bv.y);
    }
}

// ---------------------------------------------------------------------------
// Persistent encoder layer — tensor-core split-bf16 (unchanged from R6)
// ---------------------------------------------------------------------------
#define WKP 1032
#define HKP 136

__global__ void __launch_bounds__(NTH, 1) enc_layer_kernel(
    const float* __restrict__ gi,
    const float* __restrict__ Wh,
    const float* __restrict__ bh,
    float* __restrict__ out, long out_t, long out_b)
{
    __nv_bfloat16* whi = (__nv_bfloat16*)sm;
    __nv_bfloat16* wlo = whi + 24 * WKP;
    __nv_bfloat16* hhi = wlo + 24 * WKP;
    __nv_bfloat16* hlo = hhi + 64 * HKP;
    float* red = (float*)(hlo + 64 * HKP);
    float* gis = red + 4 * 24 * 68;

    const int tid  = threadIdx.x;
    const int j0   = blockIdx.x << 3;
    const int warp = tid >> 5;
    const int lane = tid & 31;
    const int mw   = warp & 3;
    const int kw   = warp >> 2;
    const int eb   = tid >> 3;
    const int ej   = tid & 7;
    const int ecol = j0 + ej;

    unsigned target;
    { volatile unsigned* pp = &g_phase; target = *pp + 1u; }

    for (int i = 0; i < 48; i++) {
        int idx = tid + (i << 9);
        int c = idx >> 10, k = idx & 1023;
        int row = ((c >> 3) << 10) + j0 + (c & 7);
        float w = Wh[(long)row * HID + k];
        __nv_bfloat16 hi, lo;
        split_bf(w, hi, lo);
        whi[c * WKP + k] = hi;
        wlo[c * WKP + k] = lo;
    }
    const float bhr = bh[ecol];
    const float bhz = bh[HID + ecol];
    const float bhn = bh[2 * HID + ecol];

    const int rowA = mw * 16 + ((lane >> 3) & 1) * 8 + (lane & 7);
    const int kA   = ((lane >> 4) & 1) * 8;
    const int lm   = lane & 15;
    const int bOff = (lm & 7) * WKP + ((lm >> 3) & 1) * 8;
    const uint32_t hhiA = smem_u32(hhi);
    const uint32_t hloA = smem_u32(hlo);
    const uint32_t whiA = smem_u32(whi);
    const uint32_t wloA = smem_u32(wlo);
    __syncthreads();

    for (int t = 0; t < TSRC; t++) {
        float c0[4], c1[4], c2[4];
#pragma unroll
        for (int i = 0; i < 4; i++) { c0[i] = 0.f; c1[i] = 0.f; c2[i] = 0.f; }

        {
            const float* gi_t = gi + (long)t * BB * G3;
#pragma unroll
            for (int i = 0; i < 3; i++) {
                int idx = (i << 9) + tid;
                int b = idx / 24;
                int rem = idx - b * 24;
                gis[b * 25 + rem] = gi_t[(long)b * G3 + ((rem >> 3) << 10) + j0 + (rem & 7)];
            }
        }

        const float* hprev = out + (long)(t - 1) * out_t;
        if (t > 0) {
            for (int k0 = 0; k0 < HID; k0 += 128) {
                __syncthreads();
#pragma unroll
                for (int i = 0; i < 4; i++) {
                    int idx = (i << 9) + tid;
                    int b = idx & 63, k4 = idx >> 6;
                    float4 v = *(const float4*)(hprev + (long)b * out_b + k0 + (k4 << 2));
                    uint2 uh, ul;
                    split4(v, uh, ul);
                    *(uint2*)&hhi[b * HKP + (k4 << 2)] = uh;
                    *(uint2*)&hlo[b * HKP + (k4 << 2)] = ul;
                }
                __syncthreads();
#pragma unroll
                for (int s = 0; s < 2; s++) {
                    int kk = kw * 32 + s * 16;
                    int kg = k0 + kk;
                    uint32_t ah[4], al[4];
                    ldsm4(ah[0], ah[1], ah[2], ah[3],
                          hhiA + (uint32_t)((rowA * HKP + kk + kA) * 2));
                    ldsm4(al[0], al[1], al[2], al[3],
                          hloA + (uint32_t)((rowA * HKP + kk + kA) * 2));
                    uint32_t bh2[2], bl2[2];
                    ldsm2(bh2[0], bh2[1], whiA + (uint32_t)((bOff + kg) * 2));
                    ldsm2(bl2[0], bl2[1], wloA + (uint32_t)((bOff + kg) * 2));
                    mma_bf16(c0, ah, bh2); mma_bf16(c0, ah, bl2); mma_bf16(c0, al, bh2);
                    ldsm2(bh2[0], bh2[1], whiA + (uint32_t)((8 * WKP + bOff + kg) * 2));
                    ldsm2(bl2[0], bl2[1], wloA + (uint32_t)((8 * WKP + bOff + kg) * 2));
                    mma_bf16(c1, ah, bh2); mma_bf16(c1, ah, bl2); mma_bf16(c1, al, bh2);
                    ldsm2(bh2[0], bh2[1], whiA + (uint32_t)((16 * WKP + bOff + kg) * 2));
                    ldsm2(bl2[0], bl2[1], wloA + (uint32_t)((16 * WKP + bOff + kg) * 2));
                    mma_bf16(c2, ah, bh2); mma_bf16(c2, ah, bl2); mma_bf16(c2, al, bh2);
                }
            }
        }
        __syncthreads();
        {
            float* rp = red + kw * 1632;
            int g = lane >> 2, t4 = lane & 3;
            int r0 = mw * 16 + g;
            int n0 = 2 * t4;
            rp[n0 * 68 + r0]            = c0[0];
            rp[(n0 + 1) * 68 + r0]      = c0[1];
            rp[n0 * 68 + r0 + 8]        = c0[2];
            rp[(n0 + 1) * 68 + r0 + 8]  = c0[3];
            rp[(8 + n0) * 68 + r0]           = c1[0];
            rp[(8 + n0 + 1) * 68 + r0]       = c1[1];
            rp[(8 + n0) * 68 + r0 + 8]       = c1[2];
            rp[(8 + n0 + 1) * 68 + r0 + 8]   = c1[3];
            rp[(16 + n0) * 68 + r0]          = c2[0];
            rp[(16 + n0 + 1) * 68 + r0]      = c2[1];
            rp[(16 + n0) * 68 + r0 + 8]      = c2[2];
            rp[(16 + n0 + 1) * 68 + r0 + 8]  = c2[3];
        }
        __syncthreads();

        float s0 = 0.f, s1 = 0.f, s2 = 0.f;
#pragma unroll
        for (int k = 0; k < 4; k++) {
            const float* rp = red + k * 1632 + eb;
            s0 += rp[(ej)      * 68];
            s1 += rp[(8 + ej)  * 68];
            s2 += rp[(16 + ej) * 68];
        }
        const float* gp = gis + eb * 25;
        float GR = gp[ej], GZ = gp[8 + ej], GN = gp[16 + ej];
        float hold = (t > 0) ? hprev[(long)eb * out_b + ecol] : 0.0f;
        float r = sigf(GR + s0 + bhr);
        float z = sigf(GZ + s1 + bhz);
        float n = tanhf(GN + r * (s2 + bhn));
        float hn = (1.0f - z) * n + z * hold;
        out[(long)t * out_t + (long)eb * out_b + ecol] = hn;

        if (t < TSRC - 1) grid_bar(target);
    }
}

// ---------------------------------------------------------------------------
// Persistent decoder (unchanged)
// ---------------------------------------------------------------------------
__global__ void __launch_bounds__(NTH, 1) dec_kernel(
    const float* __restrict__ dWi0, const float* __restrict__ dWh0,
    const float* __restrict__ dbi0, const float* __restrict__ dbh0,
    const float* __restrict__ dWi1, const float* __restrict__ dWh1,
    const float* __restrict__ dbi1, const float* __restrict__ dbh1,
    const float* __restrict__ fcW,  const float* __restrict__ fcb,
    const float* __restrict__ enc0_hT,
    const float* __restrict__ enc1_hT,
    float* __restrict__ h0buf, float* __restrict__ h1buf, float* __restrict__ xbuf,
    float* __restrict__ out,
    float* __restrict__ dec_out)
{
    float* wsd  = sm;
    float* hs   = wsd + 128 * 28;
    float* redA = hs + 128 * 72;
    float* redB = redA + 8 * 24 * 68;

    const int tid = threadIdx.x;
    const int j0  = blockIdx.x << 3;
    const int ks  = tid >> 6;
    const int bg  = (tid >> 2) & 15;
    const int cg  = tid & 3;
    const int eb  = tid >> 3;
    const int ej  = tid & 7;
    const int ecol = j0 + ej;
    const int fb  = tid >> 3;
    const int fcc = (tid >> 2) & 1;
    const int fks = tid & 3;
    const int fcol = (blockIdx.x << 1) + fcc;

    unsigned target;
    { volatile unsigned* pp = &g_phase; target = *pp + 1u; }

    const float b0ir = dbi0[ecol], b0iz = dbi0[HID + ecol], b0in = dbi0[2 * HID + ecol];
    const float b0hr = dbh0[ecol], b0hz = dbh0[HID + ecol], b0hn = dbh0[2 * HID + ecol];
    const float b1ir = dbi1[ecol], b1iz = dbi1[HID + ecol], b1in = dbi1[2 * HID + ecol];
    const float b1hr = dbh1[ecol], b1hz = dbh1[HID + ecol], b1hn = dbh1[2 * HID + ecol];
    const float fcbv = fcb[fcol];

    ull acc[3][4];

    for (int t = 0; t < TTRG; t++) {
        const int w = t & 1;

        // ================= layer 0 =================
        zero_acc(acc);
        if (t > 0)
            stream_phase(xbuf, INP, dWi0, INP, wsd, hs, acc, tid, ks, bg, cg, j0);
        dump_red(redA, acc, ks, bg, cg);

        const float* h0p = t ? h0buf + (long)(1 - w) * BB * HID : enc0_hT;
        zero_acc(acc);
        stream_phase(h0p, HID, dWh0, HID, wsd, hs, acc, tid, ks, bg, cg, j0);
        dump_red(redB, acc, ks, bg, cg);
        __syncthreads();
        {
            float a0 = 0.f, a1 = 0.f, a2 = 0.f, c0 = 0.f, c1 = 0.f, c2 = 0.f;
#pragma unroll
            for (int k = 0; k < 8; k++) {
                const float* ra = redA + k * 1632 + eb;
                const float* rb = redB + k * 1632 + eb;
                a0 += ra[ej * 68];        c0 += rb[ej * 68];
                a1 += ra[(8 + ej) * 68];  c1 += rb[(8 + ej) * 68];
                a2 += ra[(16 + ej) * 68]; c2 += rb[(16 + ej) * 68];
            }
            float hold = h0p[(long)eb * HID + ecol];
            float r = sigf(a0 + b0ir + c0 + b0hr);
            float z = sigf(a1 + b0iz + c1 + b0hz);
            float n = tanhf(a2 + b0in + r * (c2 + b0hn));
            h0buf[(long)w * BB * HID + (long)eb * HID + ecol] = (1.f - z) * n + z * hold;
        }
        grid_bar(target);

        // ================= layer 1 =================
        const float* x1 = h0buf + (long)w * BB * HID;
        zero_acc(acc);
        stream_phase(x1, HID, dWi1, HID, wsd, hs, acc, tid, ks, bg, cg, j0);
        dump_red(redA, acc, ks, bg, cg);

        const float* h1p = t ? h1buf + (long)(1 - w) * BB * HID : enc1_hT;
        const long   h1s = t ? (long)HID : (long)TSRC * HID;
        zero_acc(acc);
        stream_phase(h1p, h1s, dWh1, HID, wsd, hs, acc, tid, ks, bg, cg, j0);
        dump_red(redB, acc, ks, bg, cg);
        __syncthreads();
        {
            float a0 = 0.f, a1 = 0.f, a2 = 0.f, c0 = 0.f, c1 = 0.f, c2 = 0.f;
#pragma unroll
            for (int k = 0; k < 8; k++) {
                const float* ra = redA + k * 1632 + eb;
                const float* rb = redB + k * 1632 + eb;
                a0 += ra[ej * 68];        c0 += rb[ej * 68];
                a1 += ra[(8 + ej) * 68];  c1 += rb[(8 + ej) * 68];
                a2 += ra[(16 + ej) * 68]; c2 += rb[(16 + ej) * 68];
            }
            float hold = h1p[(long)eb * h1s + ecol];
            float r = sigf(a0 + b1ir + c0 + b1hr);
            float z = sigf(a1 + b1iz + c1 + b1hz);
            float n = tanhf(a2 + b1in + r * (c2 + b1hn));
            float hn = (1.f - z) * n + z * hold;
            h1buf[(long)w * BB * HID + (long)eb * HID + ecol] = hn;
            dec_out[(long)eb * TTRG * HID + (long)t * HID + ecol] = hn;
        }
        grid_bar(target);

        // ================= fc =================
        {
            const float* h1c = h1buf + (long)w * BB * HID;
#pragma unroll
            for (int i = 0; i < 4; i++) {
                int idx = (i << 9) + tid;
                int k = idx >> 1, c = idx & 1;
                wsd[idx] = fcW[(long)((blockIdx.x << 1) + c) * HID + k];
            }
            float partial = 0.f;
            for (int k0 = 0; k0 < HID; k0 += 128) {
                __syncthreads();
                stage_x(hs, h1c, HID, k0, tid);
                __syncthreads();
#pragma unroll 8
                for (int i = 0; i < 32; i++) {
                    int kk = fks * 32 + i;
                    partial += hs[kk * 72 + fb] * wsd[(k0 + kk) * 2 + fcc];
                }
            }
            __syncthreads();
            redA[tid] = partial;
            __syncthreads();
            if (fks == 0) {
                float s = redA[tid] + redA[tid + 1] + redA[tid + 2] + redA[tid + 3] + fcbv;
                out [(long)fb * TTRG * INP + (long)t * INP + fcol] = s;
                xbuf[(long)fb * INP + fcol] = s;
            }
        }
        grid_bar(target);
    }
}

// ---------------------------------------------------------------------------
extern "C" void kernel_launch(void* const* d_in, const int* in_sizes, int n_in,
                              void* d_out, int out_size)
{
    const float* src  = (const float*)d_in[0];
    const float* eWi0 = (const float*)d_in[2];
    const float* eWh0 = (const float*)d_in[3];
    const float* ebi0 = (const float*)d_in[4];
    const float* ebh0 = (const float*)d_in[5];
    const float* eWi1 = (const float*)d_in[6];
    const float* eWh1 = (const float*)d_in[7];
    const float* ebi1 = (const float*)d_in[8];
    const float* ebh1 = (const float*)d_in[9];
    const float* dWi0 = (const float*)d_in[10];
    const float* dWh0 = (const float*)d_in[11];
    const float* dbi0 = (const float*)d_in[12];
    const float* dbh0 = (const float*)d_in[13];
    const float* dWi1 = (const float*)d_in[14];
    const float* dWh1 = (const float*)d_in[15];
    const float* dbi1 = (const float*)d_in[16];
    const float* dbh1 = (const float*)d_in[17];
    const float* fcW  = (const float*)d_in[18];
    const float* fcb  = (const float*)d_in[19];

    float* out     = (float*)d_out;                   // [64, 64, 256]
    float* enc_out = out + (long)BB * TTRG * INP;     // [64, 256, 1024]
    float* dec_out = enc_out + (long)BB * TSRC * HID; // [64, 64, 1024]

    float *gi, *ys0, *h0, *h1, *xbuf;
    cudaGetSymbolAddress((void**)&gi,   g_gi);
    cudaGetSymbolAddress((void**)&ys0,  g_ys0);
    cudaGetSymbolAddress((void**)&h0,   g_h0);
    cudaGetSymbolAddress((void**)&h1,   g_h1);
    cudaGetSymbolAddress((void**)&xbuf, g_x);

    const int ENC_SMEM = 24 * WKP * 2 * 2 + 64 * HKP * 2 * 2
                       + 4 * 24 * 68 * 4 + 64 * 25 * 4;   // 166400 B
    const int DEC_SMEM = (128 * 28 + 128 * 72 + 2 * 8 * 24 * 68) * 4;
    cudaFuncSetAttribute(enc_layer_kernel,
                         cudaFuncAttributeMaxDynamicSharedMemorySize, ENC_SMEM);
    cudaFuncSetAttribute(dec_kernel,
                         cudaFuncAttributeMaxDynamicSharedMemorySize, DEC_SMEM);

    dim3 gridTc(48, 128);

    // ---------- encoder layer 0 ----------
    tc_gemm<<<gridTc, 256>>>(src, 65536L, 256L, eWi0, ebi0, gi, 256);
    enc_layer_kernel<<<GRID, NTH, ENC_SMEM>>>(
        gi, eWh0, ebh0, ys0, (long)BB * HID, (long)HID);

    // ---------- encoder layer 1 ----------
    tc_gemm<<<gridTc, 256>>>(ys0, 1024L, 65536L, eWi1, ebi1, gi, 1024);
    enc_layer_kernel<<<GRID, NTH, ENC_SMEM>>>(
        gi, eWh1, ebh1, enc_out, (long)HID, (long)TSRC * HID);

    // ---------- decoder ----------
    dec_kernel<<<GRID, NTH, DEC_SMEM>>>(
        dWi0, dWh0, dbi0, dbh0,
        dWi1, dWh1, dbi1, dbh1,
        fcW, fcb,
        ys0 + (long)(TSRC - 1) * BB * HID,
        enc_out + (long)(TSRC - 1) * HID,
        h0, h1, xbuf,
        out, dec_out);
}

// round 8
// speedup vs baseline: 1.5765x; 1.0864x over previous
#include <cuda_runtime.h>
#include <cuda_bf16.h>
#include <math.h>
#include <stdint.h>

#define HID  1024
#define INP  256
#define BB   64
#define TSRC 256
#define TTRG 64
#define G3   3072
#define GRID 128
#define NTH  512

typedef unsigned long long ull;

// ---------------- scratch (static device globals; no runtime allocation) ----
__device__ float g_gi [(long)TSRC * BB * G3];   // precomputed input gates
__device__ float g_ys0[(long)TSRC * BB * HID];  // enc layer-0 outputs [t][b][h]
__device__ float g_h0 [2 * BB * HID];           // decoder layer-0 hidden (ping-pong)
__device__ float g_h1 [2 * BB * HID];           // decoder layer-1 hidden (ping-pong)
__device__ float g_x  [BB * INP];               // decoder AR input
__device__ unsigned g_cnt;                      // barrier arrive count (self-resetting)
__device__ unsigned g_phase;                    // barrier release phase (monotonic)

__device__ __forceinline__ float sigf(float x) { return 1.0f / (1.0f + expf(-x)); }

// packed f32x2 helpers (decoder scalar path)
#define FMA2(a, b, c) asm volatile("fma.rn.f32x2 %0, %1, %2, %0;" : "+l"(a) : "l"(b), "l"(c))
#define PACK2(d, x)   asm volatile("mov.b64 %0, {%1, %1};" : "=l"(d) : "f"(x))
#define UNPK2(lo, hi, v) asm volatile("mov.b64 {%0, %1}, %2;" : "=f"(lo), "=f"(hi) : "l"(v))

// ---- tensor-core primitives ----
__device__ __forceinline__ uint32_t smem_u32(const void* p) {
    uint32_t a;
    asm("{ .reg .u64 t; cvta.to.shared.u64 t, %1; cvt.u32.u64 %0, t; }" : "=r"(a) : "l"(p));
    return a;
}
__device__ __forceinline__ void ldsm4(uint32_t& r0, uint32_t& r1, uint32_t& r2, uint32_t& r3,
                                      uint32_t addr) {
    asm volatile("ldmatrix.sync.aligned.m8n8.x4.shared.b16 {%0,%1,%2,%3}, [%4];"
                 : "=r"(r0), "=r"(r1), "=r"(r2), "=r"(r3) : "r"(addr));
}
__device__ __forceinline__ void ldsm2(uint32_t& r0, uint32_t& r1, uint32_t addr) {
    asm volatile("ldmatrix.sync.aligned.m8n8.x2.shared.b16 {%0,%1}, [%2];"
                 : "=r"(r0), "=r"(r1) : "r"(addr));
}
__device__ __forceinline__ void mma_bf16(float* d, const uint32_t* a, const uint32_t* b) {
    asm volatile(
        "mma.sync.aligned.m16n8k16.row.col.f32.bf16.bf16.f32 "
        "{%0,%1,%2,%3}, {%4,%5,%6,%7}, {%8,%9}, {%0,%1,%2,%3};"
        : "+f"(d[0]), "+f"(d[1]), "+f"(d[2]), "+f"(d[3])
        : "r"(a[0]), "r"(a[1]), "r"(a[2]), "r"(a[3]), "r"(b[0]), "r"(b[1]));
}
__device__ __forceinline__ uint32_t pack_bf2(float x, float y) {
    __nv_bfloat162 v = __floats2bfloat162_rn(x, y);
    return *(uint32_t*)&v;
}
__device__ __forceinline__ void split_bf(float x, __nv_bfloat16& hi, __nv_bfloat16& lo) {
    hi = __float2bfloat16_rn(x);
    lo = __float2bfloat16_rn(x - __bfloat162float(hi));
}
// PRMT: take high 16 bits of a (low half of result) and of b (high half)
__device__ __forceinline__ uint32_t prmt_hi(uint32_t a, uint32_t b) {
    uint32_t r;
    asm("prmt.b32 %0, %1, %2, 0x7632;" : "=r"(r) : "r"(a), "r"(b));
    return r;
}
// fast truncation split: hi = trunc-bf16(x), lo = rn-bf16(x - hi)
__device__ __forceinline__ void split4_fast(float4 v, uint2& uh, uint2& ul) {
    uint32_t ax = __float_as_uint(v.x), ay = __float_as_uint(v.y);
    uint32_t az = __float_as_uint(v.z), aw = __float_as_uint(v.w);
    uh.x = prmt_hi(ax, ay);
    uh.y = prmt_hi(az, aw);
    float lx = v.x - __uint_as_float(ax & 0xFFFF0000u);
    float ly = v.y - __uint_as_float(ay & 0xFFFF0000u);
    float lz = v.z - __uint_as_float(az & 0xFFFF0000u);
    float lw = v.w - __uint_as_float(aw & 0xFFFF0000u);
    ul.x = pack_bf2(lx, ly);
    ul.y = pack_bf2(lz, lw);
}

// ---------------------------------------------------------------------------
// Replay-safe grid barrier: monotonic phase + self-resetting counter.
// ---------------------------------------------------------------------------
__device__ __forceinline__ void grid_bar(unsigned& target)
{
    __threadfence();
    __syncthreads();
    if (threadIdx.x == 0) {
        unsigned a = atomicAdd(&g_cnt, 1u);
        if (a == (unsigned)GRID - 1u) {
            g_cnt = 0u;
            __threadfence();
            atomicAdd(&g_phase, 1u);
        } else {
            for (;;) {
                unsigned ph;
                asm volatile("ld.acquire.gpu.u32 %0, [%1];" : "=r"(ph) : "l"(&g_phase));
                if ((int)(ph - target) >= 0) break;
                __nanosleep(64);
            }
        }
        __threadfence();
    }
    __syncthreads();
    target++;
}

extern __shared__ float sm[];

// ---------------------------------------------------------------------------
// Decoder scalar helpers
// ---------------------------------------------------------------------------
__device__ __forceinline__ void gemm_chunk(
    const float* __restrict__ wsp, const float* __restrict__ hs,
    ull (&acc)[3][4], int ks, int bg, int cg)
{
#pragma unroll 4
    for (int i = 0; i < 16; i++) {
        int kk = (i << 3) + ks;
        const ull* wr = (const ull*)(wsp + kk * 28 + cg * 6);
        ull w0 = wr[0], w1 = wr[1], w2 = wr[2];
        float4 hv = *(const float4*)(hs + kk * 72 + (bg << 2));
        ull hb0, hb1, hb2, hb3;
        PACK2(hb0, hv.x); PACK2(hb1, hv.y); PACK2(hb2, hv.z); PACK2(hb3, hv.w);
        FMA2(acc[0][0], w0, hb0); FMA2(acc[0][1], w0, hb1);
        FMA2(acc[0][2], w0, hb2); FMA2(acc[0][3], w0, hb3);
        FMA2(acc[1][0], w1, hb0); FMA2(acc[1][1], w1, hb1);
        FMA2(acc[1][2], w1, hb2); FMA2(acc[1][3], w1, hb3);
        FMA2(acc[2][0], w2, hb0); FMA2(acc[2][1], w2, hb1);
        FMA2(acc[2][2], w2, hb2); FMA2(acc[2][3], w2, hb3);
    }
}

__device__ __forceinline__ void zero_acc(ull (&acc)[3][4])
{
#pragma unroll
    for (int c = 0; c < 3; c++)
#pragma unroll
        for (int b = 0; b < 4; b++) acc[c][b] = 0ull;
}

__device__ __forceinline__ void dump_red(
    float* red, ull (&acc)[3][4], int ks, int bg, int cg)
{
    float* rp = red + ks * 1632 + (cg * 6) * 68 + (bg << 2);
#pragma unroll
    for (int cp = 0; cp < 3; cp++) {
        float l0, h0, l1, h1, l2, h2, l3, h3;
        UNPK2(l0, h0, acc[cp][0]); UNPK2(l1, h1, acc[cp][1]);
        UNPK2(l2, h2, acc[cp][2]); UNPK2(l3, h3, acc[cp][3]);
        *(float4*)(rp + (2 * cp) * 68)     = make_float4(l0, l1, l2, l3);
        *(float4*)(rp + (2 * cp + 1) * 68) = make_float4(h0, h1, h2, h3);
    }
}

// pipelined streamed-weight GEMM phase: prefetch next chunk (x + W) into regs
// while gemm_chunk computes the current one.
__device__ __forceinline__ void stream_phase(
    const float* __restrict__ X, long xs,
    const float* __restrict__ W, int K,
    float* wsd, float* hs, ull (&acc)[3][4],
    int tid, int ks, int bg, int cg, int j0)
{
    const int NC = K >> 7;
    float4 rx[4];
    float  rw[6];
#pragma unroll
    for (int i = 0; i < 4; i++) {
        int idx = (i << 9) + tid;
        int b = idx & 63, k4 = idx >> 6;
        rx[i] = *(const float4*)(X + (long)b * xs + (k4 << 2));
    }
#pragma unroll
    for (int i = 0; i < 6; i++) {
        int idx = (i << 9) + tid;
        int c = idx >> 7, k = idx & 127;
        int row = ((c >> 3) << 10) + j0 + (c & 7);
        rw[i] = W[(long)row * (long)K + k];
    }
    for (int ci = 0; ci < NC; ci++) {
        __syncthreads();
#pragma unroll
        for (int i = 0; i < 4; i++) {
            int idx = (i << 9) + tid;
            int b = idx & 63, k4 = idx >> 6;
            int base = (k4 << 2) * 72 + b;
            hs[base]       = rx[i].x;
            hs[base + 72]  = rx[i].y;
            hs[base + 144] = rx[i].z;
            hs[base + 216] = rx[i].w;
        }
#pragma unroll
        for (int i = 0; i < 6; i++) {
            int idx = (i << 9) + tid;
            int c = idx >> 7, k = idx & 127;
            wsd[k * 28 + c] = rw[i];
        }
        __syncthreads();
        if (ci + 1 < NC) {
            int k0 = (ci + 1) << 7;
#pragma unroll
            for (int i = 0; i < 4; i++) {
                int idx = (i << 9) + tid;
                int b = idx & 63, k4 = idx >> 6;
                rx[i] = *(const float4*)(X + (long)b * xs + k0 + (k4 << 2));
            }
#pragma unroll
            for (int i = 0; i < 6; i++) {
                int idx = (i << 9) + tid;
                int c = idx >> 7, k = idx & 127;
                int row = ((c >> 3) << 10) + j0 + (c & 7);
                rw[i] = W[(long)row * (long)K + k0 + k];
            }
        }
        gemm_chunk(wsd, hs, acc, ks, bg, cg);
    }
}

// ---------------------------------------------------------------------------
// Tensor-core batched input-gate GEMM (split-bf16, compensated)
// ---------------------------------------------------------------------------
#define AKP 40

__global__ void __launch_bounds__(256) tc_gemm(
    const float* __restrict__ X, long sb, long st,
    const float* __restrict__ W, const float* __restrict__ bias,
    float* __restrict__ out, int K)
{
    __shared__ __nv_bfloat16 Ahi[128 * AKP];
    __shared__ __nv_bfloat16 Alo[128 * AKP];
    __shared__ __nv_bfloat16 Bhi[64 * AKP];
    __shared__ __nv_bfloat16 Blo[64 * AKP];

    const int tid  = threadIdx.x;
    const int warp = tid >> 5;
    const int lane = tid & 31;
    const long cb  = (long)blockIdx.x * 64;
    const long rb  = (long)blockIdx.y * 128;

    const int rowA = warp * 16 + ((lane >> 3) & 1) * 8 + (lane & 7);
    const int kA   = ((lane >> 4) & 1) * 8;
    const int lm   = lane & 15;
    const int bRow = lm & 7;
    const int bK   = ((lm >> 3) & 1) * 8;
    const uint32_t AhiA = smem_u32(Ahi);
    const uint32_t AloA = smem_u32(Alo);
    const uint32_t BhiA = smem_u32(Bhi);
    const uint32_t BloA = smem_u32(Blo);

    float acc[8][4];
#pragma unroll
    for (int n = 0; n < 8; n++)
#pragma unroll
        for (int i = 0; i < 4; i++) acc[n][i] = 0.0f;

    for (int k0 = 0; k0 < K; k0 += 32) {
        __syncthreads();
#pragma unroll
        for (int i = 0; i < 4; i++) {
            int idx = (i << 8) + tid;
            int row = idx >> 3, q = idx & 7;
            long r = rb + row;
            long off = (r & 63) * sb + (r >> 6) * st + k0 + (q << 2);
            float4 v = *(const float4*)(X + off);
            uint2 uh, ul;
            split4_fast(v, uh, ul);
            *(uint2*)&Ahi[row * AKP + (q << 2)] = uh;
            *(uint2*)&Alo[row * AKP + (q << 2)] = ul;
        }
#pragma unroll
        for (int i = 0; i < 2; i++) {
            int idx = (i << 8) + tid;
            int row = idx >> 3, q = idx & 7;
            float4 v = *(const float4*)(W + (cb + row) * (long)K + k0 + (q << 2));
            uint2 uh, ul;
            split4_fast(v, uh, ul);
            *(uint2*)&Bhi[row * AKP + (q << 2)] = uh;
            *(uint2*)&Blo[row * AKP + (q << 2)] = ul;
        }
        __syncthreads();

#pragma unroll
        for (int s = 0; s < 2; s++) {
            int kk = s * 16;
            uint32_t ah[4], al[4];
            ldsm4(ah[0], ah[1], ah[2], ah[3],
                  AhiA + (uint32_t)((rowA * AKP + kk + kA) * 2));
            ldsm4(al[0], al[1], al[2], al[3],
                  AloA + (uint32_t)((rowA * AKP + kk + kA) * 2));
#pragma unroll
            for (int nt = 0; nt < 8; nt++) {
                uint32_t bh2[2], bl2[2];
                uint32_t boff = (uint32_t)(((nt * 8 + bRow) * AKP + kk + bK) * 2);
                ldsm2(bh2[0], bh2[1], BhiA + boff);
                ldsm2(bl2[0], bl2[1], BloA + boff);
                mma_bf16(acc[nt], ah, bh2);
                mma_bf16(acc[nt], ah, bl2);
                mma_bf16(acc[nt], al, bh2);
            }
        }
    }

    const int g  = lane >> 2;
    const int t4 = lane & 3;
#pragma unroll
    for (int nt = 0; nt < 8; nt++) {
        long c = cb + nt * 8 + t4 * 2;
        float2 bv = *(const float2*)(bias + c);
        long r0 = rb + warp * 16 + g;
        *(float2*)(out + r0 * G3 + c) = make_float2(acc[nt][0] + bv.x, acc[nt][1] + bv.y);
        *(float2*)(out + (r0 + 8) * G3 + c) = make_float2(acc[nt][2] + bv.x, acc[nt][3] + bv.y);
    }
}

// ---------------------------------------------------------------------------
// Persistent encoder layer — tensor-core split-bf16 with depth-2 reg prefetch
// ---------------------------------------------------------------------------
#define WKP 1032
#define HKP 136

__global__ void __launch_bounds__(NTH, 1) enc_layer_kernel(
    const float* __restrict__ gi,
    const float* __restrict__ Wh,
    const float* __restrict__ bh,
    float* __restrict__ out, long out_t, long out_b)
{
    __nv_bfloat16* whi = (__nv_bfloat16*)sm;
    __nv_bfloat16* wlo = whi + 24 * WKP;
    __nv_bfloat16* hhi = wlo + 24 * WKP;
    __nv_bfloat16* hlo = hhi + 64 * HKP;
    float* red = (float*)(hlo + 64 * HKP);
    float* gis = red + 4 * 24 * 68;

    const int tid  = threadIdx.x;
    const int j0   = blockIdx.x << 3;
    const int warp = tid >> 5;
    const int lane = tid & 31;
    const int mw   = warp & 3;
    const int kw   = warp >> 2;
    const int eb   = tid >> 3;
    const int ej   = tid & 7;
    const int ecol = j0 + ej;

    unsigned target;
    { volatile unsigned* pp = &g_phase; target = *pp + 1u; }

    for (int i = 0; i < 48; i++) {
        int idx = tid + (i << 9);
        int c = idx >> 10, k = idx & 1023;
        int row = ((c >> 3) << 10) + j0 + (c & 7);
        float w = Wh[(long)row * HID + k];
        __nv_bfloat16 hi, lo;
        split_bf(w, hi, lo);
        whi[c * WKP + k] = hi;
        wlo[c * WKP + k] = lo;
    }
    const float bhr = bh[ecol];
    const float bhz = bh[HID + ecol];
    const float bhn = bh[2 * HID + ecol];

    const int rowA = mw * 16 + ((lane >> 3) & 1) * 8 + (lane & 7);
    const int kA   = ((lane >> 4) & 1) * 8;
    const int lm   = lane & 15;
    const int bOff = (lm & 7) * WKP + ((lm >> 3) & 1) * 8;
    const uint32_t hhiA = smem_u32(hhi);
    const uint32_t hloA = smem_u32(hlo);
    const uint32_t whiA = smem_u32(whi);
    const uint32_t wloA = smem_u32(wlo);

    // per-thread staging coordinates (reused every chunk)
    const int sb_ = tid & 63;            // batch row this thread stages
    const int sk4 = tid >> 6;            // base quad (0..7); +8 per i
    __syncthreads();

    for (int t = 0; t < TSRC; t++) {
        float c0[4], c1[4], c2[4];
#pragma unroll
        for (int i = 0; i < 4; i++) { c0[i] = 0.f; c1[i] = 0.f; c2[i] = 0.f; }

        const float* hprev = out + (long)(t - 1) * out_t;
        float hold = 0.0f;
        float4 rA[2][4];
        if (t > 0) {
            hold = hprev[(long)eb * out_b + ecol];
            // preload chunks 0,1 into regs
#pragma unroll
            for (int p = 0; p < 2; p++)
#pragma unroll
                for (int i = 0; i < 4; i++) {
                    int k4 = sk4 + (i << 3);
                    rA[p][i] = *(const float4*)(hprev + (long)sb_ * out_b + (p << 7) + (k4 << 2));
                }
        }

        // stage gi tile (overlaps with chunk prefetch)
        {
            const float* gi_t = gi + (long)t * BB * G3;
#pragma unroll
            for (int i = 0; i < 3; i++) {
                int idx = (i << 9) + tid;
                int b = idx / 24;
                int rem = idx - b * 24;
                gis[b * 25 + rem] = gi_t[(long)b * G3 + ((rem >> 3) << 10) + j0 + (rem & 7)];
            }
        }

        if (t > 0) {
            for (int c = 0; c < 8; c++) {
                __syncthreads();
                // convert + store chunk c from regs
#pragma unroll
                for (int i = 0; i < 4; i++) {
                    int k4 = sk4 + (i << 3);
                    uint2 uh, ul;
                    split4_fast(rA[c & 1][i], uh, ul);
                    *(uint2*)&hhi[sb_ * HKP + (k4 << 2)] = uh;
                    *(uint2*)&hlo[sb_ * HKP + (k4 << 2)] = ul;
                }
                __syncthreads();
                // prefetch chunk c+2
                if (c < 6) {
                    int k0n = (c + 2) << 7;
#pragma unroll
                    for (int i = 0; i < 4; i++) {
                        int k4 = sk4 + (i << 3);
                        rA[c & 1][i] =
                            *(const float4*)(hprev + (long)sb_ * out_b + k0n + (k4 << 2));
                    }
                }
                // MMA on chunk c
                int k0 = c << 7;
#pragma unroll
                for (int s = 0; s < 2; s++) {
                    int kk = kw * 32 + s * 16;
                    int kg = k0 + kk;
                    uint32_t ah[4], al[4];
                    ldsm4(ah[0], ah[1], ah[2], ah[3],
                          hhiA + (uint32_t)((rowA * HKP + kk + kA) * 2));
                    ldsm4(al[0], al[1], al[2], al[3],
                          hloA + (uint32_t)((rowA * HKP + kk + kA) * 2));
                    uint32_t bh2[2], bl2[2];
                    ldsm2(bh2[0], bh2[1], whiA + (uint32_t)((bOff + kg) * 2));
                    ldsm2(bl2[0], bl2[1], wloA + (uint32_t)((bOff + kg) * 2));
                    mma_bf16(c0, ah, bh2); mma_bf16(c0, ah, bl2); mma_bf16(c0, al, bh2);
                    ldsm2(bh2[0], bh2[1], whiA + (uint32_t)((8 * WKP + bOff + kg) * 2));
                    ldsm2(bl2[0], bl2[1], wloA + (uint32_t)((8 * WKP + bOff + kg) * 2));
                    mma_bf16(c1, ah, bh2); mma_bf16(c1, ah, bl2); mma_bf16(c1, al, bh2);
                    ldsm2(bh2[0], bh2[1], whiA + (uint32_t)((16 * WKP + bOff + kg) * 2));
                    ldsm2(bl2[0], bl2[1], wloA + (uint32_t)((16 * WKP + bOff + kg) * 2));
                    mma_bf16(c2, ah, bh2); mma_bf16(c2, ah, bl2); mma_bf16(c2, al, bh2);
                }
            }
        }
        __syncthreads();
        {
            float* rp = red + kw * 1632;
            int g = lane >> 2, t4 = lane & 3;
            int r0 = mw * 16 + g;
            int n0 = 2 * t4;
            rp[n0 * 68 + r0]            = c0[0];
            rp[(n0 + 1) * 68 + r0]      = c0[1];
            rp[n0 * 68 + r0 + 8]        = c0[2];
            rp[(n0 + 1) * 68 + r0 + 8]  = c0[3];
            rp[(8 + n0) * 68 + r0]           = c1[0];
            rp[(8 + n0 + 1) * 68 + r0]       = c1[1];
            rp[(8 + n0) * 68 + r0 + 8]       = c1[2];
            rp[(8 + n0 + 1) * 68 + r0 + 8]   = c1[3];
            rp[(16 + n0) * 68 + r0]          = c2[0];
            rp[(16 + n0 + 1) * 68 + r0]      = c2[1];
            rp[(16 + n0) * 68 + r0 + 8]      = c2[2];
            rp[(16 + n0 + 1) * 68 + r0 + 8]  = c2[3];
        }
        __syncthreads();

        float s0 = 0.f, s1 = 0.f, s2 = 0.f;
#pragma unroll
        for (int k = 0; k < 4; k++) {
            const float* rp = red + k * 1632 + eb;
            s0 += rp[(ej)      * 68];
            s1 += rp[(8 + ej)  * 68];
            s2 += rp[(16 + ej) * 68];
        }
        const float* gp = gis + eb * 25;
        float GR = gp[ej], GZ = gp[8 + ej], GN = gp[16 + ej];
        float r = sigf(GR + s0 + bhr);
        float z = sigf(GZ + s1 + bhz);
        float n = tanhf(GN + r * (s2 + bhn));
        float hn = (1.0f - z) * n + z * hold;
        out[(long)t * out_t + (long)eb * out_b + ecol] = hn;

        if (t < TSRC - 1) grid_bar(target);
    }
}

// ---------------------------------------------------------------------------
// Persistent decoder: pipelined stream phases
// ---------------------------------------------------------------------------
__global__ void __launch_bounds__(NTH, 1) dec_kernel(
    const float* __restrict__ dWi0, const float* __restrict__ dWh0,
    const float* __restrict__ dbi0, const float* __restrict__ dbh0,
    const float* __restrict__ dWi1, const float* __restrict__ dWh1,
    const float* __restrict__ dbi1, const float* __restrict__ dbh1,
    const float* __restrict__ fcW,  const float* __restrict__ fcb,
    const float* __restrict__ enc0_hT,
    const float* __restrict__ enc1_hT,
    float* __restrict__ h0buf, float* __restrict__ h1buf, float* __restrict__ xbuf,
    float* __restrict__ out,
    float* __restrict__ dec_out)
{
    float* wsd  = sm;
    float* hs   = wsd + 128 * 28;
    float* redA = hs + 128 * 72;
    float* redB = redA + 8 * 24 * 68;

    const int tid = threadIdx.x;
    const int j0  = blockIdx.x << 3;
    const int ks  = tid >> 6;
    const int bg  = (tid >> 2) & 15;
    const int cg  = tid & 3;
    const int eb  = tid >> 3;
    const int ej  = tid & 7;
    const int ecol = j0 + ej;
    const int fb  = tid >> 3;
    const int fcc = (tid >> 2) & 1;
    const int fks = tid & 3;
    const int fcol = (blockIdx.x << 1) + fcc;

    unsigned target;
    { volatile unsigned* pp = &g_phase; target = *pp + 1u; }

    const float b0ir = dbi0[ecol], b0iz = dbi0[HID + ecol], b0in = dbi0[2 * HID + ecol];
    const float b0hr = dbh0[ecol], b0hz = dbh0[HID + ecol], b0hn = dbh0[2 * HID + ecol];
    const float b1ir = dbi1[ecol], b1iz = dbi1[HID + ecol], b1in = dbi1[2 * HID + ecol];
    const float b1hr = dbh1[ecol], b1hz = dbh1[HID + ecol], b1hn = dbh1[2 * HID + ecol];
    const float fcbv = fcb[fcol];

    ull acc[3][4];

    for (int t = 0; t < TTRG; t++) {
        const int w = t & 1;

        // ================= layer 0 =================
        zero_acc(acc);
        if (t > 0)
            stream_phase(xbuf, INP, dWi0, INP, wsd, hs, acc, tid, ks, bg, cg, j0);
        dump_red(redA, acc, ks, bg, cg);

        const float* h0p = t ? h0buf + (long)(1 - w) * BB * HID : enc0_hT;
        zero_acc(acc);
        stream_phase(h0p, HID, dWh0, HID, wsd, hs, acc, tid, ks, bg, cg, j0);
        dump_red(redB, acc, ks, bg, cg);
        __syncthreads();
        {
            float a0 = 0.f, a1 = 0.f, a2 = 0.f, c0 = 0.f, c1 = 0.f, c2 = 0.f;
#pragma unroll
            for (int k = 0; k < 8; k++) {
                const float* ra = redA + k * 1632 + eb;
                const float* rb = redB + k * 1632 + eb;
                a0 += ra[ej * 68];        c0 += rb[ej * 68];
                a1 += ra[(8 + ej) * 68];  c1 += rb[(8 + ej) * 68];
                a2 += ra[(16 + ej) * 68]; c2 += rb[(16 + ej) * 68];
            }
            float hold = h0p[(long)eb * HID + ecol];
            float r = sigf(a0 + b0ir + c0 + b0hr);
            float z = sigf(a1 + b0iz + c1 + b0hz);
            float n = tanhf(a2 + b0in + r * (c2 + b0hn));
            h0buf[(long)w * BB * HID + (long)eb * HID + ecol] = (1.f - z) * n + z * hold;
        }
        grid_bar(target);

        // ================= layer 1 =================
        const float* x1 = h0buf + (long)w * BB * HID;
        zero_acc(acc);
        stream_phase(x1, HID, dWi1, HID, wsd, hs, acc, tid, ks, bg, cg, j0);
        dump_red(redA, acc, ks, bg, cg);

        const float* h1p = t ? h1buf + (long)(1 - w) * BB * HID : enc1_hT;
        const long   h1s = t ? (long)HID : (long)TSRC * HID;
        zero_acc(acc);
        stream_phase(h1p, h1s, dWh1, HID, wsd, hs, acc, tid, ks, bg, cg, j0);
        dump_red(redB, acc, ks, bg, cg);
        __syncthreads();
        {
            float a0 = 0.f, a1 = 0.f, a2 = 0.f, c0 = 0.f, c1 = 0.f, c2 = 0.f;
#pragma unroll
            for (int k = 0; k < 8; k++) {
                const float* ra = redA + k * 1632 + eb;
                const float* rb = redB + k * 1632 + eb;
                a0 += ra[ej * 68];        c0 += rb[ej * 68];
                a1 += ra[(8 + ej) * 68];  c1 += rb[(8 + ej) * 68];
                a2 += ra[(16 + ej) * 68]; c2 += rb[(16 + ej) * 68];
            }
            float hold = h1p[(long)eb * h1s + ecol];
            float r = sigf(a0 + b1ir + c0 + b1hr);
            float z = sigf(a1 + b1iz + c1 + b1hz);
            float n = tanhf(a2 + b1in + r * (c2 + b1hn));
            float hn = (1.f - z) * n + z * hold;
            h1buf[(long)w * BB * HID + (long)eb * HID + ecol] = hn;
            dec_out[(long)eb * TTRG * HID + (long)t * HID + ecol] = hn;
        }
        grid_bar(target);

        // ================= fc (pipelined) =================
        {
            const float* h1c = h1buf + (long)w * BB * HID;
#pragma unroll
            for (int i = 0; i < 4; i++) {
                int idx = (i << 9) + tid;
                int k = idx >> 1, c = idx & 1;
                wsd[idx] = fcW[(long)((blockIdx.x << 1) + c) * HID + k];
            }
            float4 rx[4];
#pragma unroll
            for (int i = 0; i < 4; i++) {
                int idx = (i << 9) + tid;
                int b = idx & 63, k4 = idx >> 6;
                rx[i] = *(const float4*)(h1c + (long)b * HID + (k4 << 2));
            }
            float partial = 0.f;
            for (int ci = 0; ci < 8; ci++) {
                __syncthreads();
#pragma unroll
                for (int i = 0; i < 4; i++) {
                    int idx = (i << 9) + tid;
                    int b = idx & 63, k4 = idx >> 6;
                    int base = (k4 << 2) * 72 + b;
                    hs[base]       = rx[i].x;
                    hs[base + 72]  = rx[i].y;
                    hs[base + 144] = rx[i].z;
                    hs[base + 216] = rx[i].w;
                }
                __syncthreads();
                if (ci + 1 < 8) {
                    int k0 = (ci + 1) << 7;
#pragma unroll
                    for (int i = 0; i < 4; i++) {
                        int idx = (i << 9) + tid;
                        int b = idx & 63, k4 = idx >> 6;
                        rx[i] = *(const float4*)(h1c + (long)b * HID + k0 + (k4 << 2));
                    }
                }
                int k0 = ci << 7;
#pragma unroll 8
                for (int i = 0; i < 32; i++) {
                    int kk = fks * 32 + i;
                    partial += hs[kk * 72 + fb] * wsd[(k0 + kk) * 2 + fcc];
                }
            }
            __syncthreads();
            redA[tid] = partial;
            __syncthreads();
            if (fks == 0) {
                float s = redA[tid] + redA[tid + 1] + redA[tid + 2] + redA[tid + 3] + fcbv;
                out [(long)fb * TTRG * INP + (long)t * INP + fcol] = s;
                xbuf[(long)fb * INP + fcol] = s;
            }
        }
        grid_bar(target);
    }
}

// ---------------------------------------------------------------------------
extern "C" void kernel_launch(void* const* d_in, const int* in_sizes, int n_in,
                              void* d_out, int out_size)
{
    const float* src  = (const float*)d_in[0];
    const float* eWi0 = (const float*)d_in[2];
    const float* eWh0 = (const float*)d_in[3];
    const float* ebi0 = (const float*)d_in[4];
    const float* ebh0 = (const float*)d_in[5];
    const float* eWi1 = (const float*)d_in[6];
    const float* eWh1 = (const float*)d_in[7];
    const float* ebi1 = (const float*)d_in[8];
    const float* ebh1 = (const float*)d_in[9];
    const float* dWi0 = (const float*)d_in[10];
    const float* dWh0 = (const float*)d_in[11];
    const float* dbi0 = (const float*)d_in[12];
    const float* dbh0 = (const float*)d_in[13];
    const float* dWi1 = (const float*)d_in[14];
    const float* dWh1 = (const float*)d_in[15];
    const float* dbi1 = (const float*)d_in[16];
    const float* dbh1 = (const float*)d_in[17];
    const float* fcW  = (const float*)d_in[18];
    const float* fcb  = (const float*)d_in[19];

    float* out     = (float*)d_out;                   // [64, 64, 256]
    float* enc_out = out + (long)BB * TTRG * INP;     // [64, 256, 1024]
    float* dec_out = enc_out + (long)BB * TSRC * HID; // [64, 64, 1024]

    float *gi, *ys0, *h0, *h1, *xbuf;
    cudaGetSymbolAddress((void**)&gi,   g_gi);
    cudaGetSymbolAddress((void**)&ys0,  g_ys0);
    cudaGetSymbolAddress((void**)&h0,   g_h0);
    cudaGetSymbolAddress((void**)&h1,   g_h1);
    cudaGetSymbolAddress((void**)&xbuf, g_x);

    const int ENC_SMEM = 24 * WKP * 2 * 2 + 64 * HKP * 2 * 2
                       + 4 * 24 * 68 * 4 + 64 * 25 * 4;   // 166400 B
    const int DEC_SMEM = (128 * 28 + 128 * 72 + 2 * 8 * 24 * 68) * 4;
    cudaFuncSetAttribute(enc_layer_kernel,
                         cudaFuncAttributeMaxDynamicSharedMemorySize, ENC_SMEM);
    cudaFuncSetAttribute(dec_kernel,
                         cudaFuncAttributeMaxDynamicSharedMemorySize, DEC_SMEM);

    dim3 gridTc(48, 128);

    // ---------- encoder layer 0 ----------
    tc_gemm<<<gridTc, 256>>>(src, 65536L, 256L, eWi0, ebi0, gi, 256);
    enc_layer_kernel<<<GRID, NTH, ENC_SMEM>>>(
        gi, eWh0, ebh0, ys0, (long)BB * HID, (long)HID);

    // ---------- encoder layer 1 ----------
    tc_gemm<<<gridTc, 256>>>(ys0, 1024L, 65536L, eWi1, ebi1, gi, 1024);
    enc_layer_kernel<<<GRID, NTH, ENC_SMEM>>>(
        gi, eWh1, ebh1, enc_out, (long)HID, (long)TSRC * HID);

    // ---------- decoder ----------
    dec_kernel<<<GRID, NTH, DEC_SMEM>>>(
        dWi0, dWh0, dbi0, dbh0,
        dWi1, dWh1, dbi1, dbh1,
        fcW, fcb,
        ys0 + (long)(TSRC - 1) * BB * HID,
        enc_out + (long)(TSRC - 1) * HID,
        h0, h1, xbuf,
        out, dec_out);
}

// round 9
// speedup vs baseline: 2.3050x; 1.4621x over previous
#include <cuda_runtime.h>
#include <cuda_bf16.h>
#include <math.h>
#include <stdint.h>

#define HID  1024
#define INP  256
#define BB   64
#define TSRC 256
#define TTRG 64
#define G3   3072
#define GRID 128
#define NTH  512

typedef unsigned long long ull;

// ---------------- scratch (static device globals; no runtime allocation) ----
__device__ float g_gi [(long)TSRC * BB * G3];   // precomputed input gates
__device__ float g_ys0[(long)TSRC * BB * HID];  // enc layer-0 outputs [t][b][h]
__device__ float g_h0 [2 * BB * HID];           // decoder layer-0 hidden (ping-pong)
__device__ float g_h1 [2 * BB * HID];           // decoder layer-1 hidden (ping-pong)
__device__ float g_x  [BB * INP];               // decoder AR input
__device__ unsigned g_cnt;                      // barrier arrive count (self-resetting)
__device__ unsigned g_phase;                    // barrier release phase (monotonic)

__device__ __forceinline__ float sigf(float x) { return 1.0f / (1.0f + expf(-x)); }

// packed f32x2 helpers (decoder scalar path)
#define FMA2(a, b, c) asm volatile("fma.rn.f32x2 %0, %1, %2, %0;" : "+l"(a) : "l"(b), "l"(c))
#define PACK2(d, x)   asm volatile("mov.b64 %0, {%1, %1};" : "=l"(d) : "f"(x))
#define UNPK2(lo, hi, v) asm volatile("mov.b64 {%0, %1}, %2;" : "=f"(lo), "=f"(hi) : "l"(v))

// ---- tensor-core primitives ----
__device__ __forceinline__ uint32_t smem_u32(const void* p) {
    uint32_t a;
    asm("{ .reg .u64 t; cvta.to.shared.u64 t, %1; cvt.u32.u64 %0, t; }" : "=r"(a) : "l"(p));
    return a;
}
__device__ __forceinline__ void ldsm4(uint32_t& r0, uint32_t& r1, uint32_t& r2, uint32_t& r3,
                                      uint32_t addr) {
    asm volatile("ldmatrix.sync.aligned.m8n8.x4.shared.b16 {%0,%1,%2,%3}, [%4];"
                 : "=r"(r0), "=r"(r1), "=r"(r2), "=r"(r3) : "r"(addr));
}
__device__ __forceinline__ void ldsm2(uint32_t& r0, uint32_t& r1, uint32_t addr) {
    asm volatile("ldmatrix.sync.aligned.m8n8.x2.shared.b16 {%0,%1}, [%2];"
                 : "=r"(r0), "=r"(r1) : "r"(addr));
}
__device__ __forceinline__ void mma_bf16(float* d, const uint32_t* a, const uint32_t* b) {
    asm volatile(
        "mma.sync.aligned.m16n8k16.row.col.f32.bf16.bf16.f32 "
        "{%0,%1,%2,%3}, {%4,%5,%6,%7}, {%8,%9}, {%0,%1,%2,%3};"
        : "+f"(d[0]), "+f"(d[1]), "+f"(d[2]), "+f"(d[3])
        : "r"(a[0]), "r"(a[1]), "r"(a[2]), "r"(a[3]), "r"(b[0]), "r"(b[1]));
}
__device__ __forceinline__ uint32_t pack_bf2(float x, float y) {
    __nv_bfloat162 v = __floats2bfloat162_rn(x, y);
    return *(uint32_t*)&v;
}
__device__ __forceinline__ void split_bf(float x, __nv_bfloat16& hi, __nv_bfloat16& lo) {
    hi = __float2bfloat16_rn(x);
    lo = __float2bfloat16_rn(x - __bfloat162float(hi));
}
// PRMT: take high 16 bits of a (low half of result) and of b (high half)
__device__ __forceinline__ uint32_t prmt_hi(uint32_t a, uint32_t b) {
    uint32_t r;
    asm("prmt.b32 %0, %1, %2, 0x7632;" : "=r"(r) : "r"(a), "r"(b));
    return r;
}
// fast truncation split: hi = trunc-bf16(x), lo = rn-bf16(x - hi)
__device__ __forceinline__ void split4_fast(float4 v, uint2& uh, uint2& ul) {
    uint32_t ax = __float_as_uint(v.x), ay = __float_as_uint(v.y);
    uint32_t az = __float_as_uint(v.z), aw = __float_as_uint(v.w);
    uh.x = prmt_hi(ax, ay);
    uh.y = prmt_hi(az, aw);
    float lx = v.x - __uint_as_float(ax & 0xFFFF0000u);
    float ly = v.y - __uint_as_float(ay & 0xFFFF0000u);
    float lz = v.z - __uint_as_float(az & 0xFFFF0000u);
    float lw = v.w - __uint_as_float(aw & 0xFFFF0000u);
    ul.x = pack_bf2(lx, ly);
    ul.y = pack_bf2(lz, lw);
}

// ---------------------------------------------------------------------------
// Replay-safe grid barrier: monotonic phase + self-resetting counter.
// ---------------------------------------------------------------------------
__device__ __forceinline__ void grid_bar(unsigned& target)
{
    __threadfence();
    __syncthreads();
    if (threadIdx.x == 0) {
        unsigned a = atomicAdd(&g_cnt, 1u);
        if (a == (unsigned)GRID - 1u) {
            g_cnt = 0u;
            __threadfence();
            atomicAdd(&g_phase, 1u);
        } else {
            for (;;) {
                unsigned ph;
                asm volatile("ld.acquire.gpu.u32 %0, [%1];" : "=r"(ph) : "l"(&g_phase));
                if ((int)(ph - target) >= 0) break;
                __nanosleep(64);
            }
        }
        __threadfence();
    }
    __syncthreads();
    target++;
}

extern __shared__ float sm[];

// ---------------------------------------------------------------------------
// Decoder scalar helpers.  hs layout: [k][68]  (pad 68 -> 2-4 way STS, aligned
// LDS.128, conflict-free gemm reads).  Staging mapping is COALESCED:
// row = tid>>3 (0..63), quad = (tid&7) + 8i  -> 8 lanes read 128 contiguous B.
// ---------------------------------------------------------------------------
#define HSP 68

__device__ __forceinline__ void stage_x(
    float* hs, const float* __restrict__ X, long xs, int k0, int tid)
{
    const int b = tid >> 3;
    const int q = tid & 7;
#pragma unroll
    for (int i = 0; i < 4; i++) {
        int k4 = q + (i << 3);
        float4 v = *(const float4*)(X + (long)b * xs + k0 + (k4 << 2));
        int base = (k4 << 2) * HSP + b;
        hs[base]           = v.x;
        hs[base + HSP]     = v.y;
        hs[base + 2 * HSP] = v.z;
        hs[base + 3 * HSP] = v.w;
    }
}

__device__ __forceinline__ void gemm_chunk(
    const float* __restrict__ wsp, const float* __restrict__ hs,
    ull (&acc)[3][4], int ks, int bg, int cg)
{
#pragma unroll 4
    for (int i = 0; i < 16; i++) {
        int kk = (i << 3) + ks;
        const ull* wr = (const ull*)(wsp + kk * 28 + cg * 6);
        ull w0 = wr[0], w1 = wr[1], w2 = wr[2];
        float4 hv = *(const float4*)(hs + kk * HSP + (bg << 2));
        ull hb0, hb1, hb2, hb3;
        PACK2(hb0, hv.x); PACK2(hb1, hv.y); PACK2(hb2, hv.z); PACK2(hb3, hv.w);
        FMA2(acc[0][0], w0, hb0); FMA2(acc[0][1], w0, hb1);
        FMA2(acc[0][2], w0, hb2); FMA2(acc[0][3], w0, hb3);
        FMA2(acc[1][0], w1, hb0); FMA2(acc[1][1], w1, hb1);
        FMA2(acc[1][2], w1, hb2); FMA2(acc[1][3], w1, hb3);
        FMA2(acc[2][0], w2, hb0); FMA2(acc[2][1], w2, hb1);
        FMA2(acc[2][2], w2, hb2); FMA2(acc[2][3], w2, hb3);
    }
}

__device__ __forceinline__ void zero_acc(ull (&acc)[3][4])
{
#pragma unroll
    for (int c = 0; c < 3; c++)
#pragma unroll
        for (int b = 0; b < 4; b++) acc[c][b] = 0ull;
}

__device__ __forceinline__ void dump_red(
    float* red, ull (&acc)[3][4], int ks, int bg, int cg)
{
    float* rp = red + ks * 1632 + (cg * 6) * 68 + (bg << 2);
#pragma unroll
    for (int cp = 0; cp < 3; cp++) {
        float l0, h0, l1, h1, l2, h2, l3, h3;
        UNPK2(l0, h0, acc[cp][0]); UNPK2(l1, h1, acc[cp][1]);
        UNPK2(l2, h2, acc[cp][2]); UNPK2(l3, h3, acc[cp][3]);
        *(float4*)(rp + (2 * cp) * 68)     = make_float4(l0, l1, l2, l3);
        *(float4*)(rp + (2 * cp + 1) * 68) = make_float4(h0, h1, h2, h3);
    }
}

// pipelined streamed-weight GEMM phase: prefetch next chunk (x + W) into regs
// while gemm_chunk computes the current one.  Coalesced x loads.
__device__ __forceinline__ void stream_phase(
    const float* __restrict__ X, long xs,
    const float* __restrict__ W, int K,
    float* wsd, float* hs, ull (&acc)[3][4],
    int tid, int ks, int bg, int cg, int j0)
{
    const int NC = K >> 7;
    const int sb = tid >> 3;
    const int sq = tid & 7;
    float4 rx[4];
    float  rw[6];
#pragma unroll
    for (int i = 0; i < 4; i++) {
        int k4 = sq + (i << 3);
        rx[i] = *(const float4*)(X + (long)sb * xs + (k4 << 2));
    }
#pragma unroll
    for (int i = 0; i < 6; i++) {
        int idx = (i << 9) + tid;
        int c = idx >> 7, k = idx & 127;
        int row = ((c >> 3) << 10) + j0 + (c & 7);
        rw[i] = W[(long)row * (long)K + k];
    }
    for (int ci = 0; ci < NC; ci++) {
        __syncthreads();
#pragma unroll
        for (int i = 0; i < 4; i++) {
            int k4 = sq + (i << 3);
            int base = (k4 << 2) * HSP + sb;
            hs[base]           = rx[i].x;
            hs[base + HSP]     = rx[i].y;
            hs[base + 2 * HSP] = rx[i].z;
            hs[base + 3 * HSP] = rx[i].w;
        }
#pragma unroll
        for (int i = 0; i < 6; i++) {
            int idx = (i << 9) + tid;
            int c = idx >> 7, k = idx & 127;
            wsd[k * 28 + c] = rw[i];
        }
        __syncthreads();
        if (ci + 1 < NC) {
            int k0 = (ci + 1) << 7;
#pragma unroll
            for (int i = 0; i < 4; i++) {
                int k4 = sq + (i << 3);
                rx[i] = *(const float4*)(X + (long)sb * xs + k0 + (k4 << 2));
            }
#pragma unroll
            for (int i = 0; i < 6; i++) {
                int idx = (i << 9) + tid;
                int c = idx >> 7, k = idx & 127;
                int row = ((c >> 3) << 10) + j0 + (c & 7);
                rw[i] = W[(long)row * (long)K + k0 + k];
            }
        }
        gemm_chunk(wsd, hs, acc, ks, bg, cg);
    }
}

// ---------------------------------------------------------------------------
// Tensor-core batched input-gate GEMM (split-bf16, compensated) — unchanged
// ---------------------------------------------------------------------------
#define AKP 40

__global__ void __launch_bounds__(256) tc_gemm(
    const float* __restrict__ X, long sb, long st,
    const float* __restrict__ W, const float* __restrict__ bias,
    float* __restrict__ out, int K)
{
    __shared__ __nv_bfloat16 Ahi[128 * AKP];
    __shared__ __nv_bfloat16 Alo[128 * AKP];
    __shared__ __nv_bfloat16 Bhi[64 * AKP];
    __shared__ __nv_bfloat16 Blo[64 * AKP];

    const int tid  = threadIdx.x;
    const int warp = tid >> 5;
    const int lane = tid & 31;
    const long cb  = (long)blockIdx.x * 64;
    const long rb  = (long)blockIdx.y * 128;

    const int rowA = warp * 16 + ((lane >> 3) & 1) * 8 + (lane & 7);
    const int kA   = ((lane >> 4) & 1) * 8;
    const int lm   = lane & 15;
    const int bRow = lm & 7;
    const int bK   = ((lm >> 3) & 1) * 8;
    const uint32_t AhiA = smem_u32(Ahi);
    const uint32_t AloA = smem_u32(Alo);
    const uint32_t BhiA = smem_u32(Bhi);
    const uint32_t BloA = smem_u32(Blo);

    float acc[8][4];
#pragma unroll
    for (int n = 0; n < 8; n++)
#pragma unroll
        for (int i = 0; i < 4; i++) acc[n][i] = 0.0f;

    for (int k0 = 0; k0 < K; k0 += 32) {
        __syncthreads();
#pragma unroll
        for (int i = 0; i < 4; i++) {
            int idx = (i << 8) + tid;
            int row = idx >> 3, q = idx & 7;
            long r = rb + row;
            long off = (r & 63) * sb + (r >> 6) * st + k0 + (q << 2);
            float4 v = *(const float4*)(X + off);
            uint2 uh, ul;
            split4_fast(v, uh, ul);
            *(uint2*)&Ahi[row * AKP + (q << 2)] = uh;
            *(uint2*)&Alo[row * AKP + (q << 2)] = ul;
        }
#pragma unroll
        for (int i = 0; i < 2; i++) {
            int idx = (i << 8) + tid;
            int row = idx >> 3, q = idx & 7;
            float4 v = *(const float4*)(W + (cb + row) * (long)K + k0 + (q << 2));
            uint2 uh, ul;
            split4_fast(v, uh, ul);
            *(uint2*)&Bhi[row * AKP + (q << 2)] = uh;
            *(uint2*)&Blo[row * AKP + (q << 2)] = ul;
        }
        __syncthreads();

#pragma unroll
        for (int s = 0; s < 2; s++) {
            int kk = s * 16;
            uint32_t ah[4], al[4];
            ldsm4(ah[0], ah[1], ah[2], ah[3],
                  AhiA + (uint32_t)((rowA * AKP + kk + kA) * 2));
            ldsm4(al[0], al[1], al[2], al[3],
                  AloA + (uint32_t)((rowA * AKP + kk + kA) * 2));
#pragma unroll
            for (int nt = 0; nt < 8; nt++) {
                uint32_t bh2[2], bl2[2];
                uint32_t boff = (uint32_t)(((nt * 8 + bRow) * AKP + kk + bK) * 2);
                ldsm2(bh2[0], bh2[1], BhiA + boff);
                ldsm2(bl2[0], bl2[1], BloA + boff);
                mma_bf16(acc[nt], ah, bh2);
                mma_bf16(acc[nt], ah, bl2);
                mma_bf16(acc[nt], al, bh2);
            }
        }
    }

    const int g  = lane >> 2;
    const int t4 = lane & 3;
#pragma unroll
    for (int nt = 0; nt < 8; nt++) {
        long c = cb + nt * 8 + t4 * 2;
        float2 bv = *(const float2*)(bias + c);
        long r0 = rb + warp * 16 + g;
        *(float2*)(out + r0 * G3 + c) = make_float2(acc[nt][0] + bv.x, acc[nt][1] + bv.y);
        *(float2*)(out + (r0 + 8) * G3 + c) = make_float2(acc[nt][2] + bv.x, acc[nt][3] + bv.y);
    }
}

// ---------------------------------------------------------------------------
// Persistent encoder layer — tensor-core split-bf16, depth-2 reg prefetch,
// COALESCED h staging (row = tid>>3, quad = (tid&7)+8i).
// ---------------------------------------------------------------------------
#define WKP 1032
#define HKP 136

__global__ void __launch_bounds__(NTH, 1) enc_layer_kernel(
    const float* __restrict__ gi,
    const float* __restrict__ Wh,
    const float* __restrict__ bh,
    float* __restrict__ out, long out_t, long out_b)
{
    __nv_bfloat16* whi = (__nv_bfloat16*)sm;
    __nv_bfloat16* wlo = whi + 24 * WKP;
    __nv_bfloat16* hhi = wlo + 24 * WKP;
    __nv_bfloat16* hlo = hhi + 64 * HKP;
    float* red = (float*)(hlo + 64 * HKP);
    float* gis = red + 4 * 24 * 68;

    const int tid  = threadIdx.x;
    const int j0   = blockIdx.x << 3;
    const int warp = tid >> 5;
    const int lane = tid & 31;
    const int mw   = warp & 3;
    const int kw   = warp >> 2;
    const int eb   = tid >> 3;
    const int ej   = tid & 7;
    const int ecol = j0 + ej;

    unsigned target;
    { volatile unsigned* pp = &g_phase; target = *pp + 1u; }

    for (int i = 0; i < 48; i++) {
        int idx = tid + (i << 9);
        int c = idx >> 10, k = idx & 1023;
        int row = ((c >> 3) << 10) + j0 + (c & 7);
        float w = Wh[(long)row * HID + k];
        __nv_bfloat16 hi, lo;
        split_bf(w, hi, lo);
        whi[c * WKP + k] = hi;
        wlo[c * WKP + k] = lo;
    }
    const float bhr = bh[ecol];
    const float bhz = bh[HID + ecol];
    const float bhn = bh[2 * HID + ecol];

    const int rowA = mw * 16 + ((lane >> 3) & 1) * 8 + (lane & 7);
    const int kA   = ((lane >> 4) & 1) * 8;
    const int lm   = lane & 15;
    const int bOff = (lm & 7) * WKP + ((lm >> 3) & 1) * 8;
    const uint32_t hhiA = smem_u32(hhi);
    const uint32_t hloA = smem_u32(hlo);
    const uint32_t whiA = smem_u32(whi);
    const uint32_t wloA = smem_u32(wlo);

    // coalesced staging coordinates: 8 lanes cover 128 contiguous bytes of one row
    const int srow = tid >> 3;           // batch row (0..63)
    const int sq   = tid & 7;            // base quad within chunk
    __syncthreads();

    for (int t = 0; t < TSRC; t++) {
        float c0[4], c1[4], c2[4];
#pragma unroll
        for (int i = 0; i < 4; i++) { c0[i] = 0.f; c1[i] = 0.f; c2[i] = 0.f; }

        const float* hprev = out + (long)(t - 1) * out_t;
        float hold = 0.0f;
        float4 rA[2][4];
        if (t > 0) {
            hold = hprev[(long)eb * out_b + ecol];
            // preload chunks 0,1 into regs (coalesced)
#pragma unroll
            for (int p = 0; p < 2; p++)
#pragma unroll
                for (int i = 0; i < 4; i++) {
                    int k4 = sq + (i << 3);
                    rA[p][i] = *(const float4*)(hprev + (long)srow * out_b + (p << 7) + (k4 << 2));
                }
        }

        // stage gi tile (overlaps with chunk prefetch)
        {
            const float* gi_t = gi + (long)t * BB * G3;
#pragma unroll
            for (int i = 0; i < 3; i++) {
                int idx = (i << 9) + tid;
                int b = idx / 24;
                int rem = idx - b * 24;
                gis[b * 25 + rem] = gi_t[(long)b * G3 + ((rem >> 3) << 10) + j0 + (rem & 7)];
            }
        }

        if (t > 0) {
            for (int c = 0; c < 8; c++) {
                __syncthreads();
                // convert + store chunk c from regs
#pragma unroll
                for (int i = 0; i < 4; i++) {
                    int k4 = sq + (i << 3);
                    uint2 uh, ul;
                    split4_fast(rA[c & 1][i], uh, ul);
                    *(uint2*)&hhi[srow * HKP + (k4 << 2)] = uh;
                    *(uint2*)&hlo[srow * HKP + (k4 << 2)] = ul;
                }
                __syncthreads();
                // prefetch chunk c+2 (coalesced)
                if (c < 6) {
                    int k0n = (c + 2) << 7;
#pragma unroll
                    for (int i = 0; i < 4; i++) {
                        int k4 = sq + (i << 3);
                        rA[c & 1][i] =
                            *(const float4*)(hprev + (long)srow * out_b + k0n + (k4 << 2));
                    }
                }
                // MMA on chunk c
                int k0 = c << 7;
#pragma unroll
                for (int s = 0; s < 2; s++) {
                    int kk = kw * 32 + s * 16;
                    int kg = k0 + kk;
                    uint32_t ah[4], al[4];
                    ldsm4(ah[0], ah[1], ah[2], ah[3],
                          hhiA + (uint32_t)((rowA * HKP + kk + kA) * 2));
                    ldsm4(al[0], al[1], al[2], al[3],
                          hloA + (uint32_t)((rowA * HKP + kk + kA) * 2));
                    uint32_t bh2[2], bl2[2];
                    ldsm2(bh2[0], bh2[1], whiA + (uint32_t)((bOff + kg) * 2));
                    ldsm2(bl2[0], bl2[1], wloA + (uint32_t)((bOff + kg) * 2));
                    mma_bf16(c0, ah, bh2); mma_bf16(c0, ah, bl2); mma_bf16(c0, al, bh2);
                    ldsm2(bh2[0], bh2[1], whiA + (uint32_t)((8 * WKP + bOff + kg) * 2));
                    ldsm2(bl2[0], bl2[1], wloA + (uint32_t)((8 * WKP + bOff + kg) * 2));
                    mma_bf16(c1, ah, bh2); mma_bf16(c1, ah, bl2); mma_bf16(c1, al, bh2);
                    ldsm2(bh2[0], bh2[1], whiA + (uint32_t)((16 * WKP + bOff + kg) * 2));
                    ldsm2(bl2[0], bl2[1], wloA + (uint32_t)((16 * WKP + bOff + kg) * 2));
                    mma_bf16(c2, ah, bh2); mma_bf16(c2, ah, bl2); mma_bf16(c2, al, bh2);
                }
            }
        }
        __syncthreads();
        {
            float* rp = red + kw * 1632;
            int g = lane >> 2, t4 = lane & 3;
            int r0 = mw * 16 + g;
            int n0 = 2 * t4;
            rp[n0 * 68 + r0]            = c0[0];
            rp[(n0 + 1) * 68 + r0]      = c0[1];
            rp[n0 * 68 + r0 + 8]        = c0[2];
            rp[(n0 + 1) * 68 + r0 + 8]  = c0[3];
            rp[(8 + n0) * 68 + r0]           = c1[0];
            rp[(8 + n0 + 1) * 68 + r0]       = c1[1];
            rp[(8 + n0) * 68 + r0 + 8]       = c1[2];
            rp[(8 + n0 + 1) * 68 + r0 + 8]   = c1[3];
            rp[(16 + n0) * 68 + r0]          = c2[0];
            rp[(16 + n0 + 1) * 68 + r0]      = c2[1];
            rp[(16 + n0) * 68 + r0 + 8]      = c2[2];
            rp[(16 + n0 + 1) * 68 + r0 + 8]  = c2[3];
        }
        __syncthreads();

        float s0 = 0.f, s1 = 0.f, s2 = 0.f;
#pragma unroll
        for (int k = 0; k < 4; k++) {
            const float* rp = red + k * 1632 + eb;
            s0 += rp[(ej)      * 68];
            s1 += rp[(8 + ej)  * 68];
            s2 += rp[(16 + ej) * 68];
        }
        const float* gp = gis + eb * 25;
        float GR = gp[ej], GZ = gp[8 + ej], GN = gp[16 + ej];
        float r = sigf(GR + s0 + bhr);
        float z = sigf(GZ + s1 + bhz);
        float n = tanhf(GN + r * (s2 + bhn));
        float hn = (1.0f - z) * n + z * hold;
        out[(long)t * out_t + (long)eb * out_b + ecol] = hn;

        if (t < TSRC - 1) grid_bar(target);
    }
}

// ---------------------------------------------------------------------------
// Persistent decoder: pipelined stream phases, coalesced staging
// ---------------------------------------------------------------------------
__global__ void __launch_bounds__(NTH, 1) dec_kernel(
    const float* __restrict__ dWi0, const float* __restrict__ dWh0,
    const float* __restrict__ dbi0, const float* __restrict__ dbh0,
    const float* __restrict__ dWi1, const float* __restrict__ dWh1,
    const float* __restrict__ dbi1, const float* __restrict__ dbh1,
    const float* __restrict__ fcW,  const float* __restrict__ fcb,
    const float* __restrict__ enc0_hT,
    const float* __restrict__ enc1_hT,
    float* __restrict__ h0buf, float* __restrict__ h1buf, float* __restrict__ xbuf,
    float* __restrict__ out,
    float* __restrict__ dec_out)
{
    float* wsd  = sm;
    float* hs   = wsd + 128 * 28;
    float* redA = hs + 128 * HSP;
    float* redB = redA + 8 * 24 * 68;

    const int tid = threadIdx.x;
    const int j0  = blockIdx.x << 3;
    const int ks  = tid >> 6;
    const int bg  = (tid >> 2) & 15;
    const int cg  = tid & 3;
    const int eb  = tid >> 3;
    const int ej  = tid & 7;
    const int ecol = j0 + ej;
    const int fb  = tid >> 3;
    const int fcc = (tid >> 2) & 1;
    const int fks = tid & 3;
    const int fcol = (blockIdx.x << 1) + fcc;

    unsigned target;
    { volatile unsigned* pp = &g_phase; target = *pp + 1u; }

    const float b0ir = dbi0[ecol], b0iz = dbi0[HID + ecol], b0in = dbi0[2 * HID + ecol];
    const float b0hr = dbh0[ecol], b0hz = dbh0[HID + ecol], b0hn = dbh0[2 * HID + ecol];
    const float b1ir = dbi1[ecol], b1iz = dbi1[HID + ecol], b1in = dbi1[2 * HID + ecol];
    const float b1hr = dbh1[ecol], b1hz = dbh1[HID + ecol], b1hn = dbh1[2 * HID + ecol];
    const float fcbv = fcb[fcol];

    ull acc[3][4];

    for (int t = 0; t < TTRG; t++) {
        const int w = t & 1;

        // ================= layer 0 =================
        zero_acc(acc);
        if (t > 0)
            stream_phase(xbuf, INP, dWi0, INP, wsd, hs, acc, tid, ks, bg, cg, j0);
        dump_red(redA, acc, ks, bg, cg);

        const float* h0p = t ? h0buf + (long)(1 - w) * BB * HID : enc0_hT;
        zero_acc(acc);
        stream_phase(h0p, HID, dWh0, HID, wsd, hs, acc, tid, ks, bg, cg, j0);
        dump_red(redB, acc, ks, bg, cg);
        __syncthreads();
        {
            float a0 = 0.f, a1 = 0.f, a2 = 0.f, c0 = 0.f, c1 = 0.f, c2 = 0.f;
#pragma unroll
            for (int k = 0; k < 8; k++) {
                const float* ra = redA + k * 1632 + eb;
                const float* rb = redB + k * 1632 + eb;
                a0 += ra[ej * 68];        c0 += rb[ej * 68];
                a1 += ra[(8 + ej) * 68];  c1 += rb[(8 + ej) * 68];
                a2 += ra[(16 + ej) * 68]; c2 += rb[(16 + ej) * 68];
            }
            float hold = h0p[(long)eb * HID + ecol];
            float r = sigf(a0 + b0ir + c0 + b0hr);
            float z = sigf(a1 + b0iz + c1 + b0hz);
            float n = tanhf(a2 + b0in + r * (c2 + b0hn));
            h0buf[(long)w * BB * HID + (long)eb * HID + ecol] = (1.f - z) * n + z * hold;
        }
        grid_bar(target);

        // ================= layer 1 =================
        const float* x1 = h0buf + (long)w * BB * HID;
        zero_acc(acc);
        stream_phase(x1, HID, dWi1, HID, wsd, hs, acc, tid, ks, bg, cg, j0);
        dump_red(redA, acc, ks, bg, cg);

        const float* h1p = t ? h1buf + (long)(1 - w) * BB * HID : enc1_hT;
        const long   h1s = t ? (long)HID : (long)TSRC * HID;
        zero_acc(acc);
        stream_phase(h1p, h1s, dWh1, HID, wsd, hs, acc, tid, ks, bg, cg, j0);
        dump_red(redB, acc, ks, bg, cg);
        __syncthreads();
        {
            float a0 = 0.f, a1 = 0.f, a2 = 0.f, c0 = 0.f, c1 = 0.f, c2 = 0.f;
#pragma unroll
            for (int k = 0; k < 8; k++) {
                const float* ra = redA + k * 1632 + eb;
                const float* rb = redB + k * 1632 + eb;
                a0 += ra[ej * 68];        c0 += rb[ej * 68];
                a1 += ra[(8 + ej) * 68];  c1 += rb[(8 + ej) * 68];
                a2 += ra[(16 + ej) * 68]; c2 += rb[(16 + ej) * 68];
            }
            float hold = h1p[(long)eb * h1s + ecol];
            float r = sigf(a0 + b1ir + c0 + b1hr);
            float z = sigf(a1 + b1iz + c1 + b1hz);
            float n = tanhf(a2 + b1in + r * (c2 + b1hn));
            float hn = (1.f - z) * n + z * hold;
            h1buf[(long)w * BB * HID + (long)eb * HID + ecol] = hn;
            dec_out[(long)eb * TTRG * HID + (long)t * HID + ecol] = hn;
        }
        grid_bar(target);

        // ================= fc (pipelined, coalesced staging) =================
        {
            const float* h1c = h1buf + (long)w * BB * HID;
            const int sb = tid >> 3;
            const int sq = tid & 7;
#pragma unroll
            for (int i = 0; i < 4; i++) {
                int idx = (i << 9) + tid;
                int k = idx >> 1, c = idx & 1;
                wsd[idx] = fcW[(long)((blockIdx.x << 1) + c) * HID + k];
            }
            float4 rx[4];
#pragma unroll
            for (int i = 0; i < 4; i++) {
                int k4 = sq + (i << 3);
                rx[i] = *(const float4*)(h1c + (long)sb * HID + (k4 << 2));
            }
            float partial = 0.f;
            for (int ci = 0; ci < 8; ci++) {
                __syncthreads();
#pragma unroll
                for (int i = 0; i < 4; i++) {
                    int k4 = sq + (i << 3);
                    int base = (k4 << 2) * HSP + sb;
                    hs[base]           = rx[i].x;
                    hs[base + HSP]     = rx[i].y;
                    hs[base + 2 * HSP] = rx[i].z;
                    hs[base + 3 * HSP] = rx[i].w;
                }
                __syncthreads();
                if (ci + 1 < 8) {
                    int k0 = (ci + 1) << 7;
#pragma unroll
                    for (int i = 0; i < 4; i++) {
                        int k4 = sq + (i << 3);
                        rx[i] = *(const float4*)(h1c + (long)sb * HID + k0 + (k4 << 2));
                    }
                }
                int k0 = ci << 7;
#pragma unroll 8
                for (int i = 0; i < 32; i++) {
                    int kk = fks * 32 + i;
                    partial += hs[kk * HSP + fb] * wsd[(k0 + kk) * 2 + fcc];
                }
            }
            __syncthreads();
            redA[tid] = partial;
            __syncthreads();
            if (fks == 0) {
                float s = redA[tid] + redA[tid + 1] + redA[tid + 2] + redA[tid + 3] + fcbv;
                out [(long)fb * TTRG * INP + (long)t * INP + fcol] = s;
                xbuf[(long)fb * INP + fcol] = s;
            }
        }
        grid_bar(target);
    }
}

// ---------------------------------------------------------------------------
extern "C" void kernel_launch(void* const* d_in, const int* in_sizes, int n_in,
                              void* d_out, int out_size)
{
    const float* src  = (const float*)d_in[0];
    const float* eWi0 = (const float*)d_in[2];
    const float* eWh0 = (const float*)d_in[3];
    const float* ebi0 = (const float*)d_in[4];
    const float* ebh0 = (const float*)d_in[5];
    const float* eWi1 = (const float*)d_in[6];
    const float* eWh1 = (const float*)d_in[7];
    const float* ebi1 = (const float*)d_in[8];
    const float* ebh1 = (const float*)d_in[9];
    const float* dWi0 = (const float*)d_in[10];
    const float* dWh0 = (const float*)d_in[11];
    const float* dbi0 = (const float*)d_in[12];
    const float* dbh0 = (const float*)d_in[13];
    const float* dWi1 = (const float*)d_in[14];
    const float* dWh1 = (const float*)d_in[15];
    const float* dbi1 = (const float*)d_in[16];
    const float* dbh1 = (const float*)d_in[17];
    const float* fcW  = (const float*)d_in[18];
    const float* fcb  = (const float*)d_in[19];

    float* out     = (float*)d_out;                   // [64, 64, 256]
    float* enc_out = out + (long)BB * TTRG * INP;     // [64, 256, 1024]
    float* dec_out = enc_out + (long)BB * TSRC * HID; // [64, 64, 1024]

    float *gi, *ys0, *h0, *h1, *xbuf;
    cudaGetSymbolAddress((void**)&gi,   g_gi);
    cudaGetSymbolAddress((void**)&ys0,  g_ys0);
    cudaGetSymbolAddress((void**)&h0,   g_h0);
    cudaGetSymbolAddress((void**)&h1,   g_h1);
    cudaGetSymbolAddress((void**)&xbuf, g_x);

    const int ENC_SMEM = 24 * WKP * 2 * 2 + 64 * HKP * 2 * 2
                       + 4 * 24 * 68 * 4 + 64 * 25 * 4;   // 166400 B
    const int DEC_SMEM = (128 * 28 + 128 * HSP + 2 * 8 * 24 * 68) * 4;
    cudaFuncSetAttribute(enc_layer_kernel,
                         cudaFuncAttributeMaxDynamicSharedMemorySize, ENC_SMEM);
    cudaFuncSetAttribute(dec_kernel,
                         cudaFuncAttributeMaxDynamicSharedMemorySize, DEC_SMEM);

    dim3 gridTc(48, 128);

    // ---------- encoder layer 0 ----------
    tc_gemm<<<gridTc, 256>>>(src, 65536L, 256L, eWi0, ebi0, gi, 256);
    enc_layer_kernel<<<GRID, NTH, ENC_SMEM>>>(
        gi, eWh0, ebh0, ys0, (long)BB * HID, (long)HID);

    // ---------- encoder layer 1 ----------
    tc_gemm<<<gridTc, 256>>>(ys0, 1024L, 65536L, eWi1, ebi1, gi, 1024);
    enc_layer_kernel<<<GRID, NTH, ENC_SMEM>>>(
        gi, eWh1, ebh1, enc_out, (long)HID, (long)TSRC * HID);

    // ---------- decoder ----------
    dec_kernel<<<GRID, NTH, DEC_SMEM>>>(
        dWi0, dWh0, dbi0, dbh0,
        dWi1, dWh1, dbi1, dbh1,
        fcW, fcb,
        ys0 + (long)(TSRC - 1) * BB * HID,
        enc_out + (long)(TSRC - 1) * HID,
        h0, h1, xbuf,
        out, dec_out);
}

// round 10
// speedup vs baseline: 2.6746x; 1.1603x over previous
#include <cuda_runtime.h>
#include <cuda_bf16.h>
#include <math.h>
#include <stdint.h>

#define HID  1024
#define INP  256
#define BB   64
#define TSRC 256
#define TTRG 64
#define G3   3072
#define GRID 128
#define NTH  512

typedef unsigned long long ull;

// ---------------- scratch (static device globals; no runtime allocation) ----
__device__ float g_gi [(long)TSRC * BB * G3];   // precomputed input gates
__device__ float g_ys0[(long)TSRC * BB * HID];  // enc layer-0 outputs [t][b][h]
__device__ float g_h0 [2 * BB * HID];           // decoder layer-0 hidden (ping-pong)
__device__ float g_h1 [2 * BB * HID];           // decoder layer-1 hidden (ping-pong)
__device__ float g_x  [BB * INP];               // decoder AR input
__device__ unsigned g_cnt;                      // barrier arrive count (self-resetting)
__device__ unsigned g_phase;                    // barrier release phase (monotonic)

__device__ __forceinline__ float sigf(float x) { return 1.0f / (1.0f + expf(-x)); }

// ---- tensor-core primitives ----
__device__ __forceinline__ uint32_t smem_u32(const void* p) {
    uint32_t a;
    asm("{ .reg .u64 t; cvta.to.shared.u64 t, %1; cvt.u32.u64 %0, t; }" : "=r"(a) : "l"(p));
    return a;
}
__device__ __forceinline__ void ldsm4(uint32_t& r0, uint32_t& r1, uint32_t& r2, uint32_t& r3,
                                      uint32_t addr) {
    asm volatile("ldmatrix.sync.aligned.m8n8.x4.shared.b16 {%0,%1,%2,%3}, [%4];"
                 : "=r"(r0), "=r"(r1), "=r"(r2), "=r"(r3) : "r"(addr));
}
__device__ __forceinline__ void ldsm2(uint32_t& r0, uint32_t& r1, uint32_t addr) {
    asm volatile("ldmatrix.sync.aligned.m8n8.x2.shared.b16 {%0,%1}, [%2];"
                 : "=r"(r0), "=r"(r1) : "r"(addr));
}
__device__ __forceinline__ void mma_bf16(float* d, const uint32_t* a, const uint32_t* b) {
    asm volatile(
        "mma.sync.aligned.m16n8k16.row.col.f32.bf16.bf16.f32 "
        "{%0,%1,%2,%3}, {%4,%5,%6,%7}, {%8,%9}, {%0,%1,%2,%3};"
        : "+f"(d[0]), "+f"(d[1]), "+f"(d[2]), "+f"(d[3])
        : "r"(a[0]), "r"(a[1]), "r"(a[2]), "r"(a[3]), "r"(b[0]), "r"(b[1]));
}
__device__ __forceinline__ uint32_t pack_bf2(float x, float y) {
    __nv_bfloat162 v = __floats2bfloat162_rn(x, y);
    return *(uint32_t*)&v;
}
__device__ __forceinline__ void split_bf(float x, __nv_bfloat16& hi, __nv_bfloat16& lo) {
    hi = __float2bfloat16_rn(x);
    lo = __float2bfloat16_rn(x - __bfloat162float(hi));
}
// PRMT: take high 16 bits of a (low half of result) and of b (high half)
__device__ __forceinline__ uint32_t prmt_hi(uint32_t a, uint32_t b) {
    uint32_t r;
    asm("prmt.b32 %0, %1, %2, 0x7632;" : "=r"(r) : "r"(a), "r"(b));
    return r;
}
// fast truncation split: hi = trunc-bf16(x), lo = rn-bf16(x - hi)
__device__ __forceinline__ void split4_fast(float4 v, uint2& uh, uint2& ul) {
    uint32_t ax = __float_as_uint(v.x), ay = __float_as_uint(v.y);
    uint32_t az = __float_as_uint(v.z), aw = __float_as_uint(v.w);
    uh.x = prmt_hi(ax, ay);
    uh.y = prmt_hi(az, aw);
    float lx = v.x - __uint_as_float(ax & 0xFFFF0000u);
    float ly = v.y - __uint_as_float(ay & 0xFFFF0000u);
    float lz = v.z - __uint_as_float(az & 0xFFFF0000u);
    float lw = v.w - __uint_as_float(aw & 0xFFFF0000u);
    ul.x = pack_bf2(lx, ly);
    ul.y = pack_bf2(lz, lw);
}
// scalar truncation split (for streamed weights)
__device__ __forceinline__ void split1_fast(float x, __nv_bfloat16& hi, __nv_bfloat16& lo) {
    uint32_t ax = __float_as_uint(x);
    uint32_t h = ax & 0xFFFF0000u;
    uint16_t hbits = (uint16_t)(ax >> 16);
    hi = *(__nv_bfloat16*)&hbits;
    lo = __float2bfloat16_rn(x - __uint_as_float(h));
}

// ---------------------------------------------------------------------------
// Replay-safe grid barrier: monotonic phase + self-resetting counter.
// ---------------------------------------------------------------------------
__device__ __forceinline__ void grid_bar(unsigned& target)
{
    __threadfence();
    __syncthreads();
    if (threadIdx.x == 0) {
        unsigned a = atomicAdd(&g_cnt, 1u);
        if (a == (unsigned)GRID - 1u) {
            g_cnt = 0u;
            __threadfence();
            atomicAdd(&g_phase, 1u);
        } else {
            for (;;) {
                unsigned ph;
                asm volatile("ld.acquire.gpu.u32 %0, [%1];" : "=r"(ph) : "l"(&g_phase));
                if ((int)(ph - target) >= 0) break;
                __nanosleep(64);
            }
        }
        __threadfence();
    }
    __syncthreads();
    target++;
}

extern __shared__ float sm[];

#define WKP 1032   // padded k-stride (bf16) for encoder persistent weights
#define HKP 136    // padded k-stride (bf16) for 128-k chunk tiles
#define HSP 68     // float stride for fc scalar tile

// fragment dump: red[kw][n(24)][b(68 pad)]
__device__ __forceinline__ void dump_frag(
    float* red, const float* c0, const float* c1, const float* c2,
    int kw, int mw, int lane)
{
    float* rp = red + kw * 1632;
    int g = lane >> 2, t4 = lane & 3;
    int r0 = mw * 16 + g;
    int n0 = 2 * t4;
    rp[n0 * 68 + r0]            = c0[0];
    rp[(n0 + 1) * 68 + r0]      = c0[1];
    rp[n0 * 68 + r0 + 8]        = c0[2];
    rp[(n0 + 1) * 68 + r0 + 8]  = c0[3];
    rp[(8 + n0) * 68 + r0]           = c1[0];
    rp[(8 + n0 + 1) * 68 + r0]       = c1[1];
    rp[(8 + n0) * 68 + r0 + 8]       = c1[2];
    rp[(8 + n0 + 1) * 68 + r0 + 8]   = c1[3];
    rp[(16 + n0) * 68 + r0]          = c2[0];
    rp[(16 + n0 + 1) * 68 + r0]      = c2[1];
    rp[(16 + n0) * 68 + r0 + 8]      = c2[2];
    rp[(16 + n0 + 1) * 68 + r0 + 8]  = c2[3];
}

// ---------------------------------------------------------------------------
// Tensor-core batched input-gate GEMM (split-bf16, compensated) — unchanged
// ---------------------------------------------------------------------------
#define AKP 40

__global__ void __launch_bounds__(256) tc_gemm(
    const float* __restrict__ X, long sb, long st,
    const float* __restrict__ W, const float* __restrict__ bias,
    float* __restrict__ out, int K)
{
    __shared__ __nv_bfloat16 Ahi[128 * AKP];
    __shared__ __nv_bfloat16 Alo[128 * AKP];
    __shared__ __nv_bfloat16 Bhi[64 * AKP];
    __shared__ __nv_bfloat16 Blo[64 * AKP];

    const int tid  = threadIdx.x;
    const int warp = tid >> 5;
    const int lane = tid & 31;
    const long cb  = (long)blockIdx.x * 64;
    const long rb  = (long)blockIdx.y * 128;

    const int rowA = warp * 16 + ((lane >> 3) & 1) * 8 + (lane & 7);
    const int kA   = ((lane >> 4) & 1) * 8;
    const int lm   = lane & 15;
    const int bRow = lm & 7;
    const int bK   = ((lm >> 3) & 1) * 8;
    const uint32_t AhiA = smem_u32(Ahi);
    const uint32_t AloA = smem_u32(Alo);
    const uint32_t BhiA = smem_u32(Bhi);
    const uint32_t BloA = smem_u32(Blo);

    float acc[8][4];
#pragma unroll
    for (int n = 0; n < 8; n++)
#pragma unroll
        for (int i = 0; i < 4; i++) acc[n][i] = 0.0f;

    for (int k0 = 0; k0 < K; k0 += 32) {
        __syncthreads();
#pragma unroll
        for (int i = 0; i < 4; i++) {
            int idx = (i << 8) + tid;
            int row = idx >> 3, q = idx & 7;
            long r = rb + row;
            long off = (r & 63) * sb + (r >> 6) * st + k0 + (q << 2);
            float4 v = *(const float4*)(X + off);
            uint2 uh, ul;
            split4_fast(v, uh, ul);
            *(uint2*)&Ahi[row * AKP + (q << 2)] = uh;
            *(uint2*)&Alo[row * AKP + (q << 2)] = ul;
        }
#pragma unroll
        for (int i = 0; i < 2; i++) {
            int idx = (i << 8) + tid;
            int row = idx >> 3, q = idx & 7;
            float4 v = *(const float4*)(W + (cb + row) * (long)K + k0 + (q << 2));
            uint2 uh, ul;
            split4_fast(v, uh, ul);
            *(uint2*)&Bhi[row * AKP + (q << 2)] = uh;
            *(uint2*)&Blo[row * AKP + (q << 2)] = ul;
        }
        __syncthreads();

#pragma unroll
        for (int s = 0; s < 2; s++) {
            int kk = s * 16;
            uint32_t ah[4], al[4];
            ldsm4(ah[0], ah[1], ah[2], ah[3],
                  AhiA + (uint32_t)((rowA * AKP + kk + kA) * 2));
            ldsm4(al[0], al[1], al[2], al[3],
                  AloA + (uint32_t)((rowA * AKP + kk + kA) * 2));
#pragma unroll
            for (int nt = 0; nt < 8; nt++) {
                uint32_t bh2[2], bl2[2];
                uint32_t boff = (uint32_t)(((nt * 8 + bRow) * AKP + kk + bK) * 2);
                ldsm2(bh2[0], bh2[1], BhiA + boff);
                ldsm2(bl2[0], bl2[1], BloA + boff);
                mma_bf16(acc[nt], ah, bh2);
                mma_bf16(acc[nt], ah, bl2);
                mma_bf16(acc[nt], al, bh2);
            }
        }
    }

    const int g  = lane >> 2;
    const int t4 = lane & 3;
#pragma unroll
    for (int nt = 0; nt < 8; nt++) {
        long c = cb + nt * 8 + t4 * 2;
        float2 bv = *(const float2*)(bias + c);
        long r0 = rb + warp * 16 + g;
        *(float2*)(out + r0 * G3 + c) = make_float2(acc[nt][0] + bv.x, acc[nt][1] + bv.y);
        *(float2*)(out + (r0 + 8) * G3 + c) = make_float2(acc[nt][2] + bv.x, acc[nt][3] + bv.y);
    }
}

// ---------------------------------------------------------------------------
// Persistent encoder layer — unchanged from R9
// ---------------------------------------------------------------------------
__global__ void __launch_bounds__(NTH, 1) enc_layer_kernel(
    const float* __restrict__ gi,
    const float* __restrict__ Wh,
    const float* __restrict__ bh,
    float* __restrict__ out, long out_t, long out_b)
{
    __nv_bfloat16* whi = (__nv_bfloat16*)sm;
    __nv_bfloat16* wlo = whi + 24 * WKP;
    __nv_bfloat16* hhi = wlo + 24 * WKP;
    __nv_bfloat16* hlo = hhi + 64 * HKP;
    float* red = (float*)(hlo + 64 * HKP);
    float* gis = red + 4 * 24 * 68;

    const int tid  = threadIdx.x;
    const int j0   = blockIdx.x << 3;
    const int warp = tid >> 5;
    const int lane = tid & 31;
    const int mw   = warp & 3;
    const int kw   = warp >> 2;
    const int eb   = tid >> 3;
    const int ej   = tid & 7;
    const int ecol = j0 + ej;

    unsigned target;
    { volatile unsigned* pp = &g_phase; target = *pp + 1u; }

    for (int i = 0; i < 48; i++) {
        int idx = tid + (i << 9);
        int c = idx >> 10, k = idx & 1023;
        int row = ((c >> 3) << 10) + j0 + (c & 7);
        float w = Wh[(long)row * HID + k];
        __nv_bfloat16 hi, lo;
        split_bf(w, hi, lo);
        whi[c * WKP + k] = hi;
        wlo[c * WKP + k] = lo;
    }
    const float bhr = bh[ecol];
    const float bhz = bh[HID + ecol];
    const float bhn = bh[2 * HID + ecol];

    const int rowA = mw * 16 + ((lane >> 3) & 1) * 8 + (lane & 7);
    const int kA   = ((lane >> 4) & 1) * 8;
    const int lm   = lane & 15;
    const int bOff = (lm & 7) * WKP + ((lm >> 3) & 1) * 8;
    const uint32_t hhiA = smem_u32(hhi);
    const uint32_t hloA = smem_u32(hlo);
    const uint32_t whiA = smem_u32(whi);
    const uint32_t wloA = smem_u32(wlo);

    const int srow = tid >> 3;
    const int sq   = tid & 7;
    __syncthreads();

    for (int t = 0; t < TSRC; t++) {
        float c0[4], c1[4], c2[4];
#pragma unroll
        for (int i = 0; i < 4; i++) { c0[i] = 0.f; c1[i] = 0.f; c2[i] = 0.f; }

        const float* hprev = out + (long)(t - 1) * out_t;
        float hold = 0.0f;
        float4 rA[2][4];
        if (t > 0) {
            hold = hprev[(long)eb * out_b + ecol];
#pragma unroll
            for (int p = 0; p < 2; p++)
#pragma unroll
                for (int i = 0; i < 4; i++) {
                    int k4 = sq + (i << 3);
                    rA[p][i] = *(const float4*)(hprev + (long)srow * out_b + (p << 7) + (k4 << 2));
                }
        }

        {
            const float* gi_t = gi + (long)t * BB * G3;
#pragma unroll
            for (int i = 0; i < 3; i++) {
                int idx = (i << 9) + tid;
                int b = idx / 24;
                int rem = idx - b * 24;
                gis[b * 25 + rem] = gi_t[(long)b * G3 + ((rem >> 3) << 10) + j0 + (rem & 7)];
            }
        }

        if (t > 0) {
            for (int c = 0; c < 8; c++) {
                __syncthreads();
#pragma unroll
                for (int i = 0; i < 4; i++) {
                    int k4 = sq + (i << 3);
                    uint2 uh, ul;
                    split4_fast(rA[c & 1][i], uh, ul);
                    *(uint2*)&hhi[srow * HKP + (k4 << 2)] = uh;
                    *(uint2*)&hlo[srow * HKP + (k4 << 2)] = ul;
                }
                __syncthreads();
                if (c < 6) {
                    int k0n = (c + 2) << 7;
#pragma unroll
                    for (int i = 0; i < 4; i++) {
                        int k4 = sq + (i << 3);
                        rA[c & 1][i] =
                            *(const float4*)(hprev + (long)srow * out_b + k0n + (k4 << 2));
                    }
                }
                int k0 = c << 7;
#pragma unroll
                for (int s = 0; s < 2; s++) {
                    int kk = kw * 32 + s * 16;
                    int kg = k0 + kk;
                    uint32_t ah[4], al[4];
                    ldsm4(ah[0], ah[1], ah[2], ah[3],
                          hhiA + (uint32_t)((rowA * HKP + kk + kA) * 2));
                    ldsm4(al[0], al[1], al[2], al[3],
                          hloA + (uint32_t)((rowA * HKP + kk + kA) * 2));
                    uint32_t bh2[2], bl2[2];
                    ldsm2(bh2[0], bh2[1], whiA + (uint32_t)((bOff + kg) * 2));
                    ldsm2(bl2[0], bl2[1], wloA + (uint32_t)((bOff + kg) * 2));
                    mma_bf16(c0, ah, bh2); mma_bf16(c0, ah, bl2); mma_bf16(c0, al, bh2);
                    ldsm2(bh2[0], bh2[1], whiA + (uint32_t)((8 * WKP + bOff + kg) * 2));
                    ldsm2(bl2[0], bl2[1], wloA + (uint32_t)((8 * WKP + bOff + kg) * 2));
                    mma_bf16(c1, ah, bh2); mma_bf16(c1, ah, bl2); mma_bf16(c1, al, bh2);
                    ldsm2(bh2[0], bh2[1], whiA + (uint32_t)((16 * WKP + bOff + kg) * 2));
                    ldsm2(bl2[0], bl2[1], wloA + (uint32_t)((16 * WKP + bOff + kg) * 2));
                    mma_bf16(c2, ah, bh2); mma_bf16(c2, ah, bl2); mma_bf16(c2, al, bh2);
                }
            }
        }
        __syncthreads();
        dump_frag(red, c0, c1, c2, kw, mw, lane);
        __syncthreads();

        float s0 = 0.f, s1 = 0.f, s2 = 0.f;
#pragma unroll
        for (int k = 0; k < 4; k++) {
            const float* rp = red + k * 1632 + eb;
            s0 += rp[(ej)      * 68];
            s1 += rp[(8 + ej)  * 68];
            s2 += rp[(16 + ej) * 68];
        }
        const float* gp = gis + eb * 25;
        float GR = gp[ej], GZ = gp[8 + ej], GN = gp[16 + ej];
        float r = sigf(GR + s0 + bhr);
        float z = sigf(GZ + s1 + bhz);
        float n = tanhf(GN + r * (s2 + bhn));
        float hn = (1.0f - z) * n + z * hold;
        out[(long)t * out_t + (long)eb * out_b + ecol] = hn;

        if (t < TSRC - 1) grid_bar(target);
    }
}

// ---------------------------------------------------------------------------
// Decoder tensor phase: streamed weights + activations as split-bf16 tiles.
// Fragments accumulate across chunks; caller zeroes and dumps.
// ---------------------------------------------------------------------------
struct TcCtx {
    __nv_bfloat16 *wshi, *wslo, *hhi, *hlo;
    uint32_t wshiA, wsloA, hhiA, hloA;
    int rowA, kA, bOff, kw, tid, j0;
};

__device__ __forceinline__ void tc_phase(
    const float* __restrict__ X, long xs,
    const float* __restrict__ W, int K,
    const TcCtx& cx,
    float (&c0)[4], float (&c1)[4], float (&c2)[4])
{
    const int NC = K >> 7;
    const int srow = cx.tid >> 3;
    const int sq   = cx.tid & 7;
    float4 rx[4];
    float  rw[6];
#pragma unroll
    for (int i = 0; i < 4; i++) {
        int k4 = sq + (i << 3);
        rx[i] = *(const float4*)(X + (long)srow * xs + (k4 << 2));
    }
#pragma unroll
    for (int i = 0; i < 6; i++) {
        int idx = (i << 9) + cx.tid;
        int c = idx >> 7, k = idx & 127;
        int row = ((c >> 3) << 10) + cx.j0 + (c & 7);
        rw[i] = W[(long)row * (long)K + k];
    }
    for (int ci = 0; ci < NC; ci++) {
        __syncthreads();
#pragma unroll
        for (int i = 0; i < 4; i++) {
            int k4 = sq + (i << 3);
            uint2 uh, ul;
            split4_fast(rx[i], uh, ul);
            *(uint2*)&cx.hhi[srow * HKP + (k4 << 2)] = uh;
            *(uint2*)&cx.hlo[srow * HKP + (k4 << 2)] = ul;
        }
#pragma unroll
        for (int i = 0; i < 6; i++) {
            int idx = (i << 9) + cx.tid;
            int c = idx >> 7, k = idx & 127;
            __nv_bfloat16 hi, lo;
            split1_fast(rw[i], hi, lo);
            cx.wshi[c * HKP + k] = hi;
            cx.wslo[c * HKP + k] = lo;
        }
        __syncthreads();
        if (ci + 1 < NC) {
            int k0 = (ci + 1) << 7;
#pragma unroll
            for (int i = 0; i < 4; i++) {
                int k4 = sq + (i << 3);
                rx[i] = *(const float4*)(X + (long)srow * xs + k0 + (k4 << 2));
            }
#pragma unroll
            for (int i = 0; i < 6; i++) {
                int idx = (i << 9) + cx.tid;
                int c = idx >> 7, k = idx & 127;
                int row = ((c >> 3) << 10) + cx.j0 + (c & 7);
                rw[i] = W[(long)row * (long)K + k0 + k];
            }
        }
#pragma unroll
        for (int s = 0; s < 2; s++) {
            int kk = cx.kw * 32 + s * 16;
            uint32_t ah[4], al[4];
            ldsm4(ah[0], ah[1], ah[2], ah[3],
                  cx.hhiA + (uint32_t)((cx.rowA * HKP + kk + cx.kA) * 2));
            ldsm4(al[0], al[1], al[2], al[3],
                  cx.hloA + (uint32_t)((cx.rowA * HKP + kk + cx.kA) * 2));
            uint32_t bh2[2], bl2[2];
            ldsm2(bh2[0], bh2[1], cx.wshiA + (uint32_t)((cx.bOff + kk) * 2));
            ldsm2(bl2[0], bl2[1], cx.wsloA + (uint32_t)((cx.bOff + kk) * 2));
            mma_bf16(c0, ah, bh2); mma_bf16(c0, ah, bl2); mma_bf16(c0, al, bh2);
            ldsm2(bh2[0], bh2[1], cx.wshiA + (uint32_t)((8 * HKP + cx.bOff + kk) * 2));
            ldsm2(bl2[0], bl2[1], cx.wsloA + (uint32_t)((8 * HKP + cx.bOff + kk) * 2));
            mma_bf16(c1, ah, bh2); mma_bf16(c1, ah, bl2); mma_bf16(c1, al, bh2);
            ldsm2(bh2[0], bh2[1], cx.wshiA + (uint32_t)((16 * HKP + cx.bOff + kk) * 2));
            ldsm2(bl2[0], bl2[1], cx.wsloA + (uint32_t)((16 * HKP + cx.bOff + kk) * 2));
            mma_bf16(c2, ah, bh2); mma_bf16(c2, ah, bl2); mma_bf16(c2, al, bh2);
        }
    }
}

#define ZFRAG(c0, c1, c2) \
    do { _Pragma("unroll") for (int i_ = 0; i_ < 4; i_++) { c0[i_]=0.f; c1[i_]=0.f; c2[i_]=0.f; } } while (0)

// ---------------------------------------------------------------------------
// Persistent decoder: tensor-core GEMM phases (split-bf16), scalar fc.
// SMEM: wshi/wslo [24*HKP bf16] | hhi/hlo [64*HKP bf16] | redA | redB
// fc overlays: fcw on wshi region, fch (float [128][HSP]) on hhi region.
// ---------------------------------------------------------------------------
__global__ void __launch_bounds__(NTH, 1) dec_kernel(
    const float* __restrict__ dWi0, const float* __restrict__ dWh0,
    const float* __restrict__ dbi0, const float* __restrict__ dbh0,
    const float* __restrict__ dWi1, const float* __restrict__ dWh1,
    const float* __restrict__ dbi1, const float* __restrict__ dbh1,
    const float* __restrict__ fcW,  const float* __restrict__ fcb,
    const float* __restrict__ enc0_hT,
    const float* __restrict__ enc1_hT,
    float* __restrict__ h0buf, float* __restrict__ h1buf, float* __restrict__ xbuf,
    float* __restrict__ out,
    float* __restrict__ dec_out)
{
    __nv_bfloat16* wshi = (__nv_bfloat16*)sm;       // 24*HKP
    __nv_bfloat16* wslo = wshi + 24 * HKP;          // 24*HKP
    __nv_bfloat16* hhi  = wslo + 24 * HKP;          // 64*HKP
    __nv_bfloat16* hlo  = hhi + 64 * HKP;           // 64*HKP
    float* redA = (float*)(hlo + 64 * HKP);         // 4*24*68
    float* redB = redA + 4 * 24 * 68;               // 4*24*68
    float* fcw  = (float*)sm;                       // 2048 f (overlays wshi/wslo)
    float* fch  = (float*)hhi;                      // 128*HSP f (overlays hhi/hlo)

    const int tid  = threadIdx.x;
    const int j0   = blockIdx.x << 3;
    const int warp = tid >> 5;
    const int lane = tid & 31;
    const int mw   = warp & 3;
    const int kw   = warp >> 2;
    const int eb   = tid >> 3;
    const int ej   = tid & 7;
    const int ecol = j0 + ej;
    const int fb   = tid >> 3;
    const int fcc  = (tid >> 2) & 1;
    const int fks  = tid & 3;
    const int fcol = (blockIdx.x << 1) + fcc;

    TcCtx cx;
    cx.wshi = wshi; cx.wslo = wslo; cx.hhi = hhi; cx.hlo = hlo;
    cx.wshiA = smem_u32(wshi); cx.wsloA = smem_u32(wslo);
    cx.hhiA = smem_u32(hhi);   cx.hloA = smem_u32(hlo);
    cx.rowA = mw * 16 + ((lane >> 3) & 1) * 8 + (lane & 7);
    cx.kA   = ((lane >> 4) & 1) * 8;
    {
        int lm = lane & 15;
        cx.bOff = (lm & 7) * HKP + ((lm >> 3) & 1) * 8;
    }
    cx.kw = kw; cx.tid = tid; cx.j0 = j0;

    unsigned target;
    { volatile unsigned* pp = &g_phase; target = *pp + 1u; }

    const float b0ir = dbi0[ecol], b0iz = dbi0[HID + ecol], b0in = dbi0[2 * HID + ecol];
    const float b0hr = dbh0[ecol], b0hz = dbh0[HID + ecol], b0hn = dbh0[2 * HID + ecol];
    const float b1ir = dbi1[ecol], b1iz = dbi1[HID + ecol], b1in = dbi1[2 * HID + ecol];
    const float b1hr = dbh1[ecol], b1hz = dbh1[HID + ecol], b1hn = dbh1[2 * HID + ecol];
    const float fcbv = fcb[fcol];

    float c0[4], c1[4], c2[4];

    for (int t = 0; t < TTRG; t++) {
        const int w = t & 1;

        // ================= layer 0 =================
        ZFRAG(c0, c1, c2);
        if (t > 0)
            tc_phase(xbuf, INP, dWi0, INP, cx, c0, c1, c2);
        __syncthreads();
        dump_frag(redA, c0, c1, c2, kw, mw, lane);

        const float* h0p = t ? h0buf + (long)(1 - w) * BB * HID : enc0_hT;
        ZFRAG(c0, c1, c2);
        tc_phase(h0p, HID, dWh0, HID, cx, c0, c1, c2);
        __syncthreads();
        dump_frag(redB, c0, c1, c2, kw, mw, lane);
        __syncthreads();
        {
            float a0 = 0.f, a1 = 0.f, a2 = 0.f, d0 = 0.f, d1 = 0.f, d2 = 0.f;
#pragma unroll
            for (int k = 0; k < 4; k++) {
                const float* ra = redA + k * 1632 + eb;
                const float* rb = redB + k * 1632 + eb;
                a0 += ra[ej * 68];        d0 += rb[ej * 68];
                a1 += ra[(8 + ej) * 68];  d1 += rb[(8 + ej) * 68];
                a2 += ra[(16 + ej) * 68]; d2 += rb[(16 + ej) * 68];
            }
            float hold = h0p[(long)eb * HID + ecol];
            float r = sigf(a0 + b0ir + d0 + b0hr);
            float z = sigf(a1 + b0iz + d1 + b0hz);
            float n = tanhf(a2 + b0in + r * (d2 + b0hn));
            h0buf[(long)w * BB * HID + (long)eb * HID + ecol] = (1.f - z) * n + z * hold;
        }
        grid_bar(target);

        // ================= layer 1 =================
        const float* x1 = h0buf + (long)w * BB * HID;
        ZFRAG(c0, c1, c2);
        tc_phase(x1, HID, dWi1, HID, cx, c0, c1, c2);
        __syncthreads();
        dump_frag(redA, c0, c1, c2, kw, mw, lane);

        const float* h1p = t ? h1buf + (long)(1 - w) * BB * HID : enc1_hT;
        const long   h1s = t ? (long)HID : (long)TSRC * HID;
        ZFRAG(c0, c1, c2);
        tc_phase(h1p, h1s, dWh1, HID, cx, c0, c1, c2);
        __syncthreads();
        dump_frag(redB, c0, c1, c2, kw, mw, lane);
        __syncthreads();
        {
            float a0 = 0.f, a1 = 0.f, a2 = 0.f, d0 = 0.f, d1 = 0.f, d2 = 0.f;
#pragma unroll
            for (int k = 0; k < 4; k++) {
                const float* ra = redA + k * 1632 + eb;
                const float* rb = redB + k * 1632 + eb;
                a0 += ra[ej * 68];        d0 += rb[ej * 68];
                a1 += ra[(8 + ej) * 68];  d1 += rb[(8 + ej) * 68];
                a2 += ra[(16 + ej) * 68]; d2 += rb[(16 + ej) * 68];
            }
            float hold = h1p[(long)eb * h1s + ecol];
            float r = sigf(a0 + b1ir + d0 + b1hr);
            float z = sigf(a1 + b1iz + d1 + b1hz);
            float n = tanhf(a2 + b1in + r * (d2 + b1hn));
            float hn = (1.f - z) * n + z * hold;
            h1buf[(long)w * BB * HID + (long)eb * HID + ecol] = hn;
            dec_out[(long)eb * TTRG * HID + (long)t * HID + ecol] = hn;
        }
        grid_bar(target);

        // ================= fc (scalar, pipelined, overlaid SMEM) ============
        {
            const float* h1c = h1buf + (long)w * BB * HID;
            const int sb = tid >> 3;
            const int sq = tid & 7;
            __syncthreads();   // everyone past GEMM regions before overlay reuse
#pragma unroll
            for (int i = 0; i < 4; i++) {
                int idx = (i << 9) + tid;
                int k = idx >> 1, c = idx & 1;
                fcw[idx] = fcW[(long)((blockIdx.x << 1) + c) * HID + k];
            }
            float4 rx[4];
#pragma unroll
            for (int i = 0; i < 4; i++) {
                int k4 = sq + (i << 3);
                rx[i] = *(const float4*)(h1c + (long)sb * HID + (k4 << 2));
            }
            float partial = 0.f;
            for (int ci = 0; ci < 8; ci++) {
                __syncthreads();
#pragma unroll
                for (int i = 0; i < 4; i++) {
                    int k4 = sq + (i << 3);
                    int base = (k4 << 2) * HSP + sb;
                    fch[base]           = rx[i].x;
                    fch[base + HSP]     = rx[i].y;
                    fch[base + 2 * HSP] = rx[i].z;
                    fch[base + 3 * HSP] = rx[i].w;
                }
                __syncthreads();
                if (ci + 1 < 8) {
                    int k0 = (ci + 1) << 7;
#pragma unroll
                    for (int i = 0; i < 4; i++) {
                        int k4 = sq + (i << 3);
                        rx[i] = *(const float4*)(h1c + (long)sb * HID + k0 + (k4 << 2));
                    }
                }
                int k0 = ci << 7;
#pragma unroll 8
                for (int i = 0; i < 32; i++) {
                    int kk = fks * 32 + i;
                    partial += fch[kk * HSP + fb] * fcw[(k0 + kk) * 2 + fcc];
                }
            }
            __syncthreads();
            redA[tid] = partial;
            __syncthreads();
            if (fks == 0) {
                float s = redA[tid] + redA[tid + 1] + redA[tid + 2] + redA[tid + 3] + fcbv;
                out [(long)fb * TTRG * INP + (long)t * INP + fcol] = s;
                xbuf[(long)fb * INP + fcol] = s;
            }
        }
        grid_bar(target);
    }
}

// ---------------------------------------------------------------------------
extern "C" void kernel_launch(void* const* d_in, const int* in_sizes, int n_in,
                              void* d_out, int out_size)
{
    const float* src  = (const float*)d_in[0];
    const float* eWi0 = (const float*)d_in[2];
    const float* eWh0 = (const float*)d_in[3];
    const float* ebi0 = (const float*)d_in[4];
    const float* ebh0 = (const float*)d_in[5];
    const float* eWi1 = (const float*)d_in[6];
    const float* eWh1 = (const float*)d_in[7];
    const float* ebi1 = (const float*)d_in[8];
    const float* ebh1 = (const float*)d_in[9];
    const float* dWi0 = (const float*)d_in[10];
    const float* dWh0 = (const float*)d_in[11];
    const float* dbi0 = (const float*)d_in[12];
    const float* dbh0 = (const float*)d_in[13];
    const float* dWi1 = (const float*)d_in[14];
    const float* dWh1 = (const float*)d_in[15];
    const float* dbi1 = (const float*)d_in[16];
    const float* dbh1 = (const float*)d_in[17];
    const float* fcW  = (const float*)d_in[18];
    const float* fcb  = (const float*)d_in[19];

    float* out     = (float*)d_out;                   // [64, 64, 256]
    float* enc_out = out + (long)BB * TTRG * INP;     // [64, 256, 1024]
    float* dec_out = enc_out + (long)BB * TSRC * HID; // [64, 64, 1024]

    float *gi, *ys0, *h0, *h1, *xbuf;
    cudaGetSymbolAddress((void**)&gi,   g_gi);
    cudaGetSymbolAddress((void**)&ys0,  g_ys0);
    cudaGetSymbolAddress((void**)&h0,   g_h0);
    cudaGetSymbolAddress((void**)&h1,   g_h1);
    cudaGetSymbolAddress((void**)&xbuf, g_x);

    const int ENC_SMEM = 24 * WKP * 2 * 2 + 64 * HKP * 2 * 2
                       + 4 * 24 * 68 * 4 + 64 * 25 * 4;   // 166400 B
    const int DEC_SMEM = (24 * HKP * 2 + 64 * HKP * 2) * 2
                       + 2 * 4 * 24 * 68 * 4;             // 100096 B
    cudaFuncSetAttribute(enc_layer_kernel,
                         cudaFuncAttributeMaxDynamicSharedMemorySize, ENC_SMEM);
    cudaFuncSetAttribute(dec_kernel,
                         cudaFuncAttributeMaxDynamicSharedMemorySize, DEC_SMEM);

    dim3 gridTc(48, 128);

    // ---------- encoder layer 0 ----------
    tc_gemm<<<gridTc, 256>>>(src, 65536L, 256L, eWi0, ebi0, gi, 256);
    enc_layer_kernel<<<GRID, NTH, ENC_SMEM>>>(
        gi, eWh0, ebh0, ys0, (long)BB * HID, (long)HID);

    // ---------- encoder layer 1 ----------
    tc_gemm<<<gridTc, 256>>>(ys0, 1024L, 65536L, eWi1, ebi1, gi, 1024);
    enc_layer_kernel<<<GRID, NTH, ENC_SMEM>>>(
        gi, eWh1, ebh1, enc_out, (long)HID, (long)TSRC * HID);

    // ---------- decoder ----------
    dec_kernel<<<GRID, NTH, DEC_SMEM>>>(
        dWi0, dWh0, dbi0, dbh0,
        dWi1, dWh1, dbi1, dbh1,
        fcW, fcb,
        ys0 + (long)(TSRC - 1) * BB * HID,
        enc_out + (long)(TSRC - 1) * HID,
        h0, h1, xbuf,
        out, dec_out);
}